// round 1
// baseline (speedup 1.0000x reference)
#include <cuda_runtime.h>
#include <math.h>

#define N_HOST 20000
#define N_FLOW 200000
#define E_HF   400000
#define E_REL  800000
#define GG     64
#define HH     128
#define FI     97

// ---------------- scratch (device globals; no allocation allowed) ----------
__device__ float g_xflowA[(size_t)N_FLOW * HH];   // padded flow features / ping
__device__ float g_xflowB[(size_t)N_FLOW * HH];   // pong
__device__ float g_agg1 [(size_t)N_FLOW * HH];    // h2f aggregation into flows
__device__ float g_agg2 [(size_t)N_FLOW * HH];    // rel aggregation into flows
__device__ float g_xhostA[(size_t)N_HOST * HH];
__device__ float g_xhostB[(size_t)N_HOST * HH];
__device__ float g_aggh [(size_t)N_HOST * HH];    // f2h aggregation into hosts

__device__ float g_WrelPad[HH * HH];   // pad(Wr0_rel)   97->128 rows
__device__ float g_Wf2hPad[HH * HH];   // pad(Wr0_f2h)
__device__ float g_WoF0   [HH * HH];   // pad(Wo0_h2f + Wo0_rel)
__device__ float g_WoComb [2][HH * HH];// Wo[l,0]+Wo[l,2]
__device__ float g_biasF0 [HH];        // br0_h2f + br0_rel
__device__ float g_biasF  [2][HH];     // br[l,0]+br[l,2]

__device__ unsigned g_poolEnc[GG * HH];
__device__ float    g_pooled [GG * HH];
__device__ float    g_h1[GG * 64];
__device__ float    g_h2[GG * HH];

// ---------------- small helpers -------------------------------------------
__device__ __forceinline__ unsigned enc_f(float f) {
    unsigned u = __float_as_uint(f);
    return (u & 0x80000000u) ? ~u : (u | 0x80000000u);
}
__device__ __forceinline__ float dec_f(unsigned e) {
    return (e & 0x80000000u) ? __uint_as_float(e ^ 0x80000000u)
                             : __uint_as_float(~e);
}

// ---------------- kernels --------------------------------------------------
__global__ void zero_kernel(float* __restrict__ p, int n4) {
    int i = blockIdx.x * blockDim.x + threadIdx.x;
    if (i < n4) ((float4*)p)[i] = make_float4(0.f, 0.f, 0.f, 0.f);
}

__global__ void embed_kernel(const int* __restrict__ ids,
                             const float* __restrict__ table,
                             float* __restrict__ xh) {
    int i = blockIdx.x * blockDim.x + threadIdx.x;  // over N_HOST*128
    if (i >= N_HOST * HH) return;
    int row = i >> 7, c = i & 127;
    xh[i] = table[(size_t)__ldg(ids + row) * HH + c];
}

__global__ void pad_flow_kernel(const float* __restrict__ fx,
                                float* __restrict__ xf) {
    int i = blockIdx.x * blockDim.x + threadIdx.x;  // over N_FLOW*128
    if (i >= N_FLOW * HH) return;
    int row = i >> 7, c = i & 127;
    xf[i] = (c < FI) ? fx[(size_t)row * FI + c] : 0.f;
}

// builds padded / combined weight+bias scratch. grid 128 blocks x 128 thr.
__global__ void prep_weights_kernel(const float* __restrict__ Wr0_rel,
                                    const float* __restrict__ Wr0_f2h,
                                    const float* __restrict__ Wo0_h2f,
                                    const float* __restrict__ Wo0_rel,
                                    const float* __restrict__ Wo,   // [2,3,128,128]
                                    const float* __restrict__ br0_h2f,
                                    const float* __restrict__ br0_rel,
                                    const float* __restrict__ br) { // [2,3,128]
    int k = blockIdx.x, c = threadIdx.x;
    int idx = k * HH + c;
    g_WrelPad[idx] = (k < FI) ? Wr0_rel[k * HH + c] : 0.f;
    g_Wf2hPad[idx] = (k < FI) ? Wr0_f2h[k * HH + c] : 0.f;
    g_WoF0[idx]    = (k < FI) ? (Wo0_h2f[k * HH + c] + Wo0_rel[k * HH + c]) : 0.f;
    for (int l = 0; l < 2; ++l)
        g_WoComb[l][idx] = Wo[((size_t)l * 3 + 0) * HH * HH + idx]
                         + Wo[((size_t)l * 3 + 2) * HH * HH + idx];
    if (k == 0) {
        g_biasF0[c] = br0_h2f[c] + br0_rel[c];
        for (int l = 0; l < 2; ++l)
            g_biasF[l][c] = br[(l * 3 + 0) * HH + c] + br[(l * 3 + 2) * HH + c];
    }
}

// one warp per edge; lane handles one float4 (4 cols); vector red to L2
__global__ void scatter_add_kernel(const float* __restrict__ src_feat,
                                   const int* __restrict__ esrc,
                                   const int* __restrict__ edst,
                                   float* __restrict__ dst_feat, int E) {
    int w = (blockIdx.x * blockDim.x + threadIdx.x) >> 5;
    int lane = threadIdx.x & 31;
    if (w >= E) return;
    int s = __ldg(esrc + w);
    int d = __ldg(edst + w);
    float4 v = ((const float4*)(src_feat + (size_t)s * HH))[lane];
    float* dp = dst_feat + (size_t)d * HH + lane * 4;
    asm volatile("red.global.add.v4.f32 [%0], {%1,%2,%3,%4};"
                 :: "l"(dp), "f"(v.x), "f"(v.y), "f"(v.z), "f"(v.w)
                 : "memory");
}

// out[M,128] = sum_s A_s[M,128] @ W_s[128,128]  (+bias, opt relu)
// block: 256 thr, tile 128x128, BK=16, thread micro-tile 8x8
__global__ __launch_bounds__(256)
void gemm3_kernel(const float* __restrict__ A0, const float* __restrict__ W0,
                  const float* __restrict__ A1, const float* __restrict__ W1,
                  const float* __restrict__ A2, const float* __restrict__ W2,
                  const float* __restrict__ bias, float* __restrict__ out,
                  int M, int nsrc, int do_relu) {
    const int BM = 128, BK = 16, BMp = BM + 4;
    __shared__ float As[BK][BMp];
    __shared__ float Ws[BK][128];
    int tid = threadIdx.x;
    int tx = tid & 15, ty = tid >> 4;
    int row0 = blockIdx.x * BM;
    float acc[8][8];
#pragma unroll
    for (int i = 0; i < 8; ++i)
#pragma unroll
        for (int j = 0; j < 8; ++j) acc[i][j] = 0.f;

    const float* Aarr[3] = {A0, A1, A2};
    const float* Warr[3] = {W0, W1, W2};

    for (int s = 0; s < nsrc; ++s) {
        const float* A = Aarr[s];
        const float* W = Warr[s];
        for (int k0 = 0; k0 < 128; k0 += BK) {
#pragma unroll
            for (int i = 0; i < 2; ++i) {              // A tile -> As[k][m]
                int idx = tid + i * 256;               // 0..511
                int r = idx >> 2, kq = idx & 3;
                int grow = row0 + r;
                float4 v = make_float4(0.f, 0.f, 0.f, 0.f);
                if (grow < M)
                    v = *(const float4*)(A + (size_t)grow * 128 + k0 + kq * 4);
                As[kq * 4 + 0][r] = v.x;
                As[kq * 4 + 1][r] = v.y;
                As[kq * 4 + 2][r] = v.z;
                As[kq * 4 + 3][r] = v.w;
            }
#pragma unroll
            for (int i = 0; i < 2; ++i) {              // W tile -> Ws[k][n]
                int idx = tid + i * 256;
                int kk = idx >> 5, cq = idx & 31;
                float4 v = *(const float4*)(W + (size_t)(k0 + kk) * 128 + cq * 4);
                *(float4*)&Ws[kk][cq * 4] = v;
            }
            __syncthreads();
#pragma unroll
            for (int k = 0; k < BK; ++k) {
                float a[8], b[8];
#pragma unroll
                for (int i = 0; i < 8; i += 4)
                    *(float4*)&a[i] = *(const float4*)&As[k][ty * 8 + i];
#pragma unroll
                for (int j = 0; j < 8; j += 4)
                    *(float4*)&b[j] = *(const float4*)&Ws[k][tx * 8 + j];
#pragma unroll
                for (int i = 0; i < 8; ++i)
#pragma unroll
                    for (int j = 0; j < 8; ++j)
                        acc[i][j] = fmaf(a[i], b[j], acc[i][j]);
            }
            __syncthreads();
        }
    }
#pragma unroll
    for (int i = 0; i < 8; ++i) {
        int r = row0 + ty * 8 + i;
        if (r >= M) break;
#pragma unroll
        for (int j = 0; j < 8; ++j) {
            float v = acc[i][j] + __ldg(bias + tx * 8 + j);
            if (do_relu) v = fmaxf(v, 0.f);
            out[(size_t)r * 128 + tx * 8 + j] = v;
        }
    }
}

__global__ void pool_init_kernel(unsigned* __restrict__ pe) {
    int i = blockIdx.x * blockDim.x + threadIdx.x;
    if (i < GG * HH) pe[i] = 0x007FFFFFu;  // enc(-inf)
}

__global__ void pool_max_kernel(const float* __restrict__ xf,
                                const int* __restrict__ batch,
                                unsigned* __restrict__ pe, int n) {
    const int R = 1024;
    int base = blockIdx.x * R;
    if (base >= n) return;
    int end = min(base + R, n);
    int c = threadIdx.x;
    int cur = __ldg(batch + base);
    float m = -INFINITY;
    for (int r = base; r < end; ++r) {
        int g = __ldg(batch + r);
        if (g != cur) {
            atomicMax(&pe[cur * HH + c], enc_f(m));
            cur = g; m = -INFINITY;
        }
        m = fmaxf(m, xf[(size_t)r * HH + c]);
    }
    atomicMax(&pe[cur * HH + c], enc_f(m));
}

__global__ void pool_decode_kernel(const unsigned* __restrict__ pe,
                                   float* __restrict__ p) {
    int i = blockIdx.x * blockDim.x + threadIdx.x;
    if (i < GG * HH) p[i] = dec_f(pe[i]);
}

__global__ void mlp1_kernel(const float* __restrict__ pooled,
                            const float* __restrict__ Wc1,
                            const float* __restrict__ bc1,
                            float* __restrict__ h1) {
    int t = blockIdx.x * blockDim.x + threadIdx.x;  // 64*64
    if (t >= GG * 64) return;
    int g = t >> 6, c = t & 63;
    float acc = bc1[c];
    for (int k = 0; k < HH; ++k)
        acc = fmaf(pooled[g * HH + k], Wc1[k * 64 + c], acc);
    h1[t] = fmaxf(acc, 0.f);
}

__global__ void mlp2_kernel(const float* __restrict__ h1,
                            const float* __restrict__ Wc2,
                            const float* __restrict__ bc2,
                            float* __restrict__ h2) {
    int t = blockIdx.x * blockDim.x + threadIdx.x;  // 64*128
    if (t >= GG * HH) return;
    int g = t >> 7, c = t & 127;
    float acc = bc2[c];
    for (int k = 0; k < 64; ++k)
        acc = fmaf(h1[g * 64 + k], Wc2[k * HH + c], acc);
    h2[t] = fmaxf(acc, 0.f);
}

__global__ void mlp3_kernel(const float* __restrict__ h2,
                            const float* __restrict__ Wc3,
                            const float* __restrict__ bc3,
                            float* __restrict__ out) {
    int t = blockIdx.x * blockDim.x + threadIdx.x;  // 64*10
    if (t >= GG * 10) return;
    int g = t / 10, c = t % 10;
    float acc = bc3[c];
    for (int k = 0; k < HH; ++k)
        acc = fmaf(h2[g * HH + k], Wc3[k * 10 + c], acc);
    out[t] = acc;
}

// ---------------- host-side orchestration ----------------------------------
static inline void zero_buf(float* p, size_t n) {
    int n4 = (int)(n / 4);
    zero_kernel<<<(n4 + 255) / 256, 256>>>(p, n4);
}

extern "C" void kernel_launch(void* const* d_in, const int* in_sizes, int n_in,
                              void* d_out, int out_size) {
    const int*   host_ids  = (const int*)  d_in[0];
    const float* flow_x    = (const float*)d_in[1];
    const int*   h2f_src   = (const int*)  d_in[2];
    const int*   h2f_dst   = (const int*)  d_in[3];
    const int*   f2h_src   = (const int*)  d_in[4];
    const int*   f2h_dst   = (const int*)  d_in[5];
    const int*   rel_src   = (const int*)  d_in[6];
    const int*   rel_dst   = (const int*)  d_in[7];
    const int*   flow_batch= (const int*)  d_in[8];
    const float* host_embed= (const float*)d_in[9];
    const float* Wr0_h2f   = (const float*)d_in[10];
    const float* br0_h2f   = (const float*)d_in[11];
    const float* Wo0_h2f   = (const float*)d_in[12];
    const float* Wr0_f2h   = (const float*)d_in[13];
    const float* br0_f2h   = (const float*)d_in[14];
    const float* Wo0_f2h   = (const float*)d_in[15];
    const float* Wr0_rel   = (const float*)d_in[16];
    const float* br0_rel   = (const float*)d_in[17];
    /* Wo0_rel = d_in[18] */
    const float* Wo0_rel   = (const float*)d_in[18];
    const float* Wr        = (const float*)d_in[19];  // [2,3,128,128]
    const float* br        = (const float*)d_in[20];  // [2,3,128]
    const float* Wo        = (const float*)d_in[21];  // [2,3,128,128]
    const float* Wc1       = (const float*)d_in[22];
    const float* bc1       = (const float*)d_in[23];
    const float* Wc2       = (const float*)d_in[24];
    const float* bc2       = (const float*)d_in[25];
    const float* Wc3       = (const float*)d_in[26];
    const float* bc3       = (const float*)d_in[27];
    float* out = (float*)d_out;

    float *xfA, *xfB, *a1, *a2, *xhA, *xhB, *ah;
    float *WrelPad, *Wf2hPad, *WoF0, *WoComb, *biasF0, *biasF;
    unsigned* poolEnc; float *pooled, *h1, *h2;
    cudaGetSymbolAddress((void**)&xfA, g_xflowA);
    cudaGetSymbolAddress((void**)&xfB, g_xflowB);
    cudaGetSymbolAddress((void**)&a1,  g_agg1);
    cudaGetSymbolAddress((void**)&a2,  g_agg2);
    cudaGetSymbolAddress((void**)&xhA, g_xhostA);
    cudaGetSymbolAddress((void**)&xhB, g_xhostB);
    cudaGetSymbolAddress((void**)&ah,  g_aggh);
    cudaGetSymbolAddress((void**)&WrelPad, g_WrelPad);
    cudaGetSymbolAddress((void**)&Wf2hPad, g_Wf2hPad);
    cudaGetSymbolAddress((void**)&WoF0,    g_WoF0);
    cudaGetSymbolAddress((void**)&WoComb,  g_WoComb);
    cudaGetSymbolAddress((void**)&biasF0,  g_biasF0);
    cudaGetSymbolAddress((void**)&biasF,   g_biasF);
    cudaGetSymbolAddress((void**)&poolEnc, g_poolEnc);
    cudaGetSymbolAddress((void**)&pooled,  g_pooled);
    cudaGetSymbolAddress((void**)&h1, g_h1);
    cudaGetSymbolAddress((void**)&h2, g_h2);

    // prep: padded/combined weights, embeddings, padded flow features
    prep_weights_kernel<<<HH, HH>>>(Wr0_rel, Wr0_f2h, Wo0_h2f, Wo0_rel, Wo,
                                    br0_h2f, br0_rel, br);
    embed_kernel<<<(N_HOST * HH + 255) / 256, 256>>>(host_ids, host_embed, xhA);
    pad_flow_kernel<<<(N_FLOW * HH + 255) / 256, 256>>>(flow_x, xfA);

    const int GEMM_BM = 128;
    int flowBlocks = (N_FLOW + GEMM_BM - 1) / GEMM_BM;
    int hostBlocks = (N_HOST + GEMM_BM - 1) / GEMM_BM;

    float* fa = xfA; float* fb = xfB;
    float* ha = xhA; float* hb = xhB;

    for (int layer = 0; layer < 3; ++layer) {
        // zero aggregation buffers
        zero_buf(a1, (size_t)N_FLOW * HH);
        zero_buf(a2, (size_t)N_FLOW * HH);
        zero_buf(ah, (size_t)N_HOST * HH);
        // scatters (read OLD fa/ha)
        scatter_add_kernel<<<(E_HF  * 32 + 255) / 256, 256>>>(ha, h2f_src, h2f_dst, a1, E_HF);
        scatter_add_kernel<<<(E_REL * 32 + 255) / 256, 256>>>(fa, rel_src, rel_dst, a2, E_REL);
        scatter_add_kernel<<<(E_HF  * 32 + 255) / 256, 256>>>(fa, f2h_src, f2h_dst, ah, E_HF);

        if (layer == 0) {
            gemm3_kernel<<<flowBlocks, 256>>>(a1, Wr0_h2f, a2, WrelPad, fa, WoF0,
                                              biasF0, fb, N_FLOW, 3, 1);
            gemm3_kernel<<<hostBlocks, 256>>>(ah, Wf2hPad, ha, Wo0_f2h, nullptr, nullptr,
                                              br0_f2h, hb, N_HOST, 2, 1);
        } else {
            int l = layer - 1;
            const float* WrF1 = Wr + ((size_t)l * 3 + 0) * HH * HH;
            const float* WrF2 = Wr + ((size_t)l * 3 + 2) * HH * HH;
            const float* WrH  = Wr + ((size_t)l * 3 + 1) * HH * HH;
            const float* WoH  = Wo + ((size_t)l * 3 + 1) * HH * HH;
            const float* brH  = br + (l * 3 + 1) * HH;
            int do_relu = (l == 0) ? 1 : 0;
            gemm3_kernel<<<flowBlocks, 256>>>(a1, WrF1, a2, WrF2, fa, WoComb + (size_t)l * HH * HH,
                                              biasF + (size_t)l * HH, fb, N_FLOW, 3, do_relu);
            gemm3_kernel<<<hostBlocks, 256>>>(ah, WrH, ha, WoH, nullptr, nullptr,
                                              brH, hb, N_HOST, 2, do_relu);
        }
        // swap ping-pong
        float* t;
        t = fa; fa = fb; fb = t;
        t = ha; ha = hb; hb = t;
    }

    // global max pool over sorted flow_batch
    pool_init_kernel<<<(GG * HH + 255) / 256, 256>>>(poolEnc);
    pool_max_kernel<<<(N_FLOW + 1023) / 1024, HH>>>(fa, flow_batch, poolEnc, N_FLOW);
    pool_decode_kernel<<<(GG * HH + 255) / 256, 256>>>(poolEnc, pooled);

    // classifier MLP
    mlp1_kernel<<<(GG * 64 + 255) / 256, 256>>>(pooled, Wc1, bc1, h1);
    mlp2_kernel<<<(GG * HH + 255) / 256, 256>>>(h1, Wc2, bc2, h2);
    mlp3_kernel<<<(GG * 10 + 255) / 256, 256>>>(h2, Wc3, bc3, out);
}

// round 2
// speedup vs baseline: 1.2323x; 1.2323x over previous
#include <cuda_runtime.h>
#include <math.h>

#define N_HOST 20000
#define N_FLOW 200000
#define E_HF   400000
#define E_REL  800000
#define GG     64
#define HH     128
#define FI     97

// ---------------- scratch (device globals; no allocation allowed) ----------
__device__ float g_xflowA[(size_t)N_FLOW * HH];   // ping
__device__ float g_xflowB[(size_t)N_FLOW * HH];   // pong
__device__ float g_trel  [(size_t)N_FLOW * HH];   // transformed flow (rel)
__device__ float g_th    [(size_t)N_HOST * HH];   // transformed host (h2f)
__device__ float g_xhostA[(size_t)N_HOST * HH];
__device__ float g_xhostB[(size_t)N_HOST * HH];
__device__ float g_aggh  [(size_t)N_HOST * HH];   // f2h aggregation into hosts

__device__ float g_WF[3][HH * 2 * HH];  // per layer: [128][256] = [WoComb | Wr_rel]
__device__ float g_Wf2hPad[HH * HH];    // pad(Wr0_f2h) 97->128 rows
__device__ float g_biasF[3][HH];        // br_h2f + br_rel per layer
__device__ float g_zeroBias[HH];        // zero-initialized device global

__device__ unsigned g_poolEnc[GG * HH];
__device__ float    g_pooled [GG * HH];
__device__ float    g_h1[GG * 64];
__device__ float    g_h2[GG * HH];

// ---------------- small helpers -------------------------------------------
__device__ __forceinline__ unsigned enc_f(float f) {
    unsigned u = __float_as_uint(f);
    return (u & 0x80000000u) ? ~u : (u | 0x80000000u);
}
__device__ __forceinline__ float dec_f(unsigned e) {
    return (e & 0x80000000u) ? __uint_as_float(e ^ 0x80000000u)
                             : __uint_as_float(~e);
}

// ---------------- prep ------------------------------------------------------
__global__ void embed_kernel(const int* __restrict__ ids,
                             const float* __restrict__ table,
                             float* __restrict__ xh) {
    int i = blockIdx.x * blockDim.x + threadIdx.x;
    if (i >= N_HOST * HH) return;
    int row = i >> 7, c = i & 127;
    xh[i] = table[(size_t)__ldg(ids + row) * HH + c];
}

__global__ void pad_flow_kernel(const float* __restrict__ fx,
                                float* __restrict__ xf) {
    int i = blockIdx.x * blockDim.x + threadIdx.x;
    if (i >= N_FLOW * HH) return;
    int row = i >> 7, c = i & 127;
    xf[i] = (c < FI) ? fx[(size_t)row * FI + c] : 0.f;
}

// grid: 128 blocks x 256 threads
__global__ void prep_weights_kernel(const float* __restrict__ Wo0_h2f,
                                    const float* __restrict__ Wo0_rel,
                                    const float* __restrict__ Wr0_rel,
                                    const float* __restrict__ Wr0_f2h,
                                    const float* __restrict__ Wo,   // [2,3,128,128]
                                    const float* __restrict__ Wr,   // [2,3,128,128]
                                    const float* __restrict__ br0_h2f,
                                    const float* __restrict__ br0_rel,
                                    const float* __restrict__ br) { // [2,3,128]
    int k = blockIdx.x;       // input dim 0..127
    int c = threadIdx.x;      // combined col 0..255
    int idx = k * 256 + c;
    if (c < HH) {
        g_WF[0][idx] = (k < FI) ? (Wo0_h2f[k * HH + c] + Wo0_rel[k * HH + c]) : 0.f;
        g_Wf2hPad[k * HH + c] = (k < FI) ? Wr0_f2h[k * HH + c] : 0.f;
    } else {
        int cc = c - HH;
        g_WF[0][idx] = (k < FI) ? Wr0_rel[k * HH + cc] : 0.f;
    }
    for (int l = 0; l < 2; ++l) {
        float v;
        if (c < HH)
            v = Wo[((size_t)l * 3 + 0) * HH * HH + k * HH + c]
              + Wo[((size_t)l * 3 + 2) * HH * HH + k * HH + c];
        else
            v = Wr[((size_t)l * 3 + 2) * HH * HH + k * HH + (c - HH)];
        g_WF[l + 1][idx] = v;
    }
    if (k == 0 && c < HH) {
        g_biasF[0][c] = br0_h2f[c] + br0_rel[c];
        for (int l = 0; l < 2; ++l)
            g_biasF[l + 1][c] = br[(l * 3 + 0) * HH + c] + br[(l * 3 + 2) * HH + c];
        g_zeroBias[c] = 0.f;
    }
}

// ---------------- scatter ---------------------------------------------------
__global__ void scatter_add_kernel(const float* __restrict__ src_feat,
                                   const int* __restrict__ esrc,
                                   const int* __restrict__ edst,
                                   float* __restrict__ dst_feat, int E,
                                   int relu_in) {
    int w = (blockIdx.x * blockDim.x + threadIdx.x) >> 5;
    int lane = threadIdx.x & 31;
    if (w >= E) return;
    int s = __ldg(esrc + w);
    int d = __ldg(edst + w);
    float4 v = ((const float4*)(src_feat + (size_t)s * HH))[lane];
    if (relu_in) {
        v.x = fmaxf(v.x, 0.f); v.y = fmaxf(v.y, 0.f);
        v.z = fmaxf(v.z, 0.f); v.w = fmaxf(v.w, 0.f);
    }
    float* dp = dst_feat + (size_t)d * HH + lane * 4;
    asm volatile("red.global.add.v4.f32 [%0], {%1,%2,%3,%4};"
                 :: "l"(dp), "f"(v.x), "f"(v.y), "f"(v.z), "f"(v.w)
                 : "memory");
}

// ---------------- GEMMs -----------------------------------------------------
// [out_main | out_aux] = (relu?)A[M,128] @ W[128,256]; bias only on main half
__global__ __launch_bounds__(512)
void gemm_dual_kernel(const float* __restrict__ A, const float* __restrict__ W,
                      const float* __restrict__ bias,
                      float* __restrict__ out_main, float* __restrict__ out_aux,
                      int M, int relu_in) {
    const int BK = 16;
    __shared__ float As[BK][HH + 4];
    __shared__ float Ws[BK][256];
    int tid = threadIdx.x;
    int tx = tid & 31, ty = tid >> 5;
    int row0 = blockIdx.x * HH;
    float acc[8][8];
#pragma unroll
    for (int i = 0; i < 8; ++i)
#pragma unroll
        for (int j = 0; j < 8; ++j) acc[i][j] = 0.f;

    for (int k0 = 0; k0 < HH; k0 += BK) {
        {
            int r = tid >> 2, kq = tid & 3;
            int grow = row0 + r;
            float4 v = make_float4(0.f, 0.f, 0.f, 0.f);
            if (grow < M)
                v = *(const float4*)(A + (size_t)grow * HH + k0 + kq * 4);
            if (relu_in) {
                v.x = fmaxf(v.x, 0.f); v.y = fmaxf(v.y, 0.f);
                v.z = fmaxf(v.z, 0.f); v.w = fmaxf(v.w, 0.f);
            }
            As[kq * 4 + 0][r] = v.x;
            As[kq * 4 + 1][r] = v.y;
            As[kq * 4 + 2][r] = v.z;
            As[kq * 4 + 3][r] = v.w;
        }
#pragma unroll
        for (int i = 0; i < 2; ++i) {
            int idx = tid + i * 512;
            int kk = idx >> 6, cq = idx & 63;
            *(float4*)&Ws[kk][cq * 4] =
                *(const float4*)(W + (size_t)(k0 + kk) * 256 + cq * 4);
        }
        __syncthreads();
#pragma unroll
        for (int k = 0; k < BK; ++k) {
            float a[8], b[8];
#pragma unroll
            for (int i = 0; i < 8; i += 4)
                *(float4*)&a[i] = *(const float4*)&As[k][ty * 8 + i];
#pragma unroll
            for (int j = 0; j < 8; j += 4)
                *(float4*)&b[j] = *(const float4*)&Ws[k][tx * 8 + j];
#pragma unroll
            for (int i = 0; i < 8; ++i)
#pragma unroll
                for (int j = 0; j < 8; ++j)
                    acc[i][j] = fmaf(a[i], b[j], acc[i][j]);
        }
        __syncthreads();
    }
    int colBase = tx * 8;
#pragma unroll
    for (int i = 0; i < 8; ++i) {
        int r = row0 + ty * 8 + i;
        if (r >= M) break;
        if (colBase < HH) {
#pragma unroll
            for (int j = 0; j < 8; ++j)
                out_main[(size_t)r * HH + colBase + j] = acc[i][j] + __ldg(bias + colBase + j);
        } else {
#pragma unroll
            for (int j = 0; j < 8; ++j)
                out_aux[(size_t)r * HH + colBase - HH + j] = acc[i][j];
        }
    }
}

// out[M,128] = sum_s (relu?)A_s @ W_s + bias ; relu_mask bit s gates A_s reads
__global__ __launch_bounds__(256)
void gemm2_kernel(const float* __restrict__ A0, const float* __restrict__ W0,
                  const float* __restrict__ A1, const float* __restrict__ W1,
                  const float* __restrict__ bias, float* __restrict__ out,
                  int M, int nsrc, int relu_mask) {
    const int BM = 128, BK = 16;
    __shared__ float As[BK][BM + 4];
    __shared__ float Ws[BK][128];
    int tid = threadIdx.x;
    int tx = tid & 15, ty = tid >> 4;
    int row0 = blockIdx.x * BM;
    float acc[8][8];
#pragma unroll
    for (int i = 0; i < 8; ++i)
#pragma unroll
        for (int j = 0; j < 8; ++j) acc[i][j] = 0.f;

    const float* Aarr[2] = {A0, A1};
    const float* Warr[2] = {W0, W1};

    for (int s = 0; s < nsrc; ++s) {
        const float* A = Aarr[s];
        const float* W = Warr[s];
        int rl = (relu_mask >> s) & 1;
        for (int k0 = 0; k0 < 128; k0 += BK) {
#pragma unroll
            for (int i = 0; i < 2; ++i) {
                int idx = tid + i * 256;
                int r = idx >> 2, kq = idx & 3;
                int grow = row0 + r;
                float4 v = make_float4(0.f, 0.f, 0.f, 0.f);
                if (grow < M)
                    v = *(const float4*)(A + (size_t)grow * 128 + k0 + kq * 4);
                if (rl) {
                    v.x = fmaxf(v.x, 0.f); v.y = fmaxf(v.y, 0.f);
                    v.z = fmaxf(v.z, 0.f); v.w = fmaxf(v.w, 0.f);
                }
                As[kq * 4 + 0][r] = v.x;
                As[kq * 4 + 1][r] = v.y;
                As[kq * 4 + 2][r] = v.z;
                As[kq * 4 + 3][r] = v.w;
            }
#pragma unroll
            for (int i = 0; i < 2; ++i) {
                int idx = tid + i * 256;
                int kk = idx >> 5, cq = idx & 31;
                *(float4*)&Ws[kk][cq * 4] =
                    *(const float4*)(W + (size_t)(k0 + kk) * 128 + cq * 4);
            }
            __syncthreads();
#pragma unroll
            for (int k = 0; k < BK; ++k) {
                float a[8], b[8];
#pragma unroll
                for (int i = 0; i < 8; i += 4)
                    *(float4*)&a[i] = *(const float4*)&As[k][ty * 8 + i];
#pragma unroll
                for (int j = 0; j < 8; j += 4)
                    *(float4*)&b[j] = *(const float4*)&Ws[k][tx * 8 + j];
#pragma unroll
                for (int i = 0; i < 8; ++i)
#pragma unroll
                    for (int j = 0; j < 8; ++j)
                        acc[i][j] = fmaf(a[i], b[j], acc[i][j]);
            }
            __syncthreads();
        }
    }
#pragma unroll
    for (int i = 0; i < 8; ++i) {
        int r = row0 + ty * 8 + i;
        if (r >= M) break;
#pragma unroll
        for (int j = 0; j < 8; ++j)
            out[(size_t)r * 128 + tx * 8 + j] = acc[i][j] + __ldg(bias + tx * 8 + j);
    }
}

// ---------------- pooling + MLP --------------------------------------------
__global__ void pool_init_kernel(unsigned* __restrict__ pe) {
    int i = blockIdx.x * blockDim.x + threadIdx.x;
    if (i < GG * HH) pe[i] = 0x007FFFFFu;  // enc(-inf)
}

__global__ void pool_max_kernel(const float* __restrict__ xf,
                                const int* __restrict__ batch,
                                unsigned* __restrict__ pe, int n) {
    const int R = 1024;
    int base = blockIdx.x * R;
    if (base >= n) return;
    int end = min(base + R, n);
    int c = threadIdx.x;
    int cur = __ldg(batch + base);
    float m = -INFINITY;
    for (int r = base; r < end; ++r) {
        int g = __ldg(batch + r);
        if (g != cur) {
            atomicMax(&pe[cur * HH + c], enc_f(m));
            cur = g; m = -INFINITY;
        }
        m = fmaxf(m, xf[(size_t)r * HH + c]);
    }
    atomicMax(&pe[cur * HH + c], enc_f(m));
}

__global__ void pool_decode_kernel(const unsigned* __restrict__ pe,
                                   float* __restrict__ p) {
    int i = blockIdx.x * blockDim.x + threadIdx.x;
    if (i < GG * HH) p[i] = dec_f(pe[i]);
}

__global__ void mlp1_kernel(const float* __restrict__ pooled,
                            const float* __restrict__ Wc1,
                            const float* __restrict__ bc1,
                            float* __restrict__ h1) {
    int t = blockIdx.x * blockDim.x + threadIdx.x;
    if (t >= GG * 64) return;
    int g = t >> 6, c = t & 63;
    float acc = bc1[c];
    for (int k = 0; k < HH; ++k)
        acc = fmaf(pooled[g * HH + k], Wc1[k * 64 + c], acc);
    h1[t] = fmaxf(acc, 0.f);
}

__global__ void mlp2_kernel(const float* __restrict__ h1,
                            const float* __restrict__ Wc2,
                            const float* __restrict__ bc2,
                            float* __restrict__ h2) {
    int t = blockIdx.x * blockDim.x + threadIdx.x;
    if (t >= GG * HH) return;
    int g = t >> 7, c = t & 127;
    float acc = bc2[c];
    for (int k = 0; k < 64; ++k)
        acc = fmaf(h1[g * 64 + k], Wc2[k * HH + c], acc);
    h2[t] = fmaxf(acc, 0.f);
}

__global__ void mlp3_kernel(const float* __restrict__ h2,
                            const float* __restrict__ Wc3,
                            const float* __restrict__ bc3,
                            float* __restrict__ out) {
    int t = blockIdx.x * blockDim.x + threadIdx.x;
    if (t >= GG * 10) return;
    int g = t / 10, c = t % 10;
    float acc = bc3[c];
    for (int k = 0; k < HH; ++k)
        acc = fmaf(h2[g * HH + k], Wc3[k * 10 + c], acc);
    out[t] = acc;
}

// ---------------- host orchestration ---------------------------------------
extern "C" void kernel_launch(void* const* d_in, const int* in_sizes, int n_in,
                              void* d_out, int out_size) {
    const int*   host_ids  = (const int*)  d_in[0];
    const float* flow_x    = (const float*)d_in[1];
    const int*   h2f_src   = (const int*)  d_in[2];
    const int*   h2f_dst   = (const int*)  d_in[3];
    const int*   f2h_src   = (const int*)  d_in[4];
    const int*   f2h_dst   = (const int*)  d_in[5];
    const int*   rel_src   = (const int*)  d_in[6];
    const int*   rel_dst   = (const int*)  d_in[7];
    const int*   flow_batch= (const int*)  d_in[8];
    const float* host_embed= (const float*)d_in[9];
    const float* Wr0_h2f   = (const float*)d_in[10];
    const float* br0_h2f   = (const float*)d_in[11];
    const float* Wo0_h2f   = (const float*)d_in[12];
    const float* Wr0_f2h   = (const float*)d_in[13];
    const float* br0_f2h   = (const float*)d_in[14];
    const float* Wo0_f2h   = (const float*)d_in[15];
    const float* Wr0_rel   = (const float*)d_in[16];
    const float* br0_rel   = (const float*)d_in[17];
    const float* Wo0_rel   = (const float*)d_in[18];
    const float* Wr        = (const float*)d_in[19];  // [2,3,128,128]
    const float* br        = (const float*)d_in[20];  // [2,3,128]
    const float* Wo        = (const float*)d_in[21];  // [2,3,128,128]
    const float* Wc1       = (const float*)d_in[22];
    const float* bc1       = (const float*)d_in[23];
    const float* Wc2       = (const float*)d_in[24];
    const float* bc2       = (const float*)d_in[25];
    const float* Wc3       = (const float*)d_in[26];
    const float* bc3       = (const float*)d_in[27];
    float* out = (float*)d_out;

    float *xfA, *xfB, *trel, *th, *xhA, *xhB, *ah;
    float *WF, *Wf2hPad, *biasF, *zeroBias;
    unsigned* poolEnc; float *pooled, *h1, *h2;
    cudaGetSymbolAddress((void**)&xfA, g_xflowA);
    cudaGetSymbolAddress((void**)&xfB, g_xflowB);
    cudaGetSymbolAddress((void**)&trel, g_trel);
    cudaGetSymbolAddress((void**)&th,  g_th);
    cudaGetSymbolAddress((void**)&xhA, g_xhostA);
    cudaGetSymbolAddress((void**)&xhB, g_xhostB);
    cudaGetSymbolAddress((void**)&ah,  g_aggh);
    cudaGetSymbolAddress((void**)&WF,  g_WF);
    cudaGetSymbolAddress((void**)&Wf2hPad, g_Wf2hPad);
    cudaGetSymbolAddress((void**)&biasF,   g_biasF);
    cudaGetSymbolAddress((void**)&zeroBias, g_zeroBias);
    cudaGetSymbolAddress((void**)&poolEnc, g_poolEnc);
    cudaGetSymbolAddress((void**)&pooled,  g_pooled);
    cudaGetSymbolAddress((void**)&h1, g_h1);
    cudaGetSymbolAddress((void**)&h2, g_h2);

    prep_weights_kernel<<<HH, 256>>>(Wo0_h2f, Wo0_rel, Wr0_rel, Wr0_f2h,
                                     Wo, Wr, br0_h2f, br0_rel, br);
    embed_kernel<<<(N_HOST * HH + 255) / 256, 256>>>(host_ids, host_embed, xhA);
    pad_flow_kernel<<<(N_FLOW * HH + 255) / 256, 256>>>(flow_x, xfA);

    int flowBlocks = (N_FLOW + 127) / 128;
    int hostBlocks = (N_HOST + 127) / 128;

    float* fa = xfA; float* fb = xfB;
    float* ha = xhA; float* hb = xhB;

    for (int layer = 0; layer < 3; ++layer) {
        int relu_in = (layer > 0) ? 1 : 0;
        const float* WFl = WF + (size_t)layer * HH * 2 * HH;
        const float* bFl = biasF + (size_t)layer * HH;
        const float *WrH2F, *WrF2H, *WoF2H, *bH;
        if (layer == 0) {
            WrH2F = Wr0_h2f; WrF2H = Wf2hPad; WoF2H = Wo0_f2h; bH = br0_f2h;
        } else {
            int l = layer - 1;
            WrH2F = Wr + ((size_t)l * 3 + 0) * HH * HH;
            WrF2H = Wr + ((size_t)l * 3 + 1) * HH * HH;
            WoF2H = Wo + ((size_t)l * 3 + 1) * HH * HH;
            bH    = br + (l * 3 + 1) * HH;
        }

        // fb = (relu)fa @ WoComb + bias ; trel = (relu)fa @ Wr_rel
        gemm_dual_kernel<<<flowBlocks, 512>>>(fa, WFl, bFl, fb, trel, N_FLOW, relu_in);
        // th = (relu)ha @ Wr_h2f  (no bias)
        gemm2_kernel<<<hostBlocks, 256>>>(ha, WrH2F, nullptr, nullptr,
                                          zeroBias, th, N_HOST, 1, relu_in);

        // scatter transformed features directly into fb (pre-activation)
        scatter_add_kernel<<<(E_REL * 32 + 255) / 256, 256>>>(trel, rel_src, rel_dst, fb, E_REL, 0);
        scatter_add_kernel<<<(E_HF  * 32 + 255) / 256, 256>>>(th,   h2f_src, h2f_dst, fb, E_HF,  0);

        // hosts: aggregate-first for f2h
        cudaMemsetAsync(ah, 0, (size_t)N_HOST * HH * sizeof(float), 0);
        scatter_add_kernel<<<(E_HF * 32 + 255) / 256, 256>>>(fa, f2h_src, f2h_dst, ah, E_HF, relu_in);
        // hb = ah @ Wr_f2h + (relu)ha @ Wo_f2h + bias
        gemm2_kernel<<<hostBlocks, 256>>>(ah, WrF2H, ha, WoF2H, bH, hb,
                                          N_HOST, 2, relu_in << 1);

        float* t;
        t = fa; fa = fb; fb = t;
        t = ha; ha = hb; hb = t;
    }

    pool_init_kernel<<<(GG * HH + 255) / 256, 256>>>(poolEnc);
    pool_max_kernel<<<(N_FLOW + 1023) / 1024, HH>>>(fa, flow_batch, poolEnc, N_FLOW);
    pool_decode_kernel<<<(GG * HH + 255) / 256, 256>>>(poolEnc, pooled);

    mlp1_kernel<<<(GG * 64 + 255) / 256, 256>>>(pooled, Wc1, bc1, h1);
    mlp2_kernel<<<(GG * HH + 255) / 256, 256>>>(h1, Wc2, bc2, h2);
    mlp3_kernel<<<(GG * 10 + 255) / 256, 256>>>(h2, Wc3, bc3, out);
}

// round 3
// speedup vs baseline: 1.9468x; 1.5798x over previous
#include <cuda_runtime.h>
#include <math.h>
#include <stdint.h>

#define N_HOST 20000
#define N_FLOW 200000
#define E_HF   400000
#define E_REL  800000
#define GG     64
#define HH     128
#define FI     97

// ---------------- scratch (device globals; no allocation allowed) ----------
__device__ float g_xflowA[(size_t)N_FLOW * HH];   // ping
__device__ float g_xflowB[(size_t)N_FLOW * HH];   // pong
__device__ float g_trel  [(size_t)N_FLOW * HH];   // transformed flow (rel)
__device__ float g_th    [(size_t)N_HOST * HH];   // transformed host (h2f)
__device__ float g_xhostA[(size_t)N_HOST * HH];
__device__ float g_xhostB[(size_t)N_HOST * HH];
__device__ float g_aggh  [(size_t)N_HOST * HH];   // f2h aggregation into hosts

__device__ float g_WF[3][HH * 2 * HH];  // per layer: [128][256] = [WoComb | Wr_rel]
__device__ float g_Wf2hPad[HH * HH];    // pad(Wr0_f2h) 97->128 rows
__device__ float g_biasF[3][HH];        // br_h2f + br_rel per layer
__device__ float g_zeroBias[HH];        // zero-initialized device global

__device__ unsigned g_poolEnc[GG * HH];
__device__ float    g_pooled [GG * HH];
__device__ float    g_h1[GG * 64];
__device__ float    g_h2[GG * HH];

// ---------------- small helpers -------------------------------------------
__device__ __forceinline__ unsigned enc_f(float f) {
    unsigned u = __float_as_uint(f);
    return (u & 0x80000000u) ? ~u : (u | 0x80000000u);
}
__device__ __forceinline__ float dec_f(unsigned e) {
    return (e & 0x80000000u) ? __uint_as_float(e ^ 0x80000000u)
                             : __uint_as_float(~e);
}
__device__ __forceinline__ uint32_t f2tf32(float f) {
    uint32_t r;
    asm("cvt.rna.tf32.f32 %0, %1;" : "=r"(r) : "f"(f));
    return r;
}
__device__ __forceinline__ void mma_tf32(float4& d, const uint32_t* a,
                                         const uint32_t* b) {
    asm volatile(
        "mma.sync.aligned.m16n8k8.row.col.f32.tf32.tf32.f32 "
        "{%0,%1,%2,%3}, {%4,%5,%6,%7}, {%8,%9}, {%0,%1,%2,%3};"
        : "+f"(d.x), "+f"(d.y), "+f"(d.z), "+f"(d.w)
        : "r"(a[0]), "r"(a[1]), "r"(a[2]), "r"(a[3]), "r"(b[0]), "r"(b[1]));
}

// ---------------- prep ------------------------------------------------------
__global__ void embed_kernel(const int* __restrict__ ids,
                             const float* __restrict__ table,
                             float* __restrict__ xh) {
    int i = blockIdx.x * blockDim.x + threadIdx.x;
    if (i >= N_HOST * HH) return;
    int row = i >> 7, c = i & 127;
    xh[i] = table[(size_t)__ldg(ids + row) * HH + c];
}

__global__ void pad_flow_kernel(const float* __restrict__ fx,
                                float* __restrict__ xf) {
    int i = blockIdx.x * blockDim.x + threadIdx.x;
    if (i >= N_FLOW * HH) return;
    int row = i >> 7, c = i & 127;
    xf[i] = (c < FI) ? fx[(size_t)row * FI + c] : 0.f;
}

// grid: 128 blocks x 256 threads
__global__ void prep_weights_kernel(const float* __restrict__ Wo0_h2f,
                                    const float* __restrict__ Wo0_rel,
                                    const float* __restrict__ Wr0_rel,
                                    const float* __restrict__ Wr0_f2h,
                                    const float* __restrict__ Wo,   // [2,3,128,128]
                                    const float* __restrict__ Wr,   // [2,3,128,128]
                                    const float* __restrict__ br0_h2f,
                                    const float* __restrict__ br0_rel,
                                    const float* __restrict__ br) { // [2,3,128]
    int k = blockIdx.x;       // input dim 0..127
    int c = threadIdx.x;      // combined col 0..255
    int idx = k * 256 + c;
    if (c < HH) {
        g_WF[0][idx] = (k < FI) ? (Wo0_h2f[k * HH + c] + Wo0_rel[k * HH + c]) : 0.f;
        g_Wf2hPad[k * HH + c] = (k < FI) ? Wr0_f2h[k * HH + c] : 0.f;
    } else {
        int cc = c - HH;
        g_WF[0][idx] = (k < FI) ? Wr0_rel[k * HH + cc] : 0.f;
    }
    for (int l = 0; l < 2; ++l) {
        float v;
        if (c < HH)
            v = Wo[((size_t)l * 3 + 0) * HH * HH + k * HH + c]
              + Wo[((size_t)l * 3 + 2) * HH * HH + k * HH + c];
        else
            v = Wr[((size_t)l * 3 + 2) * HH * HH + k * HH + (c - HH)];
        g_WF[l + 1][idx] = v;
    }
    if (k == 0 && c < HH) {
        g_biasF[0][c] = br0_h2f[c] + br0_rel[c];
        for (int l = 0; l < 2; ++l)
            g_biasF[l + 1][c] = br[(l * 3 + 0) * HH + c] + br[(l * 3 + 2) * HH + c];
        g_zeroBias[c] = 0.f;
    }
}

// ---------------- scatter ---------------------------------------------------
__global__ void scatter_add_kernel(const float* __restrict__ src_feat,
                                   const int* __restrict__ esrc,
                                   const int* __restrict__ edst,
                                   float* __restrict__ dst_feat, int E,
                                   int relu_in) {
    int w = (blockIdx.x * blockDim.x + threadIdx.x) >> 5;
    int lane = threadIdx.x & 31;
    if (w >= E) return;
    int s = __ldg(esrc + w);
    int d = __ldg(edst + w);
    float4 v = ((const float4*)(src_feat + (size_t)s * HH))[lane];
    if (relu_in) {
        v.x = fmaxf(v.x, 0.f); v.y = fmaxf(v.y, 0.f);
        v.z = fmaxf(v.z, 0.f); v.w = fmaxf(v.w, 0.f);
    }
    float* dp = dst_feat + (size_t)d * HH + lane * 4;
    asm volatile("red.global.add.v4.f32 [%0], {%1,%2,%3,%4};"
                 :: "l"(dp), "f"(v.x), "f"(v.y), "f"(v.z), "f"(v.w)
                 : "memory");
}

// ---------------- tf32 tensor-core GEMM (flow path) -------------------------
// [out_main | out_aux] = (relu?)A[M,128] @ W[128,256]; bias only on main half
// 512 thr = 16 warps (4M x 4N), warp tile 32x64, BK=16, tf32 HMMA,
// double-buffered smem with register-staged prefetch.
__global__ __launch_bounds__(512, 1)
void gemm_dual_tc_kernel(const float* __restrict__ A, const float* __restrict__ W,
                         const float* __restrict__ bias,
                         float* __restrict__ out_main, float* __restrict__ out_aux,
                         int M, int relu_in) {
    const int BK = 16;
    __shared__ uint32_t As[2][BK][136];   // [k][m], pad 8 -> conflict-free frags
    __shared__ uint32_t Ws[2][BK][264];   // [k][n], pad 8

    int tid  = threadIdx.x;
    int warp = tid >> 5, lane = tid & 31;
    int wm = warp >> 2, wn = warp & 3;    // 4x4 warp grid
    int tg = lane & 3, gp = lane >> 2;
    int row0 = blockIdx.x * 128;

    float4 acc[2][8];
#pragma unroll
    for (int i = 0; i < 2; ++i)
#pragma unroll
        for (int j = 0; j < 8; ++j) acc[i][j] = make_float4(0.f, 0.f, 0.f, 0.f);

    // global load staging: A one float4/thread, W two float4/thread
    int a_r = tid >> 2, a_kq = tid & 3;
    int a_grow = row0 + a_r;
    float4 aREG;
    float4 wREG[2];

    // prologue: load k0=0 tile
    {
        aREG = make_float4(0.f, 0.f, 0.f, 0.f);
        if (a_grow < M)
            aREG = *(const float4*)(A + (size_t)a_grow * HH + a_kq * 4);
#pragma unroll
        for (int i = 0; i < 2; ++i) {
            int idx = tid + i * 512;
            int kk = idx >> 6, cq = idx & 63;
            wREG[i] = *(const float4*)(W + (size_t)kk * 256 + cq * 4);
        }
        if (relu_in) {
            aREG.x = fmaxf(aREG.x, 0.f); aREG.y = fmaxf(aREG.y, 0.f);
            aREG.z = fmaxf(aREG.z, 0.f); aREG.w = fmaxf(aREG.w, 0.f);
        }
        As[0][a_kq * 4 + 0][a_r] = f2tf32(aREG.x);
        As[0][a_kq * 4 + 1][a_r] = f2tf32(aREG.y);
        As[0][a_kq * 4 + 2][a_r] = f2tf32(aREG.z);
        As[0][a_kq * 4 + 3][a_r] = f2tf32(aREG.w);
#pragma unroll
        for (int i = 0; i < 2; ++i) {
            int idx = tid + i * 512;
            int kk = idx >> 6, cq = idx & 63;
            uint32_t* p = &Ws[0][kk][cq * 4];
            p[0] = f2tf32(wREG[i].x); p[1] = f2tf32(wREG[i].y);
            p[2] = f2tf32(wREG[i].z); p[3] = f2tf32(wREG[i].w);
        }
        __syncthreads();
    }

    const int NITER = HH / BK;  // 8
    for (int iter = 0; iter < NITER; ++iter) {
        int cur = iter & 1;
        // issue next tile's global loads (latency hidden behind MMAs)
        if (iter + 1 < NITER) {
            int k0 = (iter + 1) * BK;
            aREG = make_float4(0.f, 0.f, 0.f, 0.f);
            if (a_grow < M)
                aREG = *(const float4*)(A + (size_t)a_grow * HH + k0 + a_kq * 4);
#pragma unroll
            for (int i = 0; i < 2; ++i) {
                int idx = tid + i * 512;
                int kk = idx >> 6, cq = idx & 63;
                wREG[i] = *(const float4*)(W + (size_t)(k0 + kk) * 256 + cq * 4);
            }
        }
        // compute on current buffer
#pragma unroll
        for (int ks = 0; ks < BK; ks += 8) {
            uint32_t af[2][4];
            uint32_t bf[8][2];
#pragma unroll
            for (int mi = 0; mi < 2; ++mi) {
                int ar = wm * 32 + mi * 16 + gp;
                af[mi][0] = As[cur][ks + tg][ar];
                af[mi][1] = As[cur][ks + tg][ar + 8];
                af[mi][2] = As[cur][ks + tg + 4][ar];
                af[mi][3] = As[cur][ks + tg + 4][ar + 8];
            }
#pragma unroll
            for (int ni = 0; ni < 8; ++ni) {
                int nc = wn * 64 + ni * 8 + gp;
                bf[ni][0] = Ws[cur][ks + tg][nc];
                bf[ni][1] = Ws[cur][ks + tg + 4][nc];
            }
#pragma unroll
            for (int mi = 0; mi < 2; ++mi)
#pragma unroll
                for (int ni = 0; ni < 8; ++ni)
                    mma_tf32(acc[mi][ni], af[mi], bf[ni]);
        }
        // store prefetched tile into other buffer
        if (iter + 1 < NITER) {
            int nxt = 1 - cur;
            if (relu_in) {
                aREG.x = fmaxf(aREG.x, 0.f); aREG.y = fmaxf(aREG.y, 0.f);
                aREG.z = fmaxf(aREG.z, 0.f); aREG.w = fmaxf(aREG.w, 0.f);
            }
            As[nxt][a_kq * 4 + 0][a_r] = f2tf32(aREG.x);
            As[nxt][a_kq * 4 + 1][a_r] = f2tf32(aREG.y);
            As[nxt][a_kq * 4 + 2][a_r] = f2tf32(aREG.z);
            As[nxt][a_kq * 4 + 3][a_r] = f2tf32(aREG.w);
#pragma unroll
            for (int i = 0; i < 2; ++i) {
                int idx = tid + i * 512;
                int kk = idx >> 6, cq = idx & 63;
                uint32_t* p = &Ws[nxt][kk][cq * 4];
                p[0] = f2tf32(wREG[i].x); p[1] = f2tf32(wREG[i].y);
                p[2] = f2tf32(wREG[i].z); p[3] = f2tf32(wREG[i].w);
            }
        }
        __syncthreads();
    }

    // epilogue
#pragma unroll
    for (int ni = 0; ni < 8; ++ni) {
        int col = wn * 64 + ni * 8 + tg * 2;
        bool main_half = (col < HH);
        float b0 = 0.f, b1 = 0.f;
        if (main_half) { b0 = __ldg(bias + col); b1 = __ldg(bias + col + 1); }
        float* outp = main_half ? out_main : out_aux;
        int oc = main_half ? col : (col - HH);
#pragma unroll
        for (int mi = 0; mi < 2; ++mi) {
            int r0 = row0 + wm * 32 + mi * 16 + gp;
            int r1 = r0 + 8;
            float4 d = acc[mi][ni];
            if (r0 < M) {
                float2 v = make_float2(d.x + b0, d.y + b1);
                *(float2*)(outp + (size_t)r0 * HH + oc) = v;
            }
            if (r1 < M) {
                float2 v = make_float2(d.z + b0, d.w + b1);
                *(float2*)(outp + (size_t)r1 * HH + oc) = v;
            }
        }
    }
}

// ---------------- fp32 GEMM (host path, small) ------------------------------
// out[M,128] = sum_s (relu?)A_s @ W_s + bias ; relu_mask bit s gates A_s reads
__global__ __launch_bounds__(256)
void gemm2_kernel(const float* __restrict__ A0, const float* __restrict__ W0,
                  const float* __restrict__ A1, const float* __restrict__ W1,
                  const float* __restrict__ bias, float* __restrict__ out,
                  int M, int nsrc, int relu_mask) {
    const int BM = 128, BK = 16;
    __shared__ float As[BK][BM + 4];
    __shared__ float Ws[BK][128];
    int tid = threadIdx.x;
    int tx = tid & 15, ty = tid >> 4;
    int row0 = blockIdx.x * BM;
    float acc[8][8];
#pragma unroll
    for (int i = 0; i < 8; ++i)
#pragma unroll
        for (int j = 0; j < 8; ++j) acc[i][j] = 0.f;

    const float* Aarr[2] = {A0, A1};
    const float* Warr[2] = {W0, W1};

    for (int s = 0; s < nsrc; ++s) {
        const float* A = Aarr[s];
        const float* W = Warr[s];
        int rl = (relu_mask >> s) & 1;
        for (int k0 = 0; k0 < 128; k0 += BK) {
#pragma unroll
            for (int i = 0; i < 2; ++i) {
                int idx = tid + i * 256;
                int r = idx >> 2, kq = idx & 3;
                int grow = row0 + r;
                float4 v = make_float4(0.f, 0.f, 0.f, 0.f);
                if (grow < M)
                    v = *(const float4*)(A + (size_t)grow * 128 + k0 + kq * 4);
                if (rl) {
                    v.x = fmaxf(v.x, 0.f); v.y = fmaxf(v.y, 0.f);
                    v.z = fmaxf(v.z, 0.f); v.w = fmaxf(v.w, 0.f);
                }
                As[kq * 4 + 0][r] = v.x;
                As[kq * 4 + 1][r] = v.y;
                As[kq * 4 + 2][r] = v.z;
                As[kq * 4 + 3][r] = v.w;
            }
#pragma unroll
            for (int i = 0; i < 2; ++i) {
                int idx = tid + i * 256;
                int kk = idx >> 5, cq = idx & 31;
                *(float4*)&Ws[kk][cq * 4] =
                    *(const float4*)(W + (size_t)(k0 + kk) * 128 + cq * 4);
            }
            __syncthreads();
#pragma unroll
            for (int k = 0; k < BK; ++k) {
                float a[8], b[8];
#pragma unroll
                for (int i = 0; i < 8; i += 4)
                    *(float4*)&a[i] = *(const float4*)&As[k][ty * 8 + i];
#pragma unroll
                for (int j = 0; j < 8; j += 4)
                    *(float4*)&b[j] = *(const float4*)&Ws[k][tx * 8 + j];
#pragma unroll
                for (int i = 0; i < 8; ++i)
#pragma unroll
                    for (int j = 0; j < 8; ++j)
                        acc[i][j] = fmaf(a[i], b[j], acc[i][j]);
            }
            __syncthreads();
        }
    }
#pragma unroll
    for (int i = 0; i < 8; ++i) {
        int r = row0 + ty * 8 + i;
        if (r >= M) break;
#pragma unroll
        for (int j = 0; j < 8; ++j)
            out[(size_t)r * 128 + tx * 8 + j] = acc[i][j] + __ldg(bias + tx * 8 + j);
    }
}

// ---------------- pooling + MLP --------------------------------------------
__global__ void pool_init_kernel(unsigned* __restrict__ pe) {
    int i = blockIdx.x * blockDim.x + threadIdx.x;
    if (i < GG * HH) pe[i] = 0x007FFFFFu;  // enc(-inf)
}

__global__ void pool_max_kernel(const float* __restrict__ xf,
                                const int* __restrict__ batch,
                                unsigned* __restrict__ pe, int n) {
    const int R = 256;
    int base = blockIdx.x * R;
    if (base >= n) return;
    int end = min(base + R, n);
    int c = threadIdx.x;
    int cur = __ldg(batch + base);
    float m = -INFINITY;
    for (int r = base; r < end; ++r) {
        int g = __ldg(batch + r);
        if (g != cur) {
            atomicMax(&pe[cur * HH + c], enc_f(m));
            cur = g; m = -INFINITY;
        }
        m = fmaxf(m, xf[(size_t)r * HH + c]);
    }
    atomicMax(&pe[cur * HH + c], enc_f(m));
}

__global__ void pool_decode_kernel(const unsigned* __restrict__ pe,
                                   float* __restrict__ p) {
    int i = blockIdx.x * blockDim.x + threadIdx.x;
    if (i < GG * HH) p[i] = dec_f(pe[i]);
}

__global__ void mlp1_kernel(const float* __restrict__ pooled,
                            const float* __restrict__ Wc1,
                            const float* __restrict__ bc1,
                            float* __restrict__ h1) {
    int t = blockIdx.x * blockDim.x + threadIdx.x;
    if (t >= GG * 64) return;
    int g = t >> 6, c = t & 63;
    float acc = bc1[c];
    for (int k = 0; k < HH; ++k)
        acc = fmaf(pooled[g * HH + k], Wc1[k * 64 + c], acc);
    h1[t] = fmaxf(acc, 0.f);
}

__global__ void mlp2_kernel(const float* __restrict__ h1,
                            const float* __restrict__ Wc2,
                            const float* __restrict__ bc2,
                            float* __restrict__ h2) {
    int t = blockIdx.x * blockDim.x + threadIdx.x;
    if (t >= GG * HH) return;
    int g = t >> 7, c = t & 127;
    float acc = bc2[c];
    for (int k = 0; k < 64; ++k)
        acc = fmaf(h1[g * 64 + k], Wc2[k * HH + c], acc);
    h2[t] = fmaxf(acc, 0.f);
}

__global__ void mlp3_kernel(const float* __restrict__ h2,
                            const float* __restrict__ Wc3,
                            const float* __restrict__ bc3,
                            float* __restrict__ out) {
    int t = blockIdx.x * blockDim.x + threadIdx.x;
    if (t >= GG * 10) return;
    int g = t / 10, c = t % 10;
    float acc = bc3[c];
    for (int k = 0; k < HH; ++k)
        acc = fmaf(h2[g * HH + k], Wc3[k * 10 + c], acc);
    out[t] = acc;
}

// ---------------- host orchestration ---------------------------------------
extern "C" void kernel_launch(void* const* d_in, const int* in_sizes, int n_in,
                              void* d_out, int out_size) {
    const int*   host_ids  = (const int*)  d_in[0];
    const float* flow_x    = (const float*)d_in[1];
    const int*   h2f_src   = (const int*)  d_in[2];
    const int*   h2f_dst   = (const int*)  d_in[3];
    const int*   f2h_src   = (const int*)  d_in[4];
    const int*   f2h_dst   = (const int*)  d_in[5];
    const int*   rel_src   = (const int*)  d_in[6];
    const int*   rel_dst   = (const int*)  d_in[7];
    const int*   flow_batch= (const int*)  d_in[8];
    const float* host_embed= (const float*)d_in[9];
    const float* Wr0_h2f   = (const float*)d_in[10];
    const float* br0_h2f   = (const float*)d_in[11];
    const float* Wo0_h2f   = (const float*)d_in[12];
    const float* Wr0_f2h   = (const float*)d_in[13];
    const float* br0_f2h   = (const float*)d_in[14];
    const float* Wo0_f2h   = (const float*)d_in[15];
    const float* Wr0_rel   = (const float*)d_in[16];
    const float* br0_rel   = (const float*)d_in[17];
    const float* Wo0_rel   = (const float*)d_in[18];
    const float* Wr        = (const float*)d_in[19];  // [2,3,128,128]
    const float* br        = (const float*)d_in[20];  // [2,3,128]
    const float* Wo        = (const float*)d_in[21];  // [2,3,128,128]
    const float* Wc1       = (const float*)d_in[22];
    const float* bc1       = (const float*)d_in[23];
    const float* Wc2       = (const float*)d_in[24];
    const float* bc2       = (const float*)d_in[25];
    const float* Wc3       = (const float*)d_in[26];
    const float* bc3       = (const float*)d_in[27];
    float* out = (float*)d_out;

    float *xfA, *xfB, *trel, *th, *xhA, *xhB, *ah;
    float *WF, *Wf2hPad, *biasF, *zeroBias;
    unsigned* poolEnc; float *pooled, *h1, *h2;
    cudaGetSymbolAddress((void**)&xfA, g_xflowA);
    cudaGetSymbolAddress((void**)&xfB, g_xflowB);
    cudaGetSymbolAddress((void**)&trel, g_trel);
    cudaGetSymbolAddress((void**)&th,  g_th);
    cudaGetSymbolAddress((void**)&xhA, g_xhostA);
    cudaGetSymbolAddress((void**)&xhB, g_xhostB);
    cudaGetSymbolAddress((void**)&ah,  g_aggh);
    cudaGetSymbolAddress((void**)&WF,  g_WF);
    cudaGetSymbolAddress((void**)&Wf2hPad, g_Wf2hPad);
    cudaGetSymbolAddress((void**)&biasF,   g_biasF);
    cudaGetSymbolAddress((void**)&zeroBias, g_zeroBias);
    cudaGetSymbolAddress((void**)&poolEnc, g_poolEnc);
    cudaGetSymbolAddress((void**)&pooled,  g_pooled);
    cudaGetSymbolAddress((void**)&h1, g_h1);
    cudaGetSymbolAddress((void**)&h2, g_h2);

    prep_weights_kernel<<<HH, 256>>>(Wo0_h2f, Wo0_rel, Wr0_rel, Wr0_f2h,
                                     Wo, Wr, br0_h2f, br0_rel, br);
    embed_kernel<<<(N_HOST * HH + 255) / 256, 256>>>(host_ids, host_embed, xhA);
    pad_flow_kernel<<<(N_FLOW * HH + 255) / 256, 256>>>(flow_x, xfA);

    int flowBlocks = (N_FLOW + 127) / 128;
    int hostBlocks = (N_HOST + 127) / 128;

    float* fa = xfA; float* fb = xfB;
    float* ha = xhA; float* hb = xhB;

    for (int layer = 0; layer < 3; ++layer) {
        int relu_in = (layer > 0) ? 1 : 0;
        const float* WFl = WF + (size_t)layer * HH * 2 * HH;
        const float* bFl = biasF + (size_t)layer * HH;
        const float *WrH2F, *WrF2H, *WoF2H, *bH;
        if (layer == 0) {
            WrH2F = Wr0_h2f; WrF2H = Wf2hPad; WoF2H = Wo0_f2h; bH = br0_f2h;
        } else {
            int l = layer - 1;
            WrH2F = Wr + ((size_t)l * 3 + 0) * HH * HH;
            WrF2H = Wr + ((size_t)l * 3 + 1) * HH * HH;
            WoF2H = Wo + ((size_t)l * 3 + 1) * HH * HH;
            bH    = br + (l * 3 + 1) * HH;
        }

        // fb = (relu)fa @ WoComb + bias ; trel = (relu)fa @ Wr_rel  (tf32 TC)
        gemm_dual_tc_kernel<<<flowBlocks, 512>>>(fa, WFl, bFl, fb, trel, N_FLOW, relu_in);
        // th = (relu)ha @ Wr_h2f  (no bias)
        gemm2_kernel<<<hostBlocks, 256>>>(ha, WrH2F, nullptr, nullptr,
                                          zeroBias, th, N_HOST, 1, relu_in);

        // scatter transformed features directly into fb (pre-activation)
        scatter_add_kernel<<<(E_REL * 32 + 255) / 256, 256>>>(trel, rel_src, rel_dst, fb, E_REL, 0);
        scatter_add_kernel<<<(E_HF  * 32 + 255) / 256, 256>>>(th,   h2f_src, h2f_dst, fb, E_HF,  0);

        // hosts: aggregate-first for f2h
        cudaMemsetAsync(ah, 0, (size_t)N_HOST * HH * sizeof(float), 0);
        scatter_add_kernel<<<(E_HF * 32 + 255) / 256, 256>>>(fa, f2h_src, f2h_dst, ah, E_HF, relu_in);
        // hb = ah @ Wr_f2h + (relu)ha @ Wo_f2h + bias
        gemm2_kernel<<<hostBlocks, 256>>>(ah, WrF2H, ha, WoF2H, bH, hb,
                                          N_HOST, 2, relu_in << 1);

        float* t;
        t = fa; fa = fb; fb = t;
        t = ha; ha = hb; hb = t;
    }

    pool_init_kernel<<<(GG * HH + 255) / 256, 256>>>(poolEnc);
    pool_max_kernel<<<(N_FLOW + 255) / 256, HH>>>(fa, flow_batch, poolEnc, N_FLOW);
    pool_decode_kernel<<<(GG * HH + 255) / 256, 256>>>(poolEnc, pooled);

    mlp1_kernel<<<(GG * 64 + 255) / 256, 256>>>(pooled, Wc1, bc1, h1);
    mlp2_kernel<<<(GG * HH + 255) / 256, 256>>>(h1, Wc2, bc2, h2);
    mlp3_kernel<<<(GG * 10 + 255) / 256, 256>>>(h2, Wc3, bc3, out);
}

// round 4
// speedup vs baseline: 2.3369x; 1.2004x over previous
#include <cuda_runtime.h>
#include <math.h>
#include <stdint.h>

#define N_HOST 20000
#define N_FLOW 200000
#define E_HF   400000
#define E_REL  800000
#define GG     64
#define HH     128
#define FI     97
#define SCAN_BLK 1024

// ---------------- scratch (device globals; no allocation allowed) ----------
__device__ float g_xflowA[(size_t)N_FLOW * HH];   // ping
__device__ float g_xflowB[(size_t)N_FLOW * HH];   // pong
__device__ float g_trel  [(size_t)N_FLOW * HH];   // transformed flow (rel)
__device__ float g_th    [(size_t)N_HOST * HH];   // transformed host (h2f)
__device__ float g_xhostA[(size_t)N_HOST * HH];
__device__ float g_xhostB[(size_t)N_HOST * HH];
__device__ float g_aggh  [(size_t)N_HOST * HH];   // f2h aggregation into hosts

__device__ float g_WF[3][HH * 2 * HH];  // per layer: [128][256] = [WoComb | Wr_rel]
__device__ float g_Wf2hPad[HH * HH];    // pad(Wr0_f2h) 97->128 rows
__device__ float g_biasF[3][HH];        // br_h2f + br_rel per layer
__device__ float g_zeroBias[HH];        // zero-initialized device global

// CSR scratch (built once per launch, reused across layers)
__device__ int g_csr_rel[E_REL];
__device__ int g_csr_h2f[E_HF];
__device__ int g_csr_f2h[E_HF];
__device__ int g_off_rel[N_FLOW + 1];
__device__ int g_off_h2f[N_FLOW + 1];
__device__ int g_off_f2h[N_HOST + 1];
__device__ int g_cur_rel[N_FLOW];
__device__ int g_cur_h2f[N_FLOW];
__device__ int g_cur_f2h[N_HOST];
__device__ int g_cnt_rel[N_FLOW];
__device__ int g_cnt_h2f[N_FLOW];
__device__ int g_cnt_f2h[N_HOST];
__device__ int g_bsum[3][256];

__device__ unsigned g_poolEnc[GG * HH];
__device__ float    g_pooled [GG * HH];
__device__ float    g_h1[GG * 64];
__device__ float    g_h2[GG * HH];

// ---------------- small helpers -------------------------------------------
__device__ __forceinline__ unsigned enc_f(float f) {
    unsigned u = __float_as_uint(f);
    return (u & 0x80000000u) ? ~u : (u | 0x80000000u);
}
__device__ __forceinline__ float dec_f(unsigned e) {
    return (e & 0x80000000u) ? __uint_as_float(e ^ 0x80000000u)
                             : __uint_as_float(~e);
}
__device__ __forceinline__ uint32_t f2tf32(float f) {
    uint32_t r;
    asm("cvt.rna.tf32.f32 %0, %1;" : "=r"(r) : "f"(f));
    return r;
}
__device__ __forceinline__ void mma_tf32(float4& d, const uint32_t* a,
                                         const uint32_t* b) {
    asm volatile(
        "mma.sync.aligned.m16n8k8.row.col.f32.tf32.tf32.f32 "
        "{%0,%1,%2,%3}, {%4,%5,%6,%7}, {%8,%9}, {%0,%1,%2,%3};"
        : "+f"(d.x), "+f"(d.y), "+f"(d.z), "+f"(d.w)
        : "r"(a[0]), "r"(a[1]), "r"(a[2]), "r"(a[3]), "r"(b[0]), "r"(b[1]));
}

// ---------------- CSR construction -----------------------------------------
__global__ void hist_kernel(const int* __restrict__ dst, int* __restrict__ cnt,
                            int E) {
    int i = blockIdx.x * blockDim.x + threadIdx.x;
    if (i < E) atomicAdd(&cnt[__ldg(dst + i)], 1);
}

// per-block exclusive scan; writes block totals
__global__ void scanA_kernel(const int* __restrict__ cnt, int* __restrict__ off,
                             int* __restrict__ bsum, int n) {
    __shared__ int sh[SCAN_BLK];
    int tx = threadIdx.x;
    int i = blockIdx.x * SCAN_BLK + tx;
    int v = (i < n) ? cnt[i] : 0;
    sh[tx] = v;
    __syncthreads();
    for (int d = 1; d < SCAN_BLK; d <<= 1) {
        int t = (tx >= d) ? sh[tx - d] : 0;
        __syncthreads();
        sh[tx] += t;
        __syncthreads();
    }
    if (i < n) off[i] = sh[tx] - v;          // exclusive
    if (tx == SCAN_BLK - 1) bsum[blockIdx.x] = sh[tx];
}

// single block: exclusive scan of block sums (nb <= 256)
__global__ void scanB_kernel(int* __restrict__ bsum, int nb) {
    __shared__ int sh[256];
    int tx = threadIdx.x;
    int v = (tx < nb) ? bsum[tx] : 0;
    sh[tx] = v;
    __syncthreads();
    for (int d = 1; d < 256; d <<= 1) {
        int t = (tx >= d) ? sh[tx - d] : 0;
        __syncthreads();
        sh[tx] += t;
        __syncthreads();
    }
    if (tx < nb) bsum[tx] = sh[tx] - v;
}

// add block offsets, init cursor, write sentinel off[n]=E
__global__ void scanC_kernel(int* __restrict__ off, int* __restrict__ cur,
                             const int* __restrict__ bsum, int n, int E) {
    int i = blockIdx.x * SCAN_BLK + threadIdx.x;
    if (i < n) {
        int o = off[i] + bsum[blockIdx.x];
        off[i] = o;
        cur[i] = o;
    }
    if (i == 0) off[n] = E;
}

__global__ void fill_kernel(const int* __restrict__ src, const int* __restrict__ dst,
                            int* __restrict__ cur, int* __restrict__ csr, int E) {
    int i = blockIdx.x * blockDim.x + threadIdx.x;
    if (i < E) {
        int d = __ldg(dst + i);
        int p = atomicAdd(&cur[d], 1);
        csr[p] = __ldg(src + i);
    }
}

// ---------------- gathers ---------------------------------------------------
// warp per flow node: fb += sum_rel trel[src] + sum_h2f th[src]
__global__ void gather_flow_kernel(const float* __restrict__ trel,
                                   const float* __restrict__ th,
                                   const int* __restrict__ off_rel,
                                   const int* __restrict__ csr_rel,
                                   const int* __restrict__ off_h2f,
                                   const int* __restrict__ csr_h2f,
                                   float* __restrict__ fb) {
    int w = (blockIdx.x * blockDim.x + threadIdx.x) >> 5;
    int lane = threadIdx.x & 31;
    if (w >= N_FLOW) return;
    float4* fp = (float4*)(fb + (size_t)w * HH);
    float4 acc = fp[lane];
    int b = __ldg(off_rel + w), e = __ldg(off_rel + w + 1);
    for (int i = b; i < e; ++i) {
        int s = __ldg(csr_rel + i);
        float4 v = ((const float4*)(trel + (size_t)s * HH))[lane];
        acc.x += v.x; acc.y += v.y; acc.z += v.z; acc.w += v.w;
    }
    b = __ldg(off_h2f + w); e = __ldg(off_h2f + w + 1);
    for (int i = b; i < e; ++i) {
        int s = __ldg(csr_h2f + i);
        float4 v = ((const float4*)(th + (size_t)s * HH))[lane];
        acc.x += v.x; acc.y += v.y; acc.z += v.z; acc.w += v.w;
    }
    fp[lane] = acc;
}

// warp per host node: ah = sum_f2h (relu?)fa[src]
__global__ void gather_host_kernel(const float* __restrict__ fa,
                                   const int* __restrict__ off,
                                   const int* __restrict__ csr,
                                   float* __restrict__ ah, int relu_in) {
    int w = (blockIdx.x * blockDim.x + threadIdx.x) >> 5;
    int lane = threadIdx.x & 31;
    if (w >= N_HOST) return;
    float4 acc = make_float4(0.f, 0.f, 0.f, 0.f);
    int b = __ldg(off + w), e = __ldg(off + w + 1);
    for (int i = b; i < e; ++i) {
        int s = __ldg(csr + i);
        float4 v = ((const float4*)(fa + (size_t)s * HH))[lane];
        if (relu_in) {
            v.x = fmaxf(v.x, 0.f); v.y = fmaxf(v.y, 0.f);
            v.z = fmaxf(v.z, 0.f); v.w = fmaxf(v.w, 0.f);
        }
        acc.x += v.x; acc.y += v.y; acc.z += v.z; acc.w += v.w;
    }
    ((float4*)(ah + (size_t)w * HH))[lane] = acc;
}

// ---------------- prep ------------------------------------------------------
__global__ void embed_kernel(const int* __restrict__ ids,
                             const float* __restrict__ table,
                             float* __restrict__ xh) {
    int i = blockIdx.x * blockDim.x + threadIdx.x;
    if (i >= N_HOST * HH) return;
    int row = i >> 7, c = i & 127;
    xh[i] = table[(size_t)__ldg(ids + row) * HH + c];
}

__global__ void pad_flow_kernel(const float* __restrict__ fx,
                                float* __restrict__ xf) {
    int i = blockIdx.x * blockDim.x + threadIdx.x;
    if (i >= N_FLOW * HH) return;
    int row = i >> 7, c = i & 127;
    xf[i] = (c < FI) ? fx[(size_t)row * FI + c] : 0.f;
}

// grid: 128 blocks x 256 threads
__global__ void prep_weights_kernel(const float* __restrict__ Wo0_h2f,
                                    const float* __restrict__ Wo0_rel,
                                    const float* __restrict__ Wr0_rel,
                                    const float* __restrict__ Wr0_f2h,
                                    const float* __restrict__ Wo,   // [2,3,128,128]
                                    const float* __restrict__ Wr,   // [2,3,128,128]
                                    const float* __restrict__ br0_h2f,
                                    const float* __restrict__ br0_rel,
                                    const float* __restrict__ br) { // [2,3,128]
    int k = blockIdx.x;
    int c = threadIdx.x;
    int idx = k * 256 + c;
    if (c < HH) {
        g_WF[0][idx] = (k < FI) ? (Wo0_h2f[k * HH + c] + Wo0_rel[k * HH + c]) : 0.f;
        g_Wf2hPad[k * HH + c] = (k < FI) ? Wr0_f2h[k * HH + c] : 0.f;
    } else {
        int cc = c - HH;
        g_WF[0][idx] = (k < FI) ? Wr0_rel[k * HH + cc] : 0.f;
    }
    for (int l = 0; l < 2; ++l) {
        float v;
        if (c < HH)
            v = Wo[((size_t)l * 3 + 0) * HH * HH + k * HH + c]
              + Wo[((size_t)l * 3 + 2) * HH * HH + k * HH + c];
        else
            v = Wr[((size_t)l * 3 + 2) * HH * HH + k * HH + (c - HH)];
        g_WF[l + 1][idx] = v;
    }
    if (k == 0 && c < HH) {
        g_biasF[0][c] = br0_h2f[c] + br0_rel[c];
        for (int l = 0; l < 2; ++l)
            g_biasF[l + 1][c] = br[(l * 3 + 0) * HH + c] + br[(l * 3 + 2) * HH + c];
        g_zeroBias[c] = 0.f;
    }
}

// ---------------- tf32 tensor-core GEMM (flow path) -------------------------
__global__ __launch_bounds__(512, 1)
void gemm_dual_tc_kernel(const float* __restrict__ A, const float* __restrict__ W,
                         const float* __restrict__ bias,
                         float* __restrict__ out_main, float* __restrict__ out_aux,
                         int M, int relu_in) {
    const int BK = 16;
    __shared__ uint32_t As[2][BK][136];
    __shared__ uint32_t Ws[2][BK][264];

    int tid  = threadIdx.x;
    int warp = tid >> 5, lane = tid & 31;
    int wm = warp >> 2, wn = warp & 3;
    int tg = lane & 3, gp = lane >> 2;
    int row0 = blockIdx.x * 128;

    float4 acc[2][8];
#pragma unroll
    for (int i = 0; i < 2; ++i)
#pragma unroll
        for (int j = 0; j < 8; ++j) acc[i][j] = make_float4(0.f, 0.f, 0.f, 0.f);

    int a_r = tid >> 2, a_kq = tid & 3;
    int a_grow = row0 + a_r;
    float4 aREG;
    float4 wREG[2];

    {
        aREG = make_float4(0.f, 0.f, 0.f, 0.f);
        if (a_grow < M)
            aREG = *(const float4*)(A + (size_t)a_grow * HH + a_kq * 4);
#pragma unroll
        for (int i = 0; i < 2; ++i) {
            int idx = tid + i * 512;
            int kk = idx >> 6, cq = idx & 63;
            wREG[i] = *(const float4*)(W + (size_t)kk * 256 + cq * 4);
        }
        if (relu_in) {
            aREG.x = fmaxf(aREG.x, 0.f); aREG.y = fmaxf(aREG.y, 0.f);
            aREG.z = fmaxf(aREG.z, 0.f); aREG.w = fmaxf(aREG.w, 0.f);
        }
        As[0][a_kq * 4 + 0][a_r] = f2tf32(aREG.x);
        As[0][a_kq * 4 + 1][a_r] = f2tf32(aREG.y);
        As[0][a_kq * 4 + 2][a_r] = f2tf32(aREG.z);
        As[0][a_kq * 4 + 3][a_r] = f2tf32(aREG.w);
#pragma unroll
        for (int i = 0; i < 2; ++i) {
            int idx = tid + i * 512;
            int kk = idx >> 6, cq = idx & 63;
            uint32_t* p = &Ws[0][kk][cq * 4];
            p[0] = f2tf32(wREG[i].x); p[1] = f2tf32(wREG[i].y);
            p[2] = f2tf32(wREG[i].z); p[3] = f2tf32(wREG[i].w);
        }
        __syncthreads();
    }

    const int NITER = HH / BK;
    for (int iter = 0; iter < NITER; ++iter) {
        int cur = iter & 1;
        if (iter + 1 < NITER) {
            int k0 = (iter + 1) * BK;
            aREG = make_float4(0.f, 0.f, 0.f, 0.f);
            if (a_grow < M)
                aREG = *(const float4*)(A + (size_t)a_grow * HH + k0 + a_kq * 4);
#pragma unroll
            for (int i = 0; i < 2; ++i) {
                int idx = tid + i * 512;
                int kk = idx >> 6, cq = idx & 63;
                wREG[i] = *(const float4*)(W + (size_t)(k0 + kk) * 256 + cq * 4);
            }
        }
#pragma unroll
        for (int ks = 0; ks < BK; ks += 8) {
            uint32_t af[2][4];
            uint32_t bf[8][2];
#pragma unroll
            for (int mi = 0; mi < 2; ++mi) {
                int ar = wm * 32 + mi * 16 + gp;
                af[mi][0] = As[cur][ks + tg][ar];
                af[mi][1] = As[cur][ks + tg][ar + 8];
                af[mi][2] = As[cur][ks + tg + 4][ar];
                af[mi][3] = As[cur][ks + tg + 4][ar + 8];
            }
#pragma unroll
            for (int ni = 0; ni < 8; ++ni) {
                int nc = wn * 64 + ni * 8 + gp;
                bf[ni][0] = Ws[cur][ks + tg][nc];
                bf[ni][1] = Ws[cur][ks + tg + 4][nc];
            }
#pragma unroll
            for (int mi = 0; mi < 2; ++mi)
#pragma unroll
                for (int ni = 0; ni < 8; ++ni)
                    mma_tf32(acc[mi][ni], af[mi], bf[ni]);
        }
        if (iter + 1 < NITER) {
            int nxt = 1 - cur;
            if (relu_in) {
                aREG.x = fmaxf(aREG.x, 0.f); aREG.y = fmaxf(aREG.y, 0.f);
                aREG.z = fmaxf(aREG.z, 0.f); aREG.w = fmaxf(aREG.w, 0.f);
            }
            As[nxt][a_kq * 4 + 0][a_r] = f2tf32(aREG.x);
            As[nxt][a_kq * 4 + 1][a_r] = f2tf32(aREG.y);
            As[nxt][a_kq * 4 + 2][a_r] = f2tf32(aREG.z);
            As[nxt][a_kq * 4 + 3][a_r] = f2tf32(aREG.w);
#pragma unroll
            for (int i = 0; i < 2; ++i) {
                int idx = tid + i * 512;
                int kk = idx >> 6, cq = idx & 63;
                uint32_t* p = &Ws[nxt][kk][cq * 4];
                p[0] = f2tf32(wREG[i].x); p[1] = f2tf32(wREG[i].y);
                p[2] = f2tf32(wREG[i].z); p[3] = f2tf32(wREG[i].w);
            }
        }
        __syncthreads();
    }

#pragma unroll
    for (int ni = 0; ni < 8; ++ni) {
        int col = wn * 64 + ni * 8 + tg * 2;
        bool main_half = (col < HH);
        float b0 = 0.f, b1 = 0.f;
        if (main_half) { b0 = __ldg(bias + col); b1 = __ldg(bias + col + 1); }
        float* outp = main_half ? out_main : out_aux;
        int oc = main_half ? col : (col - HH);
#pragma unroll
        for (int mi = 0; mi < 2; ++mi) {
            int r0 = row0 + wm * 32 + mi * 16 + gp;
            int r1 = r0 + 8;
            float4 d = acc[mi][ni];
            if (r0 < M) {
                float2 v = make_float2(d.x + b0, d.y + b1);
                *(float2*)(outp + (size_t)r0 * HH + oc) = v;
            }
            if (r1 < M) {
                float2 v = make_float2(d.z + b0, d.w + b1);
                *(float2*)(outp + (size_t)r1 * HH + oc) = v;
            }
        }
    }
}

// ---------------- fp32 GEMM (host path, small) ------------------------------
__global__ __launch_bounds__(256)
void gemm2_kernel(const float* __restrict__ A0, const float* __restrict__ W0,
                  const float* __restrict__ A1, const float* __restrict__ W1,
                  const float* __restrict__ bias, float* __restrict__ out,
                  int M, int nsrc, int relu_mask) {
    const int BM = 128, BK = 16;
    __shared__ float As[BK][BM + 4];
    __shared__ float Ws[BK][128];
    int tid = threadIdx.x;
    int tx = tid & 15, ty = tid >> 4;
    int row0 = blockIdx.x * BM;
    float acc[8][8];
#pragma unroll
    for (int i = 0; i < 8; ++i)
#pragma unroll
        for (int j = 0; j < 8; ++j) acc[i][j] = 0.f;

    const float* Aarr[2] = {A0, A1};
    const float* Warr[2] = {W0, W1};

    for (int s = 0; s < nsrc; ++s) {
        const float* A = Aarr[s];
        const float* W = Warr[s];
        int rl = (relu_mask >> s) & 1;
        for (int k0 = 0; k0 < 128; k0 += BK) {
#pragma unroll
            for (int i = 0; i < 2; ++i) {
                int idx = tid + i * 256;
                int r = idx >> 2, kq = idx & 3;
                int grow = row0 + r;
                float4 v = make_float4(0.f, 0.f, 0.f, 0.f);
                if (grow < M)
                    v = *(const float4*)(A + (size_t)grow * 128 + k0 + kq * 4);
                if (rl) {
                    v.x = fmaxf(v.x, 0.f); v.y = fmaxf(v.y, 0.f);
                    v.z = fmaxf(v.z, 0.f); v.w = fmaxf(v.w, 0.f);
                }
                As[kq * 4 + 0][r] = v.x;
                As[kq * 4 + 1][r] = v.y;
                As[kq * 4 + 2][r] = v.z;
                As[kq * 4 + 3][r] = v.w;
            }
#pragma unroll
            for (int i = 0; i < 2; ++i) {
                int idx = tid + i * 256;
                int kk = idx >> 5, cq = idx & 31;
                *(float4*)&Ws[kk][cq * 4] =
                    *(const float4*)(W + (size_t)(k0 + kk) * 128 + cq * 4);
            }
            __syncthreads();
#pragma unroll
            for (int k = 0; k < BK; ++k) {
                float a[8], b[8];
#pragma unroll
                for (int i = 0; i < 8; i += 4)
                    *(float4*)&a[i] = *(const float4*)&As[k][ty * 8 + i];
#pragma unroll
                for (int j = 0; j < 8; j += 4)
                    *(float4*)&b[j] = *(const float4*)&Ws[k][tx * 8 + j];
#pragma unroll
                for (int i = 0; i < 8; ++i)
#pragma unroll
                    for (int j = 0; j < 8; ++j)
                        acc[i][j] = fmaf(a[i], b[j], acc[i][j]);
            }
            __syncthreads();
        }
    }
#pragma unroll
    for (int i = 0; i < 8; ++i) {
        int r = row0 + ty * 8 + i;
        if (r >= M) break;
#pragma unroll
        for (int j = 0; j < 8; ++j)
            out[(size_t)r * 128 + tx * 8 + j] = acc[i][j] + __ldg(bias + tx * 8 + j);
    }
}

// ---------------- pooling + MLP --------------------------------------------
__global__ void pool_init_kernel(unsigned* __restrict__ pe) {
    int i = blockIdx.x * blockDim.x + threadIdx.x;
    if (i < GG * HH) pe[i] = 0x007FFFFFu;
}

__global__ void pool_max_kernel(const float* __restrict__ xf,
                                const int* __restrict__ batch,
                                unsigned* __restrict__ pe, int n) {
    const int R = 256;
    int base = blockIdx.x * R;
    if (base >= n) return;
    int end = min(base + R, n);
    int c = threadIdx.x;
    int cur = __ldg(batch + base);
    float m = -INFINITY;
    for (int r = base; r < end; ++r) {
        int g = __ldg(batch + r);
        if (g != cur) {
            atomicMax(&pe[cur * HH + c], enc_f(m));
            cur = g; m = -INFINITY;
        }
        m = fmaxf(m, xf[(size_t)r * HH + c]);
    }
    atomicMax(&pe[cur * HH + c], enc_f(m));
}

__global__ void pool_decode_kernel(const unsigned* __restrict__ pe,
                                   float* __restrict__ p) {
    int i = blockIdx.x * blockDim.x + threadIdx.x;
    if (i < GG * HH) p[i] = dec_f(pe[i]);
}

__global__ void mlp1_kernel(const float* __restrict__ pooled,
                            const float* __restrict__ Wc1,
                            const float* __restrict__ bc1,
                            float* __restrict__ h1) {
    int t = blockIdx.x * blockDim.x + threadIdx.x;
    if (t >= GG * 64) return;
    int g = t >> 6, c = t & 63;
    float acc = bc1[c];
    for (int k = 0; k < HH; ++k)
        acc = fmaf(pooled[g * HH + k], Wc1[k * 64 + c], acc);
    h1[t] = fmaxf(acc, 0.f);
}

__global__ void mlp2_kernel(const float* __restrict__ h1,
                            const float* __restrict__ Wc2,
                            const float* __restrict__ bc2,
                            float* __restrict__ h2) {
    int t = blockIdx.x * blockDim.x + threadIdx.x;
    if (t >= GG * HH) return;
    int g = t >> 7, c = t & 127;
    float acc = bc2[c];
    for (int k = 0; k < 64; ++k)
        acc = fmaf(h1[g * 64 + k], Wc2[k * HH + c], acc);
    h2[t] = fmaxf(acc, 0.f);
}

__global__ void mlp3_kernel(const float* __restrict__ h2,
                            const float* __restrict__ Wc3,
                            const float* __restrict__ bc3,
                            float* __restrict__ out) {
    int t = blockIdx.x * blockDim.x + threadIdx.x;
    if (t >= GG * 10) return;
    int g = t / 10, c = t % 10;
    float acc = bc3[c];
    for (int k = 0; k < HH; ++k)
        acc = fmaf(h2[g * HH + k], Wc3[k * 10 + c], acc);
    out[t] = acc;
}

// ---------------- host orchestration ---------------------------------------
static void build_csr(const int* src, const int* dst, int E, int n,
                      int* cnt, int* off, int* cur, int* csr, int* bsum) {
    int nb = (n + SCAN_BLK - 1) / SCAN_BLK;
    cudaMemsetAsync(cnt, 0, (size_t)n * sizeof(int), 0);
    hist_kernel<<<(E + 255) / 256, 256>>>(dst, cnt, E);
    scanA_kernel<<<nb, SCAN_BLK>>>(cnt, off, bsum, n);
    scanB_kernel<<<1, 256>>>(bsum, nb);
    scanC_kernel<<<nb, SCAN_BLK>>>(off, cur, bsum, n, E);
    fill_kernel<<<(E + 255) / 256, 256>>>(src, dst, cur, csr, E);
}

extern "C" void kernel_launch(void* const* d_in, const int* in_sizes, int n_in,
                              void* d_out, int out_size) {
    const int*   host_ids  = (const int*)  d_in[0];
    const float* flow_x    = (const float*)d_in[1];
    const int*   h2f_src   = (const int*)  d_in[2];
    const int*   h2f_dst   = (const int*)  d_in[3];
    const int*   f2h_src   = (const int*)  d_in[4];
    const int*   f2h_dst   = (const int*)  d_in[5];
    const int*   rel_src   = (const int*)  d_in[6];
    const int*   rel_dst   = (const int*)  d_in[7];
    const int*   flow_batch= (const int*)  d_in[8];
    const float* host_embed= (const float*)d_in[9];
    const float* Wr0_h2f   = (const float*)d_in[10];
    const float* br0_h2f   = (const float*)d_in[11];
    const float* Wo0_h2f   = (const float*)d_in[12];
    const float* Wr0_f2h   = (const float*)d_in[13];
    const float* br0_f2h   = (const float*)d_in[14];
    const float* Wo0_f2h   = (const float*)d_in[15];
    const float* Wr0_rel   = (const float*)d_in[16];
    const float* br0_rel   = (const float*)d_in[17];
    const float* Wo0_rel   = (const float*)d_in[18];
    const float* Wr        = (const float*)d_in[19];  // [2,3,128,128]
    const float* br        = (const float*)d_in[20];  // [2,3,128]
    const float* Wo        = (const float*)d_in[21];  // [2,3,128,128]
    const float* Wc1       = (const float*)d_in[22];
    const float* bc1       = (const float*)d_in[23];
    const float* Wc2       = (const float*)d_in[24];
    const float* bc2       = (const float*)d_in[25];
    const float* Wc3       = (const float*)d_in[26];
    const float* bc3       = (const float*)d_in[27];
    float* out = (float*)d_out;

    float *xfA, *xfB, *trel, *th, *xhA, *xhB, *ah;
    float *WF, *Wf2hPad, *biasF, *zeroBias;
    unsigned* poolEnc; float *pooled, *h1, *h2;
    int *csr_rel, *csr_h2f, *csr_f2h;
    int *off_rel, *off_h2f, *off_f2h;
    int *cur_rel, *cur_h2f, *cur_f2h;
    int *cnt_rel, *cnt_h2f, *cnt_f2h, *bsum;
    cudaGetSymbolAddress((void**)&xfA, g_xflowA);
    cudaGetSymbolAddress((void**)&xfB, g_xflowB);
    cudaGetSymbolAddress((void**)&trel, g_trel);
    cudaGetSymbolAddress((void**)&th,  g_th);
    cudaGetSymbolAddress((void**)&xhA, g_xhostA);
    cudaGetSymbolAddress((void**)&xhB, g_xhostB);
    cudaGetSymbolAddress((void**)&ah,  g_aggh);
    cudaGetSymbolAddress((void**)&WF,  g_WF);
    cudaGetSymbolAddress((void**)&Wf2hPad, g_Wf2hPad);
    cudaGetSymbolAddress((void**)&biasF,   g_biasF);
    cudaGetSymbolAddress((void**)&zeroBias, g_zeroBias);
    cudaGetSymbolAddress((void**)&poolEnc, g_poolEnc);
    cudaGetSymbolAddress((void**)&pooled,  g_pooled);
    cudaGetSymbolAddress((void**)&h1, g_h1);
    cudaGetSymbolAddress((void**)&h2, g_h2);
    cudaGetSymbolAddress((void**)&csr_rel, g_csr_rel);
    cudaGetSymbolAddress((void**)&csr_h2f, g_csr_h2f);
    cudaGetSymbolAddress((void**)&csr_f2h, g_csr_f2h);
    cudaGetSymbolAddress((void**)&off_rel, g_off_rel);
    cudaGetSymbolAddress((void**)&off_h2f, g_off_h2f);
    cudaGetSymbolAddress((void**)&off_f2h, g_off_f2h);
    cudaGetSymbolAddress((void**)&cur_rel, g_cur_rel);
    cudaGetSymbolAddress((void**)&cur_h2f, g_cur_h2f);
    cudaGetSymbolAddress((void**)&cur_f2h, g_cur_f2h);
    cudaGetSymbolAddress((void**)&cnt_rel, g_cnt_rel);
    cudaGetSymbolAddress((void**)&cnt_h2f, g_cnt_h2f);
    cudaGetSymbolAddress((void**)&cnt_f2h, g_cnt_f2h);
    cudaGetSymbolAddress((void**)&bsum, g_bsum);

    // CSR build (once per launch; reused for all 3 layers)
    build_csr(rel_src, rel_dst, E_REL, N_FLOW, cnt_rel, off_rel, cur_rel, csr_rel, bsum + 0 * 256);
    build_csr(h2f_src, h2f_dst, E_HF,  N_FLOW, cnt_h2f, off_h2f, cur_h2f, csr_h2f, bsum + 1 * 256);
    build_csr(f2h_src, f2h_dst, E_HF,  N_HOST, cnt_f2h, off_f2h, cur_f2h, csr_f2h, bsum + 2 * 256);

    prep_weights_kernel<<<HH, 256>>>(Wo0_h2f, Wo0_rel, Wr0_rel, Wr0_f2h,
                                     Wo, Wr, br0_h2f, br0_rel, br);
    embed_kernel<<<(N_HOST * HH + 255) / 256, 256>>>(host_ids, host_embed, xhA);
    pad_flow_kernel<<<(N_FLOW * HH + 255) / 256, 256>>>(flow_x, xfA);

    int flowBlocks = (N_FLOW + 127) / 128;
    int hostBlocks = (N_HOST + 127) / 128;

    float* fa = xfA; float* fb = xfB;
    float* ha = xhA; float* hb = xhB;

    for (int layer = 0; layer < 3; ++layer) {
        int relu_in = (layer > 0) ? 1 : 0;
        const float* WFl = WF + (size_t)layer * HH * 2 * HH;
        const float* bFl = biasF + (size_t)layer * HH;
        const float *WrH2F, *WrF2H, *WoF2H, *bH;
        if (layer == 0) {
            WrH2F = Wr0_h2f; WrF2H = Wf2hPad; WoF2H = Wo0_f2h; bH = br0_f2h;
        } else {
            int l = layer - 1;
            WrH2F = Wr + ((size_t)l * 3 + 0) * HH * HH;
            WrF2H = Wr + ((size_t)l * 3 + 1) * HH * HH;
            WoF2H = Wo + ((size_t)l * 3 + 1) * HH * HH;
            bH    = br + (l * 3 + 1) * HH;
        }

        // fb = (relu)fa @ WoComb + bias ; trel = (relu)fa @ Wr_rel  (tf32 TC)
        gemm_dual_tc_kernel<<<flowBlocks, 512>>>(fa, WFl, bFl, fb, trel, N_FLOW, relu_in);
        // th = (relu)ha @ Wr_h2f  (no bias)
        gemm2_kernel<<<hostBlocks, 256>>>(ha, WrH2F, nullptr, nullptr,
                                          zeroBias, th, N_HOST, 1, relu_in);

        // fused CSR gather: fb += sum_rel trel[src] + sum_h2f th[src]
        gather_flow_kernel<<<(N_FLOW * 32 + 255) / 256, 256>>>(
            trel, th, off_rel, csr_rel, off_h2f, csr_h2f, fb);

        // host aggregation via gather (replaces memset+scatter)
        gather_host_kernel<<<(N_HOST * 32 + 255) / 256, 256>>>(
            fa, off_f2h, csr_f2h, ah, relu_in);
        // hb = ah @ Wr_f2h + (relu)ha @ Wo_f2h + bias
        gemm2_kernel<<<hostBlocks, 256>>>(ah, WrF2H, ha, WoF2H, bH, hb,
                                          N_HOST, 2, relu_in << 1);

        float* t;
        t = fa; fa = fb; fb = t;
        t = ha; ha = hb; hb = t;
    }

    pool_init_kernel<<<(GG * HH + 255) / 256, 256>>>(poolEnc);
    pool_max_kernel<<<(N_FLOW + 255) / 256, HH>>>(fa, flow_batch, poolEnc, N_FLOW);
    pool_decode_kernel<<<(GG * HH + 255) / 256, 256>>>(poolEnc, pooled);

    mlp1_kernel<<<(GG * 64 + 255) / 256, 256>>>(pooled, Wc1, bc1, h1);
    mlp2_kernel<<<(GG * HH + 255) / 256, 256>>>(h1, Wc2, bc2, h2);
    mlp3_kernel<<<(GG * 10 + 255) / 256, 256>>>(h2, Wc3, bc3, out);
}

// round 5
// speedup vs baseline: 2.8030x; 1.1995x over previous
#include <cuda_runtime.h>
#include <math.h>
#include <stdint.h>

#define N_HOST 20000
#define N_FLOW 200000
#define E_HF   400000
#define E_REL  800000
#define GG     64
#define HH     128
#define FI     97
#define SCAN_BLK 1024

// ---------------- scratch (device globals; no allocation allowed) ----------
__device__ float g_xflowA[(size_t)N_FLOW * HH];   // ping
__device__ float g_xflowB[(size_t)N_FLOW * HH];   // pong
__device__ float g_trel  [(size_t)N_FLOW * HH];   // transformed flow (rel)
__device__ float g_th    [(size_t)N_HOST * HH];   // transformed host (h2f)
__device__ float g_xhostA[(size_t)N_HOST * HH];
__device__ float g_xhostB[(size_t)N_HOST * HH];
__device__ float g_aggh  [(size_t)N_HOST * HH];   // f2h aggregation into hosts

__device__ float g_WF[3][HH * 2 * HH];  // per layer: [128][256] = [WoComb | Wr_rel]
__device__ float g_Wf2hPad[HH * HH];    // pad(Wr0_f2h) 97->128 rows
__device__ float g_biasF[3][HH];        // br_h2f + br_rel per layer
__device__ float g_zeroBias[HH];        // zero-initialized device global

// CSR scratch (built once per launch, reused across layers)
__device__ int g_csr_rel[E_REL];
__device__ int g_csr_h2f[E_HF];
__device__ int g_csr_f2h[E_HF];
__device__ int g_off_rel[N_FLOW + 1];
__device__ int g_off_h2f[N_FLOW + 1];
__device__ int g_off_f2h[N_HOST + 1];
__device__ int g_cur_rel[N_FLOW];
__device__ int g_cur_h2f[N_FLOW];
__device__ int g_cur_f2h[N_HOST];
__device__ int g_cnt_rel[N_FLOW];
__device__ int g_cnt_h2f[N_FLOW];
__device__ int g_cnt_f2h[N_HOST];
__device__ int g_bsum[3][256];

__device__ unsigned g_poolEnc[GG * HH];
__device__ float    g_pooled [GG * HH];
__device__ float    g_h1[GG * 64];
__device__ float    g_h2[GG * HH];

// ---------------- small helpers -------------------------------------------
__device__ __forceinline__ unsigned enc_f(float f) {
    unsigned u = __float_as_uint(f);
    return (u & 0x80000000u) ? ~u : (u | 0x80000000u);
}
__device__ __forceinline__ float dec_f(unsigned e) {
    return (e & 0x80000000u) ? __uint_as_float(e ^ 0x80000000u)
                             : __uint_as_float(~e);
}
__device__ __forceinline__ uint32_t f2tf32(float f) {
    uint32_t r;
    asm("cvt.rna.tf32.f32 %0, %1;" : "=r"(r) : "f"(f));
    return r;
}
__device__ __forceinline__ void mma_tf32(float4& d, const uint32_t* a,
                                         const uint32_t* b) {
    asm volatile(
        "mma.sync.aligned.m16n8k8.row.col.f32.tf32.tf32.f32 "
        "{%0,%1,%2,%3}, {%4,%5,%6,%7}, {%8,%9}, {%0,%1,%2,%3};"
        : "+f"(d.x), "+f"(d.y), "+f"(d.z), "+f"(d.w)
        : "r"(a[0]), "r"(a[1]), "r"(a[2]), "r"(a[3]), "r"(b[0]), "r"(b[1]));
}

// ---------------- CSR construction -----------------------------------------
__global__ void hist_kernel(const int* __restrict__ dst, int* __restrict__ cnt,
                            int E) {
    int i = blockIdx.x * blockDim.x + threadIdx.x;
    if (i < E) atomicAdd(&cnt[__ldg(dst + i)], 1);
}

__global__ void scanA_kernel(const int* __restrict__ cnt, int* __restrict__ off,
                             int* __restrict__ bsum, int n) {
    __shared__ int sh[SCAN_BLK];
    int tx = threadIdx.x;
    int i = blockIdx.x * SCAN_BLK + tx;
    int v = (i < n) ? cnt[i] : 0;
    sh[tx] = v;
    __syncthreads();
    for (int d = 1; d < SCAN_BLK; d <<= 1) {
        int t = (tx >= d) ? sh[tx - d] : 0;
        __syncthreads();
        sh[tx] += t;
        __syncthreads();
    }
    if (i < n) off[i] = sh[tx] - v;
    if (tx == SCAN_BLK - 1) bsum[blockIdx.x] = sh[tx];
}

__global__ void scanB_kernel(int* __restrict__ bsum, int nb) {
    __shared__ int sh[256];
    int tx = threadIdx.x;
    int v = (tx < nb) ? bsum[tx] : 0;
    sh[tx] = v;
    __syncthreads();
    for (int d = 1; d < 256; d <<= 1) {
        int t = (tx >= d) ? sh[tx - d] : 0;
        __syncthreads();
        sh[tx] += t;
        __syncthreads();
    }
    if (tx < nb) bsum[tx] = sh[tx] - v;
}

__global__ void scanC_kernel(int* __restrict__ off, int* __restrict__ cur,
                             const int* __restrict__ bsum, int n, int E) {
    int i = blockIdx.x * SCAN_BLK + threadIdx.x;
    if (i < n) {
        int o = off[i] + bsum[blockIdx.x];
        off[i] = o;
        cur[i] = o;
    }
    if (i == 0) off[n] = E;
}

__global__ void fill_kernel(const int* __restrict__ src, const int* __restrict__ dst,
                            int* __restrict__ cur, int* __restrict__ csr, int E) {
    int i = blockIdx.x * blockDim.x + threadIdx.x;
    if (i < E) {
        int d = __ldg(dst + i);
        int p = atomicAdd(&cur[d], 1);
        csr[p] = __ldg(src + i);
    }
}

// ---------------- gathers ---------------------------------------------------
__global__ void gather_flow_kernel(const float* __restrict__ trel,
                                   const float* __restrict__ th,
                                   const int* __restrict__ off_rel,
                                   const int* __restrict__ csr_rel,
                                   const int* __restrict__ off_h2f,
                                   const int* __restrict__ csr_h2f,
                                   float* __restrict__ fb) {
    int w = (blockIdx.x * blockDim.x + threadIdx.x) >> 5;
    int lane = threadIdx.x & 31;
    if (w >= N_FLOW) return;
    float4* fp = (float4*)(fb + (size_t)w * HH);
    float4 acc = fp[lane];
    int b = __ldg(off_rel + w), e = __ldg(off_rel + w + 1);
    for (int i = b; i < e; ++i) {
        int s = __ldg(csr_rel + i);
        float4 v = ((const float4*)(trel + (size_t)s * HH))[lane];
        acc.x += v.x; acc.y += v.y; acc.z += v.z; acc.w += v.w;
    }
    b = __ldg(off_h2f + w); e = __ldg(off_h2f + w + 1);
    for (int i = b; i < e; ++i) {
        int s = __ldg(csr_h2f + i);
        float4 v = ((const float4*)(th + (size_t)s * HH))[lane];
        acc.x += v.x; acc.y += v.y; acc.z += v.z; acc.w += v.w;
    }
    fp[lane] = acc;
}

__global__ void gather_host_kernel(const float* __restrict__ fa,
                                   const int* __restrict__ off,
                                   const int* __restrict__ csr,
                                   float* __restrict__ ah, int relu_in) {
    int w = (blockIdx.x * blockDim.x + threadIdx.x) >> 5;
    int lane = threadIdx.x & 31;
    if (w >= N_HOST) return;
    float4 acc = make_float4(0.f, 0.f, 0.f, 0.f);
    int b = __ldg(off + w), e = __ldg(off + w + 1);
    for (int i = b; i < e; ++i) {
        int s = __ldg(csr + i);
        float4 v = ((const float4*)(fa + (size_t)s * HH))[lane];
        if (relu_in) {
            v.x = fmaxf(v.x, 0.f); v.y = fmaxf(v.y, 0.f);
            v.z = fmaxf(v.z, 0.f); v.w = fmaxf(v.w, 0.f);
        }
        acc.x += v.x; acc.y += v.y; acc.z += v.z; acc.w += v.w;
    }
    ((float4*)(ah + (size_t)w * HH))[lane] = acc;
}

// ---------------- prep ------------------------------------------------------
__global__ void embed_kernel(const int* __restrict__ ids,
                             const float* __restrict__ table,
                             float* __restrict__ xh) {
    int i = blockIdx.x * blockDim.x + threadIdx.x;
    if (i >= N_HOST * HH) return;
    int row = i >> 7, c = i & 127;
    xh[i] = table[(size_t)__ldg(ids + row) * HH + c];
}

__global__ void pad_flow_kernel(const float* __restrict__ fx,
                                float* __restrict__ xf) {
    int i = blockIdx.x * blockDim.x + threadIdx.x;
    if (i >= N_FLOW * HH) return;
    int row = i >> 7, c = i & 127;
    xf[i] = (c < FI) ? fx[(size_t)row * FI + c] : 0.f;
}

__global__ void prep_weights_kernel(const float* __restrict__ Wo0_h2f,
                                    const float* __restrict__ Wo0_rel,
                                    const float* __restrict__ Wr0_rel,
                                    const float* __restrict__ Wr0_f2h,
                                    const float* __restrict__ Wo,
                                    const float* __restrict__ Wr,
                                    const float* __restrict__ br0_h2f,
                                    const float* __restrict__ br0_rel,
                                    const float* __restrict__ br) {
    int k = blockIdx.x;
    int c = threadIdx.x;
    int idx = k * 256 + c;
    if (c < HH) {
        g_WF[0][idx] = (k < FI) ? (Wo0_h2f[k * HH + c] + Wo0_rel[k * HH + c]) : 0.f;
        g_Wf2hPad[k * HH + c] = (k < FI) ? Wr0_f2h[k * HH + c] : 0.f;
    } else {
        int cc = c - HH;
        g_WF[0][idx] = (k < FI) ? Wr0_rel[k * HH + cc] : 0.f;
    }
    for (int l = 0; l < 2; ++l) {
        float v;
        if (c < HH)
            v = Wo[((size_t)l * 3 + 0) * HH * HH + k * HH + c]
              + Wo[((size_t)l * 3 + 2) * HH * HH + k * HH + c];
        else
            v = Wr[((size_t)l * 3 + 2) * HH * HH + k * HH + (c - HH)];
        g_WF[l + 1][idx] = v;
    }
    if (k == 0 && c < HH) {
        g_biasF[0][c] = br0_h2f[c] + br0_rel[c];
        for (int l = 0; l < 2; ++l)
            g_biasF[l + 1][c] = br[(l * 3 + 0) * HH + c] + br[(l * 3 + 2) * HH + c];
        g_zeroBias[c] = 0.f;
    }
}

// ---------------- tf32 tensor-core GEMM (flow path) -------------------------
__global__ __launch_bounds__(512, 1)
void gemm_dual_tc_kernel(const float* __restrict__ A, const float* __restrict__ W,
                         const float* __restrict__ bias,
                         float* __restrict__ out_main, float* __restrict__ out_aux,
                         int M, int relu_in) {
    const int BK = 16;
    __shared__ uint32_t As[2][BK][136];
    __shared__ uint32_t Ws[2][BK][264];

    int tid  = threadIdx.x;
    int warp = tid >> 5, lane = tid & 31;
    int wm = warp >> 2, wn = warp & 3;
    int tg = lane & 3, gp = lane >> 2;
    int row0 = blockIdx.x * 128;

    float4 acc[2][8];
#pragma unroll
    for (int i = 0; i < 2; ++i)
#pragma unroll
        for (int j = 0; j < 8; ++j) acc[i][j] = make_float4(0.f, 0.f, 0.f, 0.f);

    int a_r = tid >> 2, a_kq = tid & 3;
    int a_grow = row0 + a_r;
    float4 aREG;
    float4 wREG[2];

    {
        aREG = make_float4(0.f, 0.f, 0.f, 0.f);
        if (a_grow < M)
            aREG = *(const float4*)(A + (size_t)a_grow * HH + a_kq * 4);
#pragma unroll
        for (int i = 0; i < 2; ++i) {
            int idx = tid + i * 512;
            int kk = idx >> 6, cq = idx & 63;
            wREG[i] = *(const float4*)(W + (size_t)kk * 256 + cq * 4);
        }
        if (relu_in) {
            aREG.x = fmaxf(aREG.x, 0.f); aREG.y = fmaxf(aREG.y, 0.f);
            aREG.z = fmaxf(aREG.z, 0.f); aREG.w = fmaxf(aREG.w, 0.f);
        }
        As[0][a_kq * 4 + 0][a_r] = f2tf32(aREG.x);
        As[0][a_kq * 4 + 1][a_r] = f2tf32(aREG.y);
        As[0][a_kq * 4 + 2][a_r] = f2tf32(aREG.z);
        As[0][a_kq * 4 + 3][a_r] = f2tf32(aREG.w);
#pragma unroll
        for (int i = 0; i < 2; ++i) {
            int idx = tid + i * 512;
            int kk = idx >> 6, cq = idx & 63;
            uint32_t* p = &Ws[0][kk][cq * 4];
            p[0] = f2tf32(wREG[i].x); p[1] = f2tf32(wREG[i].y);
            p[2] = f2tf32(wREG[i].z); p[3] = f2tf32(wREG[i].w);
        }
        __syncthreads();
    }

    const int NITER = HH / BK;
    for (int iter = 0; iter < NITER; ++iter) {
        int cur = iter & 1;
        if (iter + 1 < NITER) {
            int k0 = (iter + 1) * BK;
            aREG = make_float4(0.f, 0.f, 0.f, 0.f);
            if (a_grow < M)
                aREG = *(const float4*)(A + (size_t)a_grow * HH + k0 + a_kq * 4);
#pragma unroll
            for (int i = 0; i < 2; ++i) {
                int idx = tid + i * 512;
                int kk = idx >> 6, cq = idx & 63;
                wREG[i] = *(const float4*)(W + (size_t)(k0 + kk) * 256 + cq * 4);
            }
        }
#pragma unroll
        for (int ks = 0; ks < BK; ks += 8) {
            uint32_t af[2][4];
            uint32_t bf[8][2];
#pragma unroll
            for (int mi = 0; mi < 2; ++mi) {
                int ar = wm * 32 + mi * 16 + gp;
                af[mi][0] = As[cur][ks + tg][ar];
                af[mi][1] = As[cur][ks + tg][ar + 8];
                af[mi][2] = As[cur][ks + tg + 4][ar];
                af[mi][3] = As[cur][ks + tg + 4][ar + 8];
            }
#pragma unroll
            for (int ni = 0; ni < 8; ++ni) {
                int nc = wn * 64 + ni * 8 + gp;
                bf[ni][0] = Ws[cur][ks + tg][nc];
                bf[ni][1] = Ws[cur][ks + tg + 4][nc];
            }
#pragma unroll
            for (int mi = 0; mi < 2; ++mi)
#pragma unroll
                for (int ni = 0; ni < 8; ++ni)
                    mma_tf32(acc[mi][ni], af[mi], bf[ni]);
        }
        if (iter + 1 < NITER) {
            int nxt = 1 - cur;
            if (relu_in) {
                aREG.x = fmaxf(aREG.x, 0.f); aREG.y = fmaxf(aREG.y, 0.f);
                aREG.z = fmaxf(aREG.z, 0.f); aREG.w = fmaxf(aREG.w, 0.f);
            }
            As[nxt][a_kq * 4 + 0][a_r] = f2tf32(aREG.x);
            As[nxt][a_kq * 4 + 1][a_r] = f2tf32(aREG.y);
            As[nxt][a_kq * 4 + 2][a_r] = f2tf32(aREG.z);
            As[nxt][a_kq * 4 + 3][a_r] = f2tf32(aREG.w);
#pragma unroll
            for (int i = 0; i < 2; ++i) {
                int idx = tid + i * 512;
                int kk = idx >> 6, cq = idx & 63;
                uint32_t* p = &Ws[nxt][kk][cq * 4];
                p[0] = f2tf32(wREG[i].x); p[1] = f2tf32(wREG[i].y);
                p[2] = f2tf32(wREG[i].z); p[3] = f2tf32(wREG[i].w);
            }
        }
        __syncthreads();
    }

#pragma unroll
    for (int ni = 0; ni < 8; ++ni) {
        int col = wn * 64 + ni * 8 + tg * 2;
        bool main_half = (col < HH);
        float b0 = 0.f, b1 = 0.f;
        if (main_half) { b0 = __ldg(bias + col); b1 = __ldg(bias + col + 1); }
        float* outp = main_half ? out_main : out_aux;
        int oc = main_half ? col : (col - HH);
#pragma unroll
        for (int mi = 0; mi < 2; ++mi) {
            int r0 = row0 + wm * 32 + mi * 16 + gp;
            int r1 = r0 + 8;
            float4 d = acc[mi][ni];
            if (r0 < M) {
                float2 v = make_float2(d.x + b0, d.y + b1);
                *(float2*)(outp + (size_t)r0 * HH + oc) = v;
            }
            if (r1 < M) {
                float2 v = make_float2(d.z + b0, d.w + b1);
                *(float2*)(outp + (size_t)r1 * HH + oc) = v;
            }
        }
    }
}

// ---------------- fp32 GEMM (host path, small) ------------------------------
__global__ __launch_bounds__(256)
void gemm2_kernel(const float* __restrict__ A0, const float* __restrict__ W0,
                  const float* __restrict__ A1, const float* __restrict__ W1,
                  const float* __restrict__ bias, float* __restrict__ out,
                  int M, int nsrc, int relu_mask) {
    const int BM = 128, BK = 16;
    __shared__ float As[BK][BM + 4];
    __shared__ float Ws[BK][128];
    int tid = threadIdx.x;
    int tx = tid & 15, ty = tid >> 4;
    int row0 = blockIdx.x * BM;
    float acc[8][8];
#pragma unroll
    for (int i = 0; i < 8; ++i)
#pragma unroll
        for (int j = 0; j < 8; ++j) acc[i][j] = 0.f;

    const float* Aarr[2] = {A0, A1};
    const float* Warr[2] = {W0, W1};

    for (int s = 0; s < nsrc; ++s) {
        const float* A = Aarr[s];
        const float* W = Warr[s];
        int rl = (relu_mask >> s) & 1;
        for (int k0 = 0; k0 < 128; k0 += BK) {
#pragma unroll
            for (int i = 0; i < 2; ++i) {
                int idx = tid + i * 256;
                int r = idx >> 2, kq = idx & 3;
                int grow = row0 + r;
                float4 v = make_float4(0.f, 0.f, 0.f, 0.f);
                if (grow < M)
                    v = *(const float4*)(A + (size_t)grow * 128 + k0 + kq * 4);
                if (rl) {
                    v.x = fmaxf(v.x, 0.f); v.y = fmaxf(v.y, 0.f);
                    v.z = fmaxf(v.z, 0.f); v.w = fmaxf(v.w, 0.f);
                }
                As[kq * 4 + 0][r] = v.x;
                As[kq * 4 + 1][r] = v.y;
                As[kq * 4 + 2][r] = v.z;
                As[kq * 4 + 3][r] = v.w;
            }
#pragma unroll
            for (int i = 0; i < 2; ++i) {
                int idx = tid + i * 256;
                int kk = idx >> 5, cq = idx & 31;
                *(float4*)&Ws[kk][cq * 4] =
                    *(const float4*)(W + (size_t)(k0 + kk) * 128 + cq * 4);
            }
            __syncthreads();
#pragma unroll
            for (int k = 0; k < BK; ++k) {
                float a[8], b[8];
#pragma unroll
                for (int i = 0; i < 8; i += 4)
                    *(float4*)&a[i] = *(const float4*)&As[k][ty * 8 + i];
#pragma unroll
                for (int j = 0; j < 8; j += 4)
                    *(float4*)&b[j] = *(const float4*)&Ws[k][tx * 8 + j];
#pragma unroll
                for (int i = 0; i < 8; ++i)
#pragma unroll
                    for (int j = 0; j < 8; ++j)
                        acc[i][j] = fmaf(a[i], b[j], acc[i][j]);
            }
            __syncthreads();
        }
    }
#pragma unroll
    for (int i = 0; i < 8; ++i) {
        int r = row0 + ty * 8 + i;
        if (r >= M) break;
#pragma unroll
        for (int j = 0; j < 8; ++j)
            out[(size_t)r * 128 + tx * 8 + j] = acc[i][j] + __ldg(bias + tx * 8 + j);
    }
}

// ---------------- pooling + MLP --------------------------------------------
__global__ void pool_init_kernel(unsigned* __restrict__ pe) {
    int i = blockIdx.x * blockDim.x + threadIdx.x;
    if (i < GG * HH) pe[i] = 0x007FFFFFu;
}

__global__ void pool_max_kernel(const float* __restrict__ xf,
                                const int* __restrict__ batch,
                                unsigned* __restrict__ pe, int n) {
    const int R = 256;
    int base = blockIdx.x * R;
    if (base >= n) return;
    int end = min(base + R, n);
    int c = threadIdx.x;
    int cur = __ldg(batch + base);
    float m = -INFINITY;
    for (int r = base; r < end; ++r) {
        int g = __ldg(batch + r);
        if (g != cur) {
            atomicMax(&pe[cur * HH + c], enc_f(m));
            cur = g; m = -INFINITY;
        }
        m = fmaxf(m, xf[(size_t)r * HH + c]);
    }
    atomicMax(&pe[cur * HH + c], enc_f(m));
}

__global__ void pool_decode_kernel(const unsigned* __restrict__ pe,
                                   float* __restrict__ p) {
    int i = blockIdx.x * blockDim.x + threadIdx.x;
    if (i < GG * HH) p[i] = dec_f(pe[i]);
}

__global__ void mlp1_kernel(const float* __restrict__ pooled,
                            const float* __restrict__ Wc1,
                            const float* __restrict__ bc1,
                            float* __restrict__ h1) {
    int t = blockIdx.x * blockDim.x + threadIdx.x;
    if (t >= GG * 64) return;
    int g = t >> 6, c = t & 63;
    float acc = bc1[c];
    for (int k = 0; k < HH; ++k)
        acc = fmaf(pooled[g * HH + k], Wc1[k * 64 + c], acc);
    h1[t] = fmaxf(acc, 0.f);
}

__global__ void mlp2_kernel(const float* __restrict__ h1,
                            const float* __restrict__ Wc2,
                            const float* __restrict__ bc2,
                            float* __restrict__ h2) {
    int t = blockIdx.x * blockDim.x + threadIdx.x;
    if (t >= GG * HH) return;
    int g = t >> 7, c = t & 127;
    float acc = bc2[c];
    for (int k = 0; k < 64; ++k)
        acc = fmaf(h1[g * 64 + k], Wc2[k * HH + c], acc);
    h2[t] = fmaxf(acc, 0.f);
}

__global__ void mlp3_kernel(const float* __restrict__ h2,
                            const float* __restrict__ Wc3,
                            const float* __restrict__ bc3,
                            float* __restrict__ out) {
    int t = blockIdx.x * blockDim.x + threadIdx.x;
    if (t >= GG * 10) return;
    int g = t / 10, c = t % 10;
    float acc = bc3[c];
    for (int k = 0; k < HH; ++k)
        acc = fmaf(h2[g * HH + k], Wc3[k * 10 + c], acc);
    out[t] = acc;
}

// ---------------- host orchestration ---------------------------------------
static void build_csr(cudaStream_t st, const int* src, const int* dst, int E, int n,
                      int* cnt, int* off, int* cur, int* csr, int* bsum) {
    int nb = (n + SCAN_BLK - 1) / SCAN_BLK;
    cudaMemsetAsync(cnt, 0, (size_t)n * sizeof(int), st);
    hist_kernel<<<(E + 255) / 256, 256, 0, st>>>(dst, cnt, E);
    scanA_kernel<<<nb, SCAN_BLK, 0, st>>>(cnt, off, bsum, n);
    scanB_kernel<<<1, 256, 0, st>>>(bsum, nb);
    scanC_kernel<<<nb, SCAN_BLK, 0, st>>>(off, cur, bsum, n, E);
    fill_kernel<<<(E + 255) / 256, 256, 0, st>>>(src, dst, cur, csr, E);
}

extern "C" void kernel_launch(void* const* d_in, const int* in_sizes, int n_in,
                              void* d_out, int out_size) {
    const int*   host_ids  = (const int*)  d_in[0];
    const float* flow_x    = (const float*)d_in[1];
    const int*   h2f_src   = (const int*)  d_in[2];
    const int*   h2f_dst   = (const int*)  d_in[3];
    const int*   f2h_src   = (const int*)  d_in[4];
    const int*   f2h_dst   = (const int*)  d_in[5];
    const int*   rel_src   = (const int*)  d_in[6];
    const int*   rel_dst   = (const int*)  d_in[7];
    const int*   flow_batch= (const int*)  d_in[8];
    const float* host_embed= (const float*)d_in[9];
    const float* Wr0_h2f   = (const float*)d_in[10];
    const float* br0_h2f   = (const float*)d_in[11];
    const float* Wo0_h2f   = (const float*)d_in[12];
    const float* Wr0_f2h   = (const float*)d_in[13];
    const float* br0_f2h   = (const float*)d_in[14];
    const float* Wo0_f2h   = (const float*)d_in[15];
    const float* Wr0_rel   = (const float*)d_in[16];
    const float* br0_rel   = (const float*)d_in[17];
    const float* Wo0_rel   = (const float*)d_in[18];
    const float* Wr        = (const float*)d_in[19];  // [2,3,128,128]
    const float* br        = (const float*)d_in[20];  // [2,3,128]
    const float* Wo        = (const float*)d_in[21];  // [2,3,128,128]
    const float* Wc1       = (const float*)d_in[22];
    const float* bc1       = (const float*)d_in[23];
    const float* Wc2       = (const float*)d_in[24];
    const float* bc2       = (const float*)d_in[25];
    const float* Wc3       = (const float*)d_in[26];
    const float* bc3       = (const float*)d_in[27];
    float* out = (float*)d_out;

    float *xfA, *xfB, *trel, *th, *xhA, *xhB, *ah;
    float *WF, *Wf2hPad, *biasF, *zeroBias;
    unsigned* poolEnc; float *pooled, *h1, *h2;
    int *csr_rel, *csr_h2f, *csr_f2h;
    int *off_rel, *off_h2f, *off_f2h;
    int *cur_rel, *cur_h2f, *cur_f2h;
    int *cnt_rel, *cnt_h2f, *cnt_f2h, *bsum;
    cudaGetSymbolAddress((void**)&xfA, g_xflowA);
    cudaGetSymbolAddress((void**)&xfB, g_xflowB);
    cudaGetSymbolAddress((void**)&trel, g_trel);
    cudaGetSymbolAddress((void**)&th,  g_th);
    cudaGetSymbolAddress((void**)&xhA, g_xhostA);
    cudaGetSymbolAddress((void**)&xhB, g_xhostB);
    cudaGetSymbolAddress((void**)&ah,  g_aggh);
    cudaGetSymbolAddress((void**)&WF,  g_WF);
    cudaGetSymbolAddress((void**)&Wf2hPad, g_Wf2hPad);
    cudaGetSymbolAddress((void**)&biasF,   g_biasF);
    cudaGetSymbolAddress((void**)&zeroBias, g_zeroBias);
    cudaGetSymbolAddress((void**)&poolEnc, g_poolEnc);
    cudaGetSymbolAddress((void**)&pooled,  g_pooled);
    cudaGetSymbolAddress((void**)&h1, g_h1);
    cudaGetSymbolAddress((void**)&h2, g_h2);
    cudaGetSymbolAddress((void**)&csr_rel, g_csr_rel);
    cudaGetSymbolAddress((void**)&csr_h2f, g_csr_h2f);
    cudaGetSymbolAddress((void**)&csr_f2h, g_csr_f2h);
    cudaGetSymbolAddress((void**)&off_rel, g_off_rel);
    cudaGetSymbolAddress((void**)&off_h2f, g_off_h2f);
    cudaGetSymbolAddress((void**)&off_f2h, g_off_f2h);
    cudaGetSymbolAddress((void**)&cur_rel, g_cur_rel);
    cudaGetSymbolAddress((void**)&cur_h2f, g_cur_h2f);
    cudaGetSymbolAddress((void**)&cur_f2h, g_cur_f2h);
    cudaGetSymbolAddress((void**)&cnt_rel, g_cnt_rel);
    cudaGetSymbolAddress((void**)&cnt_h2f, g_cnt_h2f);
    cudaGetSymbolAddress((void**)&cnt_f2h, g_cnt_f2h);
    cudaGetSymbolAddress((void**)&bsum, g_bsum);

    // lazily-created side stream + events (host-side resources only)
    static cudaStream_t sB = nullptr;
    static cudaEvent_t evFork = nullptr, evPrep = nullptr, evCsrB = nullptr,
                       evTh = nullptr, evFlow = nullptr;
    if (!sB) {
        cudaStreamCreateWithFlags(&sB, cudaStreamNonBlocking);
        cudaEventCreateWithFlags(&evFork, cudaEventDisableTiming);
        cudaEventCreateWithFlags(&evPrep, cudaEventDisableTiming);
        cudaEventCreateWithFlags(&evCsrB, cudaEventDisableTiming);
        cudaEventCreateWithFlags(&evTh,   cudaEventDisableTiming);
        cudaEventCreateWithFlags(&evFlow, cudaEventDisableTiming);
    }
    cudaStream_t s0 = 0;

    // fork side stream
    cudaEventRecord(evFork, s0);
    cudaStreamWaitEvent(sB, evFork, 0);

    // side stream: build h2f + f2h CSR
    build_csr(sB, h2f_src, h2f_dst, E_HF, N_FLOW, cnt_h2f, off_h2f, cur_h2f, csr_h2f, bsum + 1 * 256);
    build_csr(sB, f2h_src, f2h_dst, E_HF, N_HOST, cnt_f2h, off_f2h, cur_f2h, csr_f2h, bsum + 2 * 256);
    cudaEventRecord(evCsrB, sB);

    // main stream: prep + rel CSR
    prep_weights_kernel<<<HH, 256, 0, s0>>>(Wo0_h2f, Wo0_rel, Wr0_rel, Wr0_f2h,
                                            Wo, Wr, br0_h2f, br0_rel, br);
    embed_kernel<<<(N_HOST * HH + 255) / 256, 256, 0, s0>>>(host_ids, host_embed, xhA);
    pad_flow_kernel<<<(N_FLOW * HH + 255) / 256, 256, 0, s0>>>(flow_x, xfA);
    cudaEventRecord(evPrep, s0);
    build_csr(s0, rel_src, rel_dst, E_REL, N_FLOW, cnt_rel, off_rel, cur_rel, csr_rel, bsum + 0 * 256);

    int flowBlocks = (N_FLOW + 127) / 128;
    int hostBlocks = (N_HOST + 127) / 128;

    float* fa = xfA; float* fb = xfB;
    float* ha = xhA; float* hb = xhB;

    for (int layer = 0; layer < 3; ++layer) {
        int relu_in = (layer > 0) ? 1 : 0;
        const float* WFl = WF + (size_t)layer * HH * 2 * HH;
        const float* bFl = biasF + (size_t)layer * HH;
        const float *WrH2F, *WrF2H, *WoF2H, *bH;
        if (layer == 0) {
            WrH2F = Wr0_h2f; WrF2H = Wf2hPad; WoF2H = Wo0_f2h; bH = br0_f2h;
        } else {
            int l = layer - 1;
            WrH2F = Wr + ((size_t)l * 3 + 0) * HH * HH;
            WrF2H = Wr + ((size_t)l * 3 + 1) * HH * HH;
            WoF2H = Wo + ((size_t)l * 3 + 1) * HH * HH;
            bH    = br + (l * 3 + 1) * HH;
        }

        // s0: fb = (relu)fa @ WoComb + bias ; trel = (relu)fa @ Wr_rel
        gemm_dual_tc_kernel<<<flowBlocks, 512, 0, s0>>>(fa, WFl, bFl, fb, trel, N_FLOW, relu_in);

        // sB: host chain — needs fa/ha of this layer
        if (layer == 0) cudaStreamWaitEvent(sB, evPrep, 0);
        else            cudaStreamWaitEvent(sB, evFlow, 0);
        gemm2_kernel<<<hostBlocks, 256, 0, sB>>>(ha, WrH2F, nullptr, nullptr,
                                                 zeroBias, th, N_HOST, 1, relu_in);
        cudaEventRecord(evTh, sB);
        if (layer < 2) {  // last-layer host update is dead code
            gather_host_kernel<<<(N_HOST * 32 + 255) / 256, 256, 0, sB>>>(
                fa, off_f2h, csr_f2h, ah, relu_in);
            gemm2_kernel<<<hostBlocks, 256, 0, sB>>>(ah, WrF2H, ha, WoF2H, bH, hb,
                                                     N_HOST, 2, relu_in << 1);
        }

        // s0: fused CSR gather (needs th; layer0 also needs sB's csr_h2f)
        cudaStreamWaitEvent(s0, evTh, 0);
        if (layer == 0) cudaStreamWaitEvent(s0, evCsrB, 0);
        gather_flow_kernel<<<(N_FLOW * 32 + 255) / 256, 256, 0, s0>>>(
            trel, th, off_rel, csr_rel, off_h2f, csr_h2f, fb);
        cudaEventRecord(evFlow, s0);

        float* t;
        t = fa; fa = fb; fb = t;
        t = ha; ha = hb; hb = t;
    }

    // epilogue on s0 (sB already joined via evTh wait in layer 2)
    pool_init_kernel<<<(GG * HH + 255) / 256, 256, 0, s0>>>(poolEnc);
    pool_max_kernel<<<(N_FLOW + 255) / 256, HH, 0, s0>>>(fa, flow_batch, poolEnc, N_FLOW);
    pool_decode_kernel<<<(GG * HH + 255) / 256, 256, 0, s0>>>(poolEnc, pooled);

    mlp1_kernel<<<(GG * 64 + 255) / 256, 256, 0, s0>>>(pooled, Wc1, bc1, h1);
    mlp2_kernel<<<(GG * HH + 255) / 256, 256, 0, s0>>>(h1, Wc2, bc2, h2);
    mlp3_kernel<<<(GG * 10 + 255) / 256, 256, 0, s0>>>(h2, Wc3, bc3, out);
}

// round 7
// speedup vs baseline: 3.1170x; 1.1120x over previous
#include <cuda_runtime.h>
#include <cuda_fp16.h>
#include <math.h>
#include <stdint.h>

#define N_HOST 20000
#define N_FLOW 200000
#define E_HF   400000
#define E_REL  800000
#define GG     64
#define HH     128
#define FI     97
#define SCAN_BLK 1024

// ---------------- scratch (device globals; no allocation allowed) ----------
__device__ float  g_xflowA[(size_t)N_FLOW * HH];   // ping
__device__ float  g_xflowB[(size_t)N_FLOW * HH];   // pong
__device__ __half g_trel  [(size_t)N_FLOW * HH];   // transformed flow (rel), fp16
__device__ __half g_th    [(size_t)N_HOST * HH];   // transformed host (h2f), fp16
__device__ float  g_xhostA[(size_t)N_HOST * HH];
__device__ float  g_xhostB[(size_t)N_HOST * HH];
__device__ float  g_aggh  [(size_t)N_HOST * HH];   // f2h aggregation into hosts

__device__ float g_WF[3][HH * 2 * HH];  // per layer: [128][256] = [WoComb | Wr_rel]
__device__ float g_Wf2hPad[HH * HH];    // pad(Wr0_f2h) 97->128 rows
__device__ float g_biasF[3][HH];        // br_h2f + br_rel per layer
__device__ float g_zeroBias[HH];        // zero-initialized device global

// CSR scratch (built once per launch, reused across layers)
__device__ int g_csr_rel[E_REL];
__device__ int g_csr_h2f[E_HF];
__device__ int g_csr_f2h[E_HF];
__device__ int g_off_rel[N_FLOW + 1];
__device__ int g_off_h2f[N_FLOW + 1];
__device__ int g_off_f2h[N_HOST + 1];
__device__ int g_cur_rel[N_FLOW];
__device__ int g_cur_h2f[N_FLOW];
__device__ int g_cur_f2h[N_HOST];
__device__ int g_cnt_rel[N_FLOW];
__device__ int g_cnt_h2f[N_FLOW];
__device__ int g_cnt_f2h[N_HOST];
__device__ int g_bsum[3][256];

__device__ unsigned g_poolEnc[GG * HH];
__device__ float    g_pooled [GG * HH];
__device__ float    g_h1[GG * 64];
__device__ float    g_h2[GG * HH];

// ---------------- small helpers -------------------------------------------
__device__ __forceinline__ unsigned enc_f(float f) {
    unsigned u = __float_as_uint(f);
    return (u & 0x80000000u) ? ~u : (u | 0x80000000u);
}
__device__ __forceinline__ float dec_f(unsigned e) {
    return (e & 0x80000000u) ? __uint_as_float(e ^ 0x80000000u)
                             : __uint_as_float(~e);
}
__device__ __forceinline__ uint32_t f2tf32(float f) {
    uint32_t r;
    asm("cvt.rna.tf32.f32 %0, %1;" : "=r"(r) : "f"(f));
    return r;
}
__device__ __forceinline__ void mma_tf32(float4& d, const uint32_t* a,
                                         const uint32_t* b) {
    asm volatile(
        "mma.sync.aligned.m16n8k8.row.col.f32.tf32.tf32.f32 "
        "{%0,%1,%2,%3}, {%4,%5,%6,%7}, {%8,%9}, {%0,%1,%2,%3};"
        : "+f"(d.x), "+f"(d.y), "+f"(d.z), "+f"(d.w)
        : "r"(a[0]), "r"(a[1]), "r"(a[2]), "r"(a[3]), "r"(b[0]), "r"(b[1]));
}

// ---------------- CSR construction -----------------------------------------
__global__ void hist_kernel(const int* __restrict__ dst, int* __restrict__ cnt,
                            int E) {
    int i = blockIdx.x * blockDim.x + threadIdx.x;
    if (i < E) atomicAdd(&cnt[__ldg(dst + i)], 1);
}

__global__ void scanA_kernel(const int* __restrict__ cnt, int* __restrict__ off,
                             int* __restrict__ bsum, int n) {
    __shared__ int sh[SCAN_BLK];
    int tx = threadIdx.x;
    int i = blockIdx.x * SCAN_BLK + tx;
    int v = (i < n) ? cnt[i] : 0;
    sh[tx] = v;
    __syncthreads();
    for (int d = 1; d < SCAN_BLK; d <<= 1) {
        int t = (tx >= d) ? sh[tx - d] : 0;
        __syncthreads();
        sh[tx] += t;
        __syncthreads();
    }
    if (i < n) off[i] = sh[tx] - v;
    if (tx == SCAN_BLK - 1) bsum[blockIdx.x] = sh[tx];
}

__global__ void scanB_kernel(int* __restrict__ bsum, int nb) {
    __shared__ int sh[256];
    int tx = threadIdx.x;
    int v = (tx < nb) ? bsum[tx] : 0;
    sh[tx] = v;
    __syncthreads();
    for (int d = 1; d < 256; d <<= 1) {
        int t = (tx >= d) ? sh[tx - d] : 0;
        __syncthreads();
        sh[tx] += t;
        __syncthreads();
    }
    if (tx < nb) bsum[tx] = sh[tx] - v;
}

__global__ void scanC_kernel(int* __restrict__ off, int* __restrict__ cur,
                             const int* __restrict__ bsum, int n, int E) {
    int i = blockIdx.x * SCAN_BLK + threadIdx.x;
    if (i < n) {
        int o = off[i] + bsum[blockIdx.x];
        off[i] = o;
        cur[i] = o;
    }
    if (i == 0) off[n] = E;
}

__global__ void fill_kernel(const int* __restrict__ src, const int* __restrict__ dst,
                            int* __restrict__ cur, int* __restrict__ csr, int E) {
    int i = blockIdx.x * blockDim.x + threadIdx.x;
    if (i < E) {
        int d = __ldg(dst + i);
        int p = atomicAdd(&cur[d], 1);
        csr[p] = __ldg(src + i);
    }
}

// ---------------- gathers ---------------------------------------------------
// warp per flow node; lane covers 4 cols; fp16 message rows (8B per lane)
__global__ void gather_flow_kernel(const __half* __restrict__ trel,
                                   const __half* __restrict__ th,
                                   const int* __restrict__ off_rel,
                                   const int* __restrict__ csr_rel,
                                   const int* __restrict__ off_h2f,
                                   const int* __restrict__ csr_h2f,
                                   float* __restrict__ fb) {
    int w = (blockIdx.x * blockDim.x + threadIdx.x) >> 5;
    int lane = threadIdx.x & 31;
    if (w >= N_FLOW) return;
    float4* fp = (float4*)(fb + (size_t)w * HH);
    float4 acc = fp[lane];
    int b = __ldg(off_rel + w), e = __ldg(off_rel + w + 1);
    for (int i = b; i < e; ++i) {
        int s = __ldg(csr_rel + i);
        uint2 v = ((const uint2*)(trel + (size_t)s * HH))[lane];
        float2 p0 = __half22float2(*(__half2*)&v.x);
        float2 p1 = __half22float2(*(__half2*)&v.y);
        acc.x += p0.x; acc.y += p0.y; acc.z += p1.x; acc.w += p1.y;
    }
    b = __ldg(off_h2f + w); e = __ldg(off_h2f + w + 1);
    for (int i = b; i < e; ++i) {
        int s = __ldg(csr_h2f + i);
        uint2 v = ((const uint2*)(th + (size_t)s * HH))[lane];
        float2 p0 = __half22float2(*(__half2*)&v.x);
        float2 p1 = __half22float2(*(__half2*)&v.y);
        acc.x += p0.x; acc.y += p0.y; acc.z += p1.x; acc.w += p1.y;
    }
    fp[lane] = acc;
}

__global__ void gather_host_kernel(const float* __restrict__ fa,
                                   const int* __restrict__ off,
                                   const int* __restrict__ csr,
                                   float* __restrict__ ah, int relu_in) {
    int w = (blockIdx.x * blockDim.x + threadIdx.x) >> 5;
    int lane = threadIdx.x & 31;
    if (w >= N_HOST) return;
    float4 acc = make_float4(0.f, 0.f, 0.f, 0.f);
    int b = __ldg(off + w), e = __ldg(off + w + 1);
    for (int i = b; i < e; ++i) {
        int s = __ldg(csr + i);
        float4 v = ((const float4*)(fa + (size_t)s * HH))[lane];
        if (relu_in) {
            v.x = fmaxf(v.x, 0.f); v.y = fmaxf(v.y, 0.f);
            v.z = fmaxf(v.z, 0.f); v.w = fmaxf(v.w, 0.f);
        }
        acc.x += v.x; acc.y += v.y; acc.z += v.z; acc.w += v.w;
    }
    ((float4*)(ah + (size_t)w * HH))[lane] = acc;
}

// ---------------- prep ------------------------------------------------------
__global__ void embed_kernel(const int* __restrict__ ids,
                             const float* __restrict__ table,
                             float* __restrict__ xh) {
    int i = blockIdx.x * blockDim.x + threadIdx.x;
    if (i >= N_HOST * HH) return;
    int row = i >> 7, c = i & 127;
    xh[i] = table[(size_t)__ldg(ids + row) * HH + c];
}

__global__ void pad_flow_kernel(const float* __restrict__ fx,
                                float* __restrict__ xf) {
    int i = blockIdx.x * blockDim.x + threadIdx.x;
    if (i >= N_FLOW * HH) return;
    int row = i >> 7, c = i & 127;
    xf[i] = (c < FI) ? fx[(size_t)row * FI + c] : 0.f;
}

__global__ void prep_weights_kernel(const float* __restrict__ Wo0_h2f,
                                    const float* __restrict__ Wo0_rel,
                                    const float* __restrict__ Wr0_rel,
                                    const float* __restrict__ Wr0_f2h,
                                    const float* __restrict__ Wo,
                                    const float* __restrict__ Wr,
                                    const float* __restrict__ br0_h2f,
                                    const float* __restrict__ br0_rel,
                                    const float* __restrict__ br) {
    int k = blockIdx.x;
    int c = threadIdx.x;
    int idx = k * 256 + c;
    if (c < HH) {
        g_WF[0][idx] = (k < FI) ? (Wo0_h2f[k * HH + c] + Wo0_rel[k * HH + c]) : 0.f;
        g_Wf2hPad[k * HH + c] = (k < FI) ? Wr0_f2h[k * HH + c] : 0.f;
    } else {
        int cc = c - HH;
        g_WF[0][idx] = (k < FI) ? Wr0_rel[k * HH + cc] : 0.f;
    }
    for (int l = 0; l < 2; ++l) {
        float v;
        if (c < HH)
            v = Wo[((size_t)l * 3 + 0) * HH * HH + k * HH + c]
              + Wo[((size_t)l * 3 + 2) * HH * HH + k * HH + c];
        else
            v = Wr[((size_t)l * 3 + 2) * HH * HH + k * HH + (c - HH)];
        g_WF[l + 1][idx] = v;
    }
    if (k == 0 && c < HH) {
        g_biasF[0][c] = br0_h2f[c] + br0_rel[c];
        for (int l = 0; l < 2; ++l)
            g_biasF[l + 1][c] = br[(l * 3 + 0) * HH + c] + br[(l * 3 + 2) * HH + c];
        g_zeroBias[c] = 0.f;
    }
}

// ---------------- tf32 tensor-core GEMM (flow path) -------------------------
// out_main fp32 (+bias); out_aux fp16
__global__ __launch_bounds__(512, 1)
void gemm_dual_tc_kernel(const float* __restrict__ A, const float* __restrict__ W,
                         const float* __restrict__ bias,
                         float* __restrict__ out_main, __half* __restrict__ out_aux,
                         int M, int relu_in) {
    const int BK = 16;
    __shared__ uint32_t As[2][BK][136];
    __shared__ uint32_t Ws[2][BK][264];

    int tid  = threadIdx.x;
    int warp = tid >> 5, lane = tid & 31;
    int wm = warp >> 2, wn = warp & 3;
    int tg = lane & 3, gp = lane >> 2;
    int row0 = blockIdx.x * 128;

    float4 acc[2][8];
#pragma unroll
    for (int i = 0; i < 2; ++i)
#pragma unroll
        for (int j = 0; j < 8; ++j) acc[i][j] = make_float4(0.f, 0.f, 0.f, 0.f);

    int a_r = tid >> 2, a_kq = tid & 3;
    int a_grow = row0 + a_r;
    float4 aREG;
    float4 wREG[2];

    {
        aREG = make_float4(0.f, 0.f, 0.f, 0.f);
        if (a_grow < M)
            aREG = *(const float4*)(A + (size_t)a_grow * HH + a_kq * 4);
#pragma unroll
        for (int i = 0; i < 2; ++i) {
            int idx = tid + i * 512;
            int kk = idx >> 6, cq = idx & 63;
            wREG[i] = *(const float4*)(W + (size_t)kk * 256 + cq * 4);
        }
        if (relu_in) {
            aREG.x = fmaxf(aREG.x, 0.f); aREG.y = fmaxf(aREG.y, 0.f);
            aREG.z = fmaxf(aREG.z, 0.f); aREG.w = fmaxf(aREG.w, 0.f);
        }
        As[0][a_kq * 4 + 0][a_r] = f2tf32(aREG.x);
        As[0][a_kq * 4 + 1][a_r] = f2tf32(aREG.y);
        As[0][a_kq * 4 + 2][a_r] = f2tf32(aREG.z);
        As[0][a_kq * 4 + 3][a_r] = f2tf32(aREG.w);
#pragma unroll
        for (int i = 0; i < 2; ++i) {
            int idx = tid + i * 512;
            int kk = idx >> 6, cq = idx & 63;
            uint32_t* p = &Ws[0][kk][cq * 4];
            p[0] = f2tf32(wREG[i].x); p[1] = f2tf32(wREG[i].y);
            p[2] = f2tf32(wREG[i].z); p[3] = f2tf32(wREG[i].w);
        }
        __syncthreads();
    }

    const int NITER = HH / BK;
    for (int iter = 0; iter < NITER; ++iter) {
        int cur = iter & 1;
        if (iter + 1 < NITER) {
            int k0 = (iter + 1) * BK;
            aREG = make_float4(0.f, 0.f, 0.f, 0.f);
            if (a_grow < M)
                aREG = *(const float4*)(A + (size_t)a_grow * HH + k0 + a_kq * 4);
#pragma unroll
            for (int i = 0; i < 2; ++i) {
                int idx = tid + i * 512;
                int kk = idx >> 6, cq = idx & 63;
                wREG[i] = *(const float4*)(W + (size_t)(k0 + kk) * 256 + cq * 4);
            }
        }
#pragma unroll
        for (int ks = 0; ks < BK; ks += 8) {
            uint32_t af[2][4];
            uint32_t bf[8][2];
#pragma unroll
            for (int mi = 0; mi < 2; ++mi) {
                int ar = wm * 32 + mi * 16 + gp;
                af[mi][0] = As[cur][ks + tg][ar];
                af[mi][1] = As[cur][ks + tg][ar + 8];
                af[mi][2] = As[cur][ks + tg + 4][ar];
                af[mi][3] = As[cur][ks + tg + 4][ar + 8];
            }
#pragma unroll
            for (int ni = 0; ni < 8; ++ni) {
                int nc = wn * 64 + ni * 8 + gp;
                bf[ni][0] = Ws[cur][ks + tg][nc];
                bf[ni][1] = Ws[cur][ks + tg + 4][nc];
            }
#pragma unroll
            for (int mi = 0; mi < 2; ++mi)
#pragma unroll
                for (int ni = 0; ni < 8; ++ni)
                    mma_tf32(acc[mi][ni], af[mi], bf[ni]);
        }
        if (iter + 1 < NITER) {
            int nxt = 1 - cur;
            if (relu_in) {
                aREG.x = fmaxf(aREG.x, 0.f); aREG.y = fmaxf(aREG.y, 0.f);
                aREG.z = fmaxf(aREG.z, 0.f); aREG.w = fmaxf(aREG.w, 0.f);
            }
            As[nxt][a_kq * 4 + 0][a_r] = f2tf32(aREG.x);
            As[nxt][a_kq * 4 + 1][a_r] = f2tf32(aREG.y);
            As[nxt][a_kq * 4 + 2][a_r] = f2tf32(aREG.z);
            As[nxt][a_kq * 4 + 3][a_r] = f2tf32(aREG.w);
#pragma unroll
            for (int i = 0; i < 2; ++i) {
                int idx = tid + i * 512;
                int kk = idx >> 6, cq = idx & 63;
                uint32_t* p = &Ws[nxt][kk][cq * 4];
                p[0] = f2tf32(wREG[i].x); p[1] = f2tf32(wREG[i].y);
                p[2] = f2tf32(wREG[i].z); p[3] = f2tf32(wREG[i].w);
            }
        }
        __syncthreads();
    }

#pragma unroll
    for (int ni = 0; ni < 8; ++ni) {
        int col = wn * 64 + ni * 8 + tg * 2;
        bool main_half = (col < HH);
        float b0 = 0.f, b1 = 0.f;
        if (main_half) { b0 = __ldg(bias + col); b1 = __ldg(bias + col + 1); }
        int oc = main_half ? col : (col - HH);
#pragma unroll
        for (int mi = 0; mi < 2; ++mi) {
            int r0 = row0 + wm * 32 + mi * 16 + gp;
            int r1 = r0 + 8;
            float4 d = acc[mi][ni];
            if (main_half) {
                if (r0 < M)
                    *(float2*)(out_main + (size_t)r0 * HH + oc) =
                        make_float2(d.x + b0, d.y + b1);
                if (r1 < M)
                    *(float2*)(out_main + (size_t)r1 * HH + oc) =
                        make_float2(d.z + b0, d.w + b1);
            } else {
                if (r0 < M)
                    *(__half2*)(out_aux + (size_t)r0 * HH + oc) =
                        __floats2half2_rn(d.x, d.y);
                if (r1 < M)
                    *(__half2*)(out_aux + (size_t)r1 * HH + oc) =
                        __floats2half2_rn(d.z, d.w);
            }
        }
    }
}

// ---------------- fp32 GEMM (host path, small) ------------------------------
// out fp32, or outh fp16 when outh != nullptr
__global__ __launch_bounds__(256)
void gemm2_kernel(const float* __restrict__ A0, const float* __restrict__ W0,
                  const float* __restrict__ A1, const float* __restrict__ W1,
                  const float* __restrict__ bias, float* __restrict__ out,
                  __half* __restrict__ outh,
                  int M, int nsrc, int relu_mask) {
    const int BM = 128, BK = 16;
    __shared__ float As[BK][BM + 4];
    __shared__ float Ws[BK][128];
    int tid = threadIdx.x;
    int tx = tid & 15, ty = tid >> 4;
    int row0 = blockIdx.x * BM;
    float acc[8][8];
#pragma unroll
    for (int i = 0; i < 8; ++i)
#pragma unroll
        for (int j = 0; j < 8; ++j) acc[i][j] = 0.f;

    const float* Aarr[2] = {A0, A1};
    const float* Warr[2] = {W0, W1};

    for (int s = 0; s < nsrc; ++s) {
        const float* A = Aarr[s];
        const float* W = Warr[s];
        int rl = (relu_mask >> s) & 1;
        for (int k0 = 0; k0 < 128; k0 += BK) {
#pragma unroll
            for (int i = 0; i < 2; ++i) {
                int idx = tid + i * 256;
                int r = idx >> 2, kq = idx & 3;
                int grow = row0 + r;
                float4 v = make_float4(0.f, 0.f, 0.f, 0.f);
                if (grow < M)
                    v = *(const float4*)(A + (size_t)grow * 128 + k0 + kq * 4);
                if (rl) {
                    v.x = fmaxf(v.x, 0.f); v.y = fmaxf(v.y, 0.f);
                    v.z = fmaxf(v.z, 0.f); v.w = fmaxf(v.w, 0.f);
                }
                As[kq * 4 + 0][r] = v.x;
                As[kq * 4 + 1][r] = v.y;
                As[kq * 4 + 2][r] = v.z;
                As[kq * 4 + 3][r] = v.w;
            }
#pragma unroll
            for (int i = 0; i < 2; ++i) {
                int idx = tid + i * 256;
                int kk = idx >> 5, cq = idx & 31;
                *(float4*)&Ws[kk][cq * 4] =
                    *(const float4*)(W + (size_t)(k0 + kk) * 128 + cq * 4);
            }
            __syncthreads();
#pragma unroll
            for (int k = 0; k < BK; ++k) {
                float a[8], b[8];
#pragma unroll
                for (int i = 0; i < 8; i += 4)
                    *(float4*)&a[i] = *(const float4*)&As[k][ty * 8 + i];
#pragma unroll
                for (int j = 0; j < 8; j += 4)
                    *(float4*)&b[j] = *(const float4*)&Ws[k][tx * 8 + j];
#pragma unroll
                for (int i = 0; i < 8; ++i)
#pragma unroll
                    for (int j = 0; j < 8; ++j)
                        acc[i][j] = fmaf(a[i], b[j], acc[i][j]);
            }
            __syncthreads();
        }
    }
#pragma unroll
    for (int i = 0; i < 8; ++i) {
        int r = row0 + ty * 8 + i;
        if (r >= M) break;
        if (outh) {
#pragma unroll
            for (int j = 0; j < 8; j += 2) {
                float v0 = acc[i][j]   + __ldg(bias + tx * 8 + j);
                float v1 = acc[i][j+1] + __ldg(bias + tx * 8 + j + 1);
                *(__half2*)(outh + (size_t)r * 128 + tx * 8 + j) =
                    __floats2half2_rn(v0, v1);
            }
        } else {
#pragma unroll
            for (int j = 0; j < 8; ++j)
                out[(size_t)r * 128 + tx * 8 + j] = acc[i][j] + __ldg(bias + tx * 8 + j);
        }
    }
}

// ---------------- pooling + MLP --------------------------------------------
__global__ void pool_init_kernel(unsigned* __restrict__ pe) {
    int i = blockIdx.x * blockDim.x + threadIdx.x;
    if (i < GG * HH) pe[i] = 0x007FFFFFu;
}

__global__ void pool_max_kernel(const float* __restrict__ xf,
                                const int* __restrict__ batch,
                                unsigned* __restrict__ pe, int n) {
    const int R = 256;
    int base = blockIdx.x * R;
    if (base >= n) return;
    int end = min(base + R, n);
    int c = threadIdx.x;
    int cur = __ldg(batch + base);
    float m = -INFINITY;
    for (int r = base; r < end; ++r) {
        int g = __ldg(batch + r);
        if (g != cur) {
            atomicMax(&pe[cur * HH + c], enc_f(m));
            cur = g; m = -INFINITY;
        }
        m = fmaxf(m, xf[(size_t)r * HH + c]);
    }
    atomicMax(&pe[cur * HH + c], enc_f(m));
}

__global__ void pool_decode_kernel(const unsigned* __restrict__ pe,
                                   float* __restrict__ p) {
    int i = blockIdx.x * blockDim.x + threadIdx.x;
    if (i < GG * HH) p[i] = dec_f(pe[i]);
}

__global__ void mlp1_kernel(const float* __restrict__ pooled,
                            const float* __restrict__ Wc1,
                            const float* __restrict__ bc1,
                            float* __restrict__ h1) {
    int t = blockIdx.x * blockDim.x + threadIdx.x;
    if (t >= GG * 64) return;
    int g = t >> 6, c = t & 63;
    float acc = bc1[c];
    for (int k = 0; k < HH; ++k)
        acc = fmaf(pooled[g * HH + k], Wc1[k * 64 + c], acc);
    h1[t] = fmaxf(acc, 0.f);
}

__global__ void mlp2_kernel(const float* __restrict__ h1,
                            const float* __restrict__ Wc2,
                            const float* __restrict__ bc2,
                            float* __restrict__ h2) {
    int t = blockIdx.x * blockDim.x + threadIdx.x;
    if (t >= GG * HH) return;
    int g = t >> 7, c = t & 127;
    float acc = bc2[c];
    for (int k = 0; k < 64; ++k)
        acc = fmaf(h1[g * 64 + k], Wc2[k * HH + c], acc);
    h2[t] = fmaxf(acc, 0.f);
}

__global__ void mlp3_kernel(const float* __restrict__ h2,
                            const float* __restrict__ Wc3,
                            const float* __restrict__ bc3,
                            float* __restrict__ out) {
    int t = blockIdx.x * blockDim.x + threadIdx.x;
    if (t >= GG * 10) return;
    int g = t / 10, c = t % 10;
    float acc = bc3[c];
    for (int k = 0; k < HH; ++k)
        acc = fmaf(h2[g * HH + k], Wc3[k * 10 + c], acc);
    out[t] = acc;
}

// ---------------- host orchestration ---------------------------------------
static void build_csr(cudaStream_t st, const int* src, const int* dst, int E, int n,
                      int* cnt, int* off, int* cur, int* csr, int* bsum) {
    int nb = (n + SCAN_BLK - 1) / SCAN_BLK;
    cudaMemsetAsync(cnt, 0, (size_t)n * sizeof(int), st);
    hist_kernel<<<(E + 255) / 256, 256, 0, st>>>(dst, cnt, E);
    scanA_kernel<<<nb, SCAN_BLK, 0, st>>>(cnt, off, bsum, n);
    scanB_kernel<<<1, 256, 0, st>>>(bsum, nb);
    scanC_kernel<<<nb, SCAN_BLK, 0, st>>>(off, cur, bsum, n, E);
    fill_kernel<<<(E + 255) / 256, 256, 0, st>>>(src, dst, cur, csr, E);
}

extern "C" void kernel_launch(void* const* d_in, const int* in_sizes, int n_in,
                              void* d_out, int out_size) {
    const int*   host_ids  = (const int*)  d_in[0];
    const float* flow_x    = (const float*)d_in[1];
    const int*   h2f_src   = (const int*)  d_in[2];
    const int*   h2f_dst   = (const int*)  d_in[3];
    const int*   f2h_src   = (const int*)  d_in[4];
    const int*   f2h_dst   = (const int*)  d_in[5];
    const int*   rel_src   = (const int*)  d_in[6];
    const int*   rel_dst   = (const int*)  d_in[7];
    const int*   flow_batch= (const int*)  d_in[8];
    const float* host_embed= (const float*)d_in[9];
    const float* Wr0_h2f   = (const float*)d_in[10];
    const float* br0_h2f   = (const float*)d_in[11];
    const float* Wo0_h2f   = (const float*)d_in[12];
    const float* Wr0_f2h   = (const float*)d_in[13];
    const float* br0_f2h   = (const float*)d_in[14];
    const float* Wo0_f2h   = (const float*)d_in[15];
    const float* Wr0_rel   = (const float*)d_in[16];
    const float* br0_rel   = (const float*)d_in[17];
    const float* Wo0_rel   = (const float*)d_in[18];
    const float* Wr        = (const float*)d_in[19];  // [2,3,128,128]
    const float* br        = (const float*)d_in[20];  // [2,3,128]
    const float* Wo        = (const float*)d_in[21];  // [2,3,128,128]
    const float* Wc1       = (const float*)d_in[22];
    const float* bc1       = (const float*)d_in[23];
    const float* Wc2       = (const float*)d_in[24];
    const float* bc2       = (const float*)d_in[25];
    const float* Wc3       = (const float*)d_in[26];
    const float* bc3       = (const float*)d_in[27];
    float* out = (float*)d_out;

    float *xfA, *xfB, *xhA, *xhB, *ah;
    __half *trel, *th;
    float *WF, *Wf2hPad, *biasF, *zeroBias;
    unsigned* poolEnc; float *pooled, *h1, *h2;
    int *csr_rel, *csr_h2f, *csr_f2h;
    int *off_rel, *off_h2f, *off_f2h;
    int *cur_rel, *cur_h2f, *cur_f2h;
    int *cnt_rel, *cnt_h2f, *cnt_f2h, *bsum;
    cudaGetSymbolAddress((void**)&xfA, g_xflowA);
    cudaGetSymbolAddress((void**)&xfB, g_xflowB);
    cudaGetSymbolAddress((void**)&trel, g_trel);
    cudaGetSymbolAddress((void**)&th,  g_th);
    cudaGetSymbolAddress((void**)&xhA, g_xhostA);
    cudaGetSymbolAddress((void**)&xhB, g_xhostB);
    cudaGetSymbolAddress((void**)&ah,  g_aggh);
    cudaGetSymbolAddress((void**)&WF,  g_WF);
    cudaGetSymbolAddress((void**)&Wf2hPad, g_Wf2hPad);
    cudaGetSymbolAddress((void**)&biasF,   g_biasF);
    cudaGetSymbolAddress((void**)&zeroBias, g_zeroBias);
    cudaGetSymbolAddress((void**)&poolEnc, g_poolEnc);
    cudaGetSymbolAddress((void**)&pooled,  g_pooled);
    cudaGetSymbolAddress((void**)&h1, g_h1);
    cudaGetSymbolAddress((void**)&h2, g_h2);
    cudaGetSymbolAddress((void**)&csr_rel, g_csr_rel);
    cudaGetSymbolAddress((void**)&csr_h2f, g_csr_h2f);
    cudaGetSymbolAddress((void**)&csr_f2h, g_csr_f2h);
    cudaGetSymbolAddress((void**)&off_rel, g_off_rel);
    cudaGetSymbolAddress((void**)&off_h2f, g_off_h2f);
    cudaGetSymbolAddress((void**)&off_f2h, g_off_f2h);
    cudaGetSymbolAddress((void**)&cur_rel, g_cur_rel);
    cudaGetSymbolAddress((void**)&cur_h2f, g_cur_h2f);
    cudaGetSymbolAddress((void**)&cur_f2h, g_cur_f2h);
    cudaGetSymbolAddress((void**)&cnt_rel, g_cnt_rel);
    cudaGetSymbolAddress((void**)&cnt_h2f, g_cnt_h2f);
    cudaGetSymbolAddress((void**)&cnt_f2h, g_cnt_f2h);
    cudaGetSymbolAddress((void**)&bsum, g_bsum);

    static cudaStream_t sB = nullptr;
    static cudaEvent_t evFork = nullptr, evPrep = nullptr, evCsrB = nullptr,
                       evTh = nullptr, evFlow = nullptr;
    if (!sB) {
        cudaStreamCreateWithFlags(&sB, cudaStreamNonBlocking);
        cudaEventCreateWithFlags(&evFork, cudaEventDisableTiming);
        cudaEventCreateWithFlags(&evPrep, cudaEventDisableTiming);
        cudaEventCreateWithFlags(&evCsrB, cudaEventDisableTiming);
        cudaEventCreateWithFlags(&evTh,   cudaEventDisableTiming);
        cudaEventCreateWithFlags(&evFlow, cudaEventDisableTiming);
    }
    cudaStream_t s0 = 0;

    cudaEventRecord(evFork, s0);
    cudaStreamWaitEvent(sB, evFork, 0);

    build_csr(sB, h2f_src, h2f_dst, E_HF, N_FLOW, cnt_h2f, off_h2f, cur_h2f, csr_h2f, bsum + 1 * 256);
    build_csr(sB, f2h_src, f2h_dst, E_HF, N_HOST, cnt_f2h, off_f2h, cur_f2h, csr_f2h, bsum + 2 * 256);
    cudaEventRecord(evCsrB, sB);

    prep_weights_kernel<<<HH, 256, 0, s0>>>(Wo0_h2f, Wo0_rel, Wr0_rel, Wr0_f2h,
                                            Wo, Wr, br0_h2f, br0_rel, br);
    embed_kernel<<<(N_HOST * HH + 255) / 256, 256, 0, s0>>>(host_ids, host_embed, xhA);
    pad_flow_kernel<<<(N_FLOW * HH + 255) / 256, 256, 0, s0>>>(flow_x, xfA);
    cudaEventRecord(evPrep, s0);
    build_csr(s0, rel_src, rel_dst, E_REL, N_FLOW, cnt_rel, off_rel, cur_rel, csr_rel, bsum + 0 * 256);

    int flowBlocks = (N_FLOW + 127) / 128;
    int hostBlocks = (N_HOST + 127) / 128;

    float* fa = xfA; float* fb = xfB;
    float* ha = xhA; float* hb = xhB;

    for (int layer = 0; layer < 3; ++layer) {
        int relu_in = (layer > 0) ? 1 : 0;
        const float* WFl = WF + (size_t)layer * HH * 2 * HH;
        const float* bFl = biasF + (size_t)layer * HH;
        const float *WrH2F, *WrF2H, *WoF2H, *bH;
        if (layer == 0) {
            WrH2F = Wr0_h2f; WrF2H = Wf2hPad; WoF2H = Wo0_f2h; bH = br0_f2h;
        } else {
            int l = layer - 1;
            WrH2F = Wr + ((size_t)l * 3 + 0) * HH * HH;
            WrF2H = Wr + ((size_t)l * 3 + 1) * HH * HH;
            WoF2H = Wo + ((size_t)l * 3 + 1) * HH * HH;
            bH    = br + (l * 3 + 1) * HH;
        }

        // s0: fb = (relu)fa @ WoComb + bias ; trel(fp16) = (relu)fa @ Wr_rel
        gemm_dual_tc_kernel<<<flowBlocks, 512, 0, s0>>>(fa, WFl, bFl, fb, trel, N_FLOW, relu_in);

        // sB: host chain
        if (layer == 0) cudaStreamWaitEvent(sB, evPrep, 0);
        else            cudaStreamWaitEvent(sB, evFlow, 0);
        gemm2_kernel<<<hostBlocks, 256, 0, sB>>>(ha, WrH2F, nullptr, nullptr,
                                                 zeroBias, nullptr, th, N_HOST, 1, relu_in);
        cudaEventRecord(evTh, sB);
        if (layer < 2) {
            gather_host_kernel<<<(N_HOST * 32 + 255) / 256, 256, 0, sB>>>(
                fa, off_f2h, csr_f2h, ah, relu_in);
            gemm2_kernel<<<hostBlocks, 256, 0, sB>>>(ah, WrF2H, ha, WoF2H, bH, hb,
                                                     nullptr, N_HOST, 2, relu_in << 1);
        }

        // s0: fused CSR gather
        cudaStreamWaitEvent(s0, evTh, 0);
        if (layer == 0) cudaStreamWaitEvent(s0, evCsrB, 0);
        gather_flow_kernel<<<(N_FLOW * 32 + 255) / 256, 256, 0, s0>>>(
            trel, th, off_rel, csr_rel, off_h2f, csr_h2f, fb);
        cudaEventRecord(evFlow, s0);

        float* t;
        t = fa; fa = fb; fb = t;
        t = ha; ha = hb; hb = t;
    }

    pool_init_kernel<<<(GG * HH + 255) / 256, 256, 0, s0>>>(poolEnc);
    pool_max_kernel<<<(N_FLOW + 255) / 256, HH, 0, s0>>>(fa, flow_batch, poolEnc, N_FLOW);
    pool_decode_kernel<<<(GG * HH + 255) / 256, 256, 0, s0>>>(poolEnc, pooled);

    mlp1_kernel<<<(GG * 64 + 255) / 256, 256, 0, s0>>>(pooled, Wc1, bc1, h1);
    mlp2_kernel<<<(GG * HH + 255) / 256, 256, 0, s0>>>(h1, Wc2, bc2, h2);
    mlp3_kernel<<<(GG * 10 + 255) / 256, 256, 0, s0>>>(h2, Wc3, bc3, out);
}

// round 8
// speedup vs baseline: 3.2172x; 1.0322x over previous
#include <cuda_runtime.h>
#include <cuda_fp16.h>
#include <math.h>
#include <stdint.h>

#define N_HOST 20000
#define N_FLOW 200000
#define E_HF   400000
#define E_REL  800000
#define GG     64
#define HH     128
#define FI     97
#define SCAN_BLK 1024

// ---------------- scratch (device globals; no allocation allowed) ----------
__device__ float  g_xflowA[(size_t)N_FLOW * HH];   // ping
__device__ float  g_xflowB[(size_t)N_FLOW * HH];   // pong
__device__ __half g_trel  [(size_t)N_FLOW * HH];   // transformed flow (rel), fp16
__device__ __half g_th    [(size_t)N_HOST * HH];   // transformed host (h2f), fp16
__device__ float  g_xhostA[(size_t)N_HOST * HH];
__device__ float  g_xhostB[(size_t)N_HOST * HH];
__device__ float  g_aggh  [(size_t)N_HOST * HH];   // f2h aggregation into hosts

__device__ float g_WF[3][HH * 2 * HH];  // per layer: [128][256] = [WoComb | Wr_rel]
__device__ float g_Wf2hPad[HH * HH];    // pad(Wr0_f2h) 97->128 rows
__device__ float g_biasF[3][HH];        // br_h2f + br_rel per layer
__device__ float g_zeroBias[HH];        // zero-initialized device global

// CSR scratch (built once per launch, reused across layers)
__device__ int g_csr_rel[E_REL];
__device__ int g_csr_h2f[E_HF];
__device__ int g_csr_f2h[E_HF];
__device__ int g_off_rel[N_FLOW + 1];
__device__ int g_off_h2f[N_FLOW + 1];
__device__ int g_off_f2h[N_HOST + 1];
__device__ int g_cur_rel[N_FLOW];
__device__ int g_cur_h2f[N_FLOW];
__device__ int g_cur_f2h[N_HOST];
__device__ int g_cnt_rel[N_FLOW];
__device__ int g_cnt_h2f[N_FLOW];
__device__ int g_cnt_f2h[N_HOST];
__device__ int g_bsum[3][256];

__device__ unsigned g_poolEnc[GG * HH];
__device__ float    g_pooled [GG * HH];
__device__ float    g_h1[GG * 64];
__device__ float    g_h2[GG * HH];

// ---------------- small helpers -------------------------------------------
__device__ __forceinline__ unsigned enc_f(float f) {
    unsigned u = __float_as_uint(f);
    return (u & 0x80000000u) ? ~u : (u | 0x80000000u);
}
__device__ __forceinline__ float dec_f(unsigned e) {
    return (e & 0x80000000u) ? __uint_as_float(e ^ 0x80000000u)
                             : __uint_as_float(~e);
}
__device__ __forceinline__ uint32_t f2tf32(float f) {
    uint32_t r;
    asm("cvt.rna.tf32.f32 %0, %1;" : "=r"(r) : "f"(f));
    return r;
}
__device__ __forceinline__ void mma_tf32(float4& d, const uint32_t* a,
                                         const uint32_t* b) {
    asm volatile(
        "mma.sync.aligned.m16n8k8.row.col.f32.tf32.tf32.f32 "
        "{%0,%1,%2,%3}, {%4,%5,%6,%7}, {%8,%9}, {%0,%1,%2,%3};"
        : "+f"(d.x), "+f"(d.y), "+f"(d.z), "+f"(d.w)
        : "r"(a[0]), "r"(a[1]), "r"(a[2]), "r"(a[3]), "r"(b[0]), "r"(b[1]));
}

// ---------------- CSR construction -----------------------------------------
__global__ void hist_kernel(const int* __restrict__ dst, int* __restrict__ cnt,
                            int E) {
    int i = blockIdx.x * blockDim.x + threadIdx.x;
    if (i < E) atomicAdd(&cnt[__ldg(dst + i)], 1);
}

__global__ void scanA_kernel(const int* __restrict__ cnt, int* __restrict__ off,
                             int* __restrict__ bsum, int n) {
    __shared__ int sh[SCAN_BLK];
    int tx = threadIdx.x;
    int i = blockIdx.x * SCAN_BLK + tx;
    int v = (i < n) ? cnt[i] : 0;
    sh[tx] = v;
    __syncthreads();
    for (int d = 1; d < SCAN_BLK; d <<= 1) {
        int t = (tx >= d) ? sh[tx - d] : 0;
        __syncthreads();
        sh[tx] += t;
        __syncthreads();
    }
    if (i < n) off[i] = sh[tx] - v;
    if (tx == SCAN_BLK - 1) bsum[blockIdx.x] = sh[tx];
}

__global__ void scanB_kernel(int* __restrict__ bsum, int nb) {
    __shared__ int sh[256];
    int tx = threadIdx.x;
    int v = (tx < nb) ? bsum[tx] : 0;
    sh[tx] = v;
    __syncthreads();
    for (int d = 1; d < 256; d <<= 1) {
        int t = (tx >= d) ? sh[tx - d] : 0;
        __syncthreads();
        sh[tx] += t;
        __syncthreads();
    }
    if (tx < nb) bsum[tx] = sh[tx] - v;
}

__global__ void scanC_kernel(int* __restrict__ off, int* __restrict__ cur,
                             const int* __restrict__ bsum, int n, int E) {
    int i = blockIdx.x * SCAN_BLK + threadIdx.x;
    if (i < n) {
        int o = off[i] + bsum[blockIdx.x];
        off[i] = o;
        cur[i] = o;
    }
    if (i == 0) off[n] = E;
}

__global__ void fill_kernel(const int* __restrict__ src, const int* __restrict__ dst,
                            int* __restrict__ cur, int* __restrict__ csr, int E) {
    int i = blockIdx.x * blockDim.x + threadIdx.x;
    if (i < E) {
        int d = __ldg(dst + i);
        int p = atomicAdd(&cur[d], 1);
        csr[p] = __ldg(src + i);
    }
}

// ---------------- gathers ---------------------------------------------------
__global__ void gather_flow_kernel(const __half* __restrict__ trel,
                                   const __half* __restrict__ th,
                                   const int* __restrict__ off_rel,
                                   const int* __restrict__ csr_rel,
                                   const int* __restrict__ off_h2f,
                                   const int* __restrict__ csr_h2f,
                                   float* __restrict__ fb) {
    int w = (blockIdx.x * blockDim.x + threadIdx.x) >> 5;
    int lane = threadIdx.x & 31;
    if (w >= N_FLOW) return;
    float4* fp = (float4*)(fb + (size_t)w * HH);
    float4 acc = fp[lane];
    int b = __ldg(off_rel + w), e = __ldg(off_rel + w + 1);
    for (int i = b; i < e; ++i) {
        int s = __ldg(csr_rel + i);
        uint2 v = ((const uint2*)(trel + (size_t)s * HH))[lane];
        float2 p0 = __half22float2(*(__half2*)&v.x);
        float2 p1 = __half22float2(*(__half2*)&v.y);
        acc.x += p0.x; acc.y += p0.y; acc.z += p1.x; acc.w += p1.y;
    }
    b = __ldg(off_h2f + w); e = __ldg(off_h2f + w + 1);
    for (int i = b; i < e; ++i) {
        int s = __ldg(csr_h2f + i);
        uint2 v = ((const uint2*)(th + (size_t)s * HH))[lane];
        float2 p0 = __half22float2(*(__half2*)&v.x);
        float2 p1 = __half22float2(*(__half2*)&v.y);
        acc.x += p0.x; acc.y += p0.y; acc.z += p1.x; acc.w += p1.y;
    }
    fp[lane] = acc;
}

// last layer: gather + global max pool fused; never writes fb.
// 256 thr = 8 warps = 8 consecutive flows; smem reduce then atomicMax.
__global__ __launch_bounds__(256)
void gather_flow_pool_kernel(const __half* __restrict__ trel,
                             const __half* __restrict__ th,
                             const float* __restrict__ fmain,
                             const int* __restrict__ off_rel,
                             const int* __restrict__ csr_rel,
                             const int* __restrict__ off_h2f,
                             const int* __restrict__ csr_h2f,
                             const int* __restrict__ batch,
                             unsigned* __restrict__ pe) {
    __shared__ float sm[8][HH];
    __shared__ int sg[8];
    int warp = threadIdx.x >> 5, lane = threadIdx.x & 31;
    int w = blockIdx.x * 8 + warp;
    float4 acc = make_float4(0.f, 0.f, 0.f, 0.f);
    int g = -1;
    if (w < N_FLOW) {
        g = __ldg(batch + w);
        acc = ((const float4*)(fmain + (size_t)w * HH))[lane];
        int b = __ldg(off_rel + w), e = __ldg(off_rel + w + 1);
        for (int i = b; i < e; ++i) {
            int s = __ldg(csr_rel + i);
            uint2 v = ((const uint2*)(trel + (size_t)s * HH))[lane];
            float2 p0 = __half22float2(*(__half2*)&v.x);
            float2 p1 = __half22float2(*(__half2*)&v.y);
            acc.x += p0.x; acc.y += p0.y; acc.z += p1.x; acc.w += p1.y;
        }
        b = __ldg(off_h2f + w); e = __ldg(off_h2f + w + 1);
        for (int i = b; i < e; ++i) {
            int s = __ldg(csr_h2f + i);
            uint2 v = ((const uint2*)(th + (size_t)s * HH))[lane];
            float2 p0 = __half22float2(*(__half2*)&v.x);
            float2 p1 = __half22float2(*(__half2*)&v.y);
            acc.x += p0.x; acc.y += p0.y; acc.z += p1.x; acc.w += p1.y;
        }
    }
    if (lane == 0) sg[warp] = g;
    *(float4*)&sm[warp][lane * 4] = acc;
    __syncthreads();
    if (threadIdx.x < HH) {
        int c = threadIdx.x;
        int cur = sg[0];
        float m = -INFINITY;
#pragma unroll
        for (int r = 0; r < 8; ++r) {
            int gg = sg[r];
            if (gg != cur) {
                if (cur >= 0) atomicMax(&pe[cur * HH + c], enc_f(m));
                cur = gg; m = -INFINITY;
            }
            if (gg >= 0) m = fmaxf(m, sm[r][c]);
        }
        if (cur >= 0) atomicMax(&pe[cur * HH + c], enc_f(m));
    }
}

__global__ void gather_host_kernel(const float* __restrict__ fa,
                                   const int* __restrict__ off,
                                   const int* __restrict__ csr,
                                   float* __restrict__ ah, int relu_in) {
    int w = (blockIdx.x * blockDim.x + threadIdx.x) >> 5;
    int lane = threadIdx.x & 31;
    if (w >= N_HOST) return;
    float4 acc = make_float4(0.f, 0.f, 0.f, 0.f);
    int b = __ldg(off + w), e = __ldg(off + w + 1);
    for (int i = b; i < e; ++i) {
        int s = __ldg(csr + i);
        float4 v = ((const float4*)(fa + (size_t)s * HH))[lane];
        if (relu_in) {
            v.x = fmaxf(v.x, 0.f); v.y = fmaxf(v.y, 0.f);
            v.z = fmaxf(v.z, 0.f); v.w = fmaxf(v.w, 0.f);
        }
        acc.x += v.x; acc.y += v.y; acc.z += v.z; acc.w += v.w;
    }
    ((float4*)(ah + (size_t)w * HH))[lane] = acc;
}

// ---------------- prep ------------------------------------------------------
__global__ void embed_kernel(const int* __restrict__ ids,
                             const float* __restrict__ table,
                             float* __restrict__ xh) {
    int i = blockIdx.x * blockDim.x + threadIdx.x;
    if (i >= N_HOST * HH) return;
    int row = i >> 7, c = i & 127;
    xh[i] = table[(size_t)__ldg(ids + row) * HH + c];
}

__global__ void pad_flow_kernel(const float* __restrict__ fx,
                                float* __restrict__ xf) {
    int i = blockIdx.x * blockDim.x + threadIdx.x;
    if (i >= N_FLOW * HH) return;
    int row = i >> 7, c = i & 127;
    xf[i] = (c < FI) ? fx[(size_t)row * FI + c] : 0.f;
}

__global__ void prep_weights_kernel(const float* __restrict__ Wo0_h2f,
                                    const float* __restrict__ Wo0_rel,
                                    const float* __restrict__ Wr0_rel,
                                    const float* __restrict__ Wr0_f2h,
                                    const float* __restrict__ Wo,
                                    const float* __restrict__ Wr,
                                    const float* __restrict__ br0_h2f,
                                    const float* __restrict__ br0_rel,
                                    const float* __restrict__ br) {
    int k = blockIdx.x;
    int c = threadIdx.x;
    int idx = k * 256 + c;
    if (c < HH) {
        g_WF[0][idx] = (k < FI) ? (Wo0_h2f[k * HH + c] + Wo0_rel[k * HH + c]) : 0.f;
        g_Wf2hPad[k * HH + c] = (k < FI) ? Wr0_f2h[k * HH + c] : 0.f;
    } else {
        int cc = c - HH;
        g_WF[0][idx] = (k < FI) ? Wr0_rel[k * HH + cc] : 0.f;
    }
    for (int l = 0; l < 2; ++l) {
        float v;
        if (c < HH)
            v = Wo[((size_t)l * 3 + 0) * HH * HH + k * HH + c]
              + Wo[((size_t)l * 3 + 2) * HH * HH + k * HH + c];
        else
            v = Wr[((size_t)l * 3 + 2) * HH * HH + k * HH + (c - HH)];
        g_WF[l + 1][idx] = v;
    }
    if (k == 0 && c < HH) {
        g_biasF[0][c] = br0_h2f[c] + br0_rel[c];
        for (int l = 0; l < 2; ++l)
            g_biasF[l + 1][c] = br[(l * 3 + 0) * HH + c] + br[(l * 3 + 2) * HH + c];
        g_zeroBias[c] = 0.f;
    }
}

// ---------------- tf32 tensor-core GEMM (flow path) -------------------------
__global__ __launch_bounds__(512, 1)
void gemm_dual_tc_kernel(const float* __restrict__ A, const float* __restrict__ W,
                         const float* __restrict__ bias,
                         float* __restrict__ out_main, __half* __restrict__ out_aux,
                         int M, int relu_in) {
    const int BK = 16;
    __shared__ uint32_t As[2][BK][136];
    __shared__ uint32_t Ws[2][BK][264];

    int tid  = threadIdx.x;
    int warp = tid >> 5, lane = tid & 31;
    int wm = warp >> 2, wn = warp & 3;
    int tg = lane & 3, gp = lane >> 2;
    int row0 = blockIdx.x * 128;

    float4 acc[2][8];
#pragma unroll
    for (int i = 0; i < 2; ++i)
#pragma unroll
        for (int j = 0; j < 8; ++j) acc[i][j] = make_float4(0.f, 0.f, 0.f, 0.f);

    int a_r = tid >> 2, a_kq = tid & 3;
    int a_grow = row0 + a_r;
    float4 aREG;
    float4 wREG[2];

    {
        aREG = make_float4(0.f, 0.f, 0.f, 0.f);
        if (a_grow < M)
            aREG = *(const float4*)(A + (size_t)a_grow * HH + a_kq * 4);
#pragma unroll
        for (int i = 0; i < 2; ++i) {
            int idx = tid + i * 512;
            int kk = idx >> 6, cq = idx & 63;
            wREG[i] = *(const float4*)(W + (size_t)kk * 256 + cq * 4);
        }
        if (relu_in) {
            aREG.x = fmaxf(aREG.x, 0.f); aREG.y = fmaxf(aREG.y, 0.f);
            aREG.z = fmaxf(aREG.z, 0.f); aREG.w = fmaxf(aREG.w, 0.f);
        }
        As[0][a_kq * 4 + 0][a_r] = f2tf32(aREG.x);
        As[0][a_kq * 4 + 1][a_r] = f2tf32(aREG.y);
        As[0][a_kq * 4 + 2][a_r] = f2tf32(aREG.z);
        As[0][a_kq * 4 + 3][a_r] = f2tf32(aREG.w);
#pragma unroll
        for (int i = 0; i < 2; ++i) {
            int idx = tid + i * 512;
            int kk = idx >> 6, cq = idx & 63;
            uint32_t* p = &Ws[0][kk][cq * 4];
            p[0] = f2tf32(wREG[i].x); p[1] = f2tf32(wREG[i].y);
            p[2] = f2tf32(wREG[i].z); p[3] = f2tf32(wREG[i].w);
        }
        __syncthreads();
    }

    const int NITER = HH / BK;
    for (int iter = 0; iter < NITER; ++iter) {
        int cur = iter & 1;
        if (iter + 1 < NITER) {
            int k0 = (iter + 1) * BK;
            aREG = make_float4(0.f, 0.f, 0.f, 0.f);
            if (a_grow < M)
                aREG = *(const float4*)(A + (size_t)a_grow * HH + k0 + a_kq * 4);
#pragma unroll
            for (int i = 0; i < 2; ++i) {
                int idx = tid + i * 512;
                int kk = idx >> 6, cq = idx & 63;
                wREG[i] = *(const float4*)(W + (size_t)(k0 + kk) * 256 + cq * 4);
            }
        }
#pragma unroll
        for (int ks = 0; ks < BK; ks += 8) {
            uint32_t af[2][4];
            uint32_t bf[8][2];
#pragma unroll
            for (int mi = 0; mi < 2; ++mi) {
                int ar = wm * 32 + mi * 16 + gp;
                af[mi][0] = As[cur][ks + tg][ar];
                af[mi][1] = As[cur][ks + tg][ar + 8];
                af[mi][2] = As[cur][ks + tg + 4][ar];
                af[mi][3] = As[cur][ks + tg + 4][ar + 8];
            }
#pragma unroll
            for (int ni = 0; ni < 8; ++ni) {
                int nc = wn * 64 + ni * 8 + gp;
                bf[ni][0] = Ws[cur][ks + tg][nc];
                bf[ni][1] = Ws[cur][ks + tg + 4][nc];
            }
#pragma unroll
            for (int mi = 0; mi < 2; ++mi)
#pragma unroll
                for (int ni = 0; ni < 8; ++ni)
                    mma_tf32(acc[mi][ni], af[mi], bf[ni]);
        }
        if (iter + 1 < NITER) {
            int nxt = 1 - cur;
            if (relu_in) {
                aREG.x = fmaxf(aREG.x, 0.f); aREG.y = fmaxf(aREG.y, 0.f);
                aREG.z = fmaxf(aREG.z, 0.f); aREG.w = fmaxf(aREG.w, 0.f);
            }
            As[nxt][a_kq * 4 + 0][a_r] = f2tf32(aREG.x);
            As[nxt][a_kq * 4 + 1][a_r] = f2tf32(aREG.y);
            As[nxt][a_kq * 4 + 2][a_r] = f2tf32(aREG.z);
            As[nxt][a_kq * 4 + 3][a_r] = f2tf32(aREG.w);
#pragma unroll
            for (int i = 0; i < 2; ++i) {
                int idx = tid + i * 512;
                int kk = idx >> 6, cq = idx & 63;
                uint32_t* p = &Ws[nxt][kk][cq * 4];
                p[0] = f2tf32(wREG[i].x); p[1] = f2tf32(wREG[i].y);
                p[2] = f2tf32(wREG[i].z); p[3] = f2tf32(wREG[i].w);
            }
        }
        __syncthreads();
    }

#pragma unroll
    for (int ni = 0; ni < 8; ++ni) {
        int col = wn * 64 + ni * 8 + tg * 2;
        bool main_half = (col < HH);
        float b0 = 0.f, b1 = 0.f;
        if (main_half) { b0 = __ldg(bias + col); b1 = __ldg(bias + col + 1); }
        int oc = main_half ? col : (col - HH);
#pragma unroll
        for (int mi = 0; mi < 2; ++mi) {
            int r0 = row0 + wm * 32 + mi * 16 + gp;
            int r1 = r0 + 8;
            float4 d = acc[mi][ni];
            if (main_half) {
                if (r0 < M)
                    *(float2*)(out_main + (size_t)r0 * HH + oc) =
                        make_float2(d.x + b0, d.y + b1);
                if (r1 < M)
                    *(float2*)(out_main + (size_t)r1 * HH + oc) =
                        make_float2(d.z + b0, d.w + b1);
            } else {
                if (r0 < M)
                    *(__half2*)(out_aux + (size_t)r0 * HH + oc) =
                        __floats2half2_rn(d.x, d.y);
                if (r1 < M)
                    *(__half2*)(out_aux + (size_t)r1 * HH + oc) =
                        __floats2half2_rn(d.z, d.w);
            }
        }
    }
}

// ---------------- fp32 GEMM (host path, small) ------------------------------
__global__ __launch_bounds__(256)
void gemm2_kernel(const float* __restrict__ A0, const float* __restrict__ W0,
                  const float* __restrict__ A1, const float* __restrict__ W1,
                  const float* __restrict__ bias, float* __restrict__ out,
                  __half* __restrict__ outh,
                  int M, int nsrc, int relu_mask) {
    const int BM = 128, BK = 16;
    __shared__ float As[BK][BM + 4];
    __shared__ float Ws[BK][128];
    int tid = threadIdx.x;
    int tx = tid & 15, ty = tid >> 4;
    int row0 = blockIdx.x * BM;
    float acc[8][8];
#pragma unroll
    for (int i = 0; i < 8; ++i)
#pragma unroll
        for (int j = 0; j < 8; ++j) acc[i][j] = 0.f;

    const float* Aarr[2] = {A0, A1};
    const float* Warr[2] = {W0, W1};

    for (int s = 0; s < nsrc; ++s) {
        const float* A = Aarr[s];
        const float* W = Warr[s];
        int rl = (relu_mask >> s) & 1;
        for (int k0 = 0; k0 < 128; k0 += BK) {
#pragma unroll
            for (int i = 0; i < 2; ++i) {
                int idx = tid + i * 256;
                int r = idx >> 2, kq = idx & 3;
                int grow = row0 + r;
                float4 v = make_float4(0.f, 0.f, 0.f, 0.f);
                if (grow < M)
                    v = *(const float4*)(A + (size_t)grow * 128 + k0 + kq * 4);
                if (rl) {
                    v.x = fmaxf(v.x, 0.f); v.y = fmaxf(v.y, 0.f);
                    v.z = fmaxf(v.z, 0.f); v.w = fmaxf(v.w, 0.f);
                }
                As[kq * 4 + 0][r] = v.x;
                As[kq * 4 + 1][r] = v.y;
                As[kq * 4 + 2][r] = v.z;
                As[kq * 4 + 3][r] = v.w;
            }
#pragma unroll
            for (int i = 0; i < 2; ++i) {
                int idx = tid + i * 256;
                int kk = idx >> 5, cq = idx & 31;
                *(float4*)&Ws[kk][cq * 4] =
                    *(const float4*)(W + (size_t)(k0 + kk) * 128 + cq * 4);
            }
            __syncthreads();
#pragma unroll
            for (int k = 0; k < BK; ++k) {
                float a[8], b[8];
#pragma unroll
                for (int i = 0; i < 8; i += 4)
                    *(float4*)&a[i] = *(const float4*)&As[k][ty * 8 + i];
#pragma unroll
                for (int j = 0; j < 8; j += 4)
                    *(float4*)&b[j] = *(const float4*)&Ws[k][tx * 8 + j];
#pragma unroll
                for (int i = 0; i < 8; ++i)
#pragma unroll
                    for (int j = 0; j < 8; ++j)
                        acc[i][j] = fmaf(a[i], b[j], acc[i][j]);
            }
            __syncthreads();
        }
    }
#pragma unroll
    for (int i = 0; i < 8; ++i) {
        int r = row0 + ty * 8 + i;
        if (r >= M) break;
        if (outh) {
#pragma unroll
            for (int j = 0; j < 8; j += 2) {
                float v0 = acc[i][j]   + __ldg(bias + tx * 8 + j);
                float v1 = acc[i][j+1] + __ldg(bias + tx * 8 + j + 1);
                *(__half2*)(outh + (size_t)r * 128 + tx * 8 + j) =
                    __floats2half2_rn(v0, v1);
            }
        } else {
#pragma unroll
            for (int j = 0; j < 8; ++j)
                out[(size_t)r * 128 + tx * 8 + j] = acc[i][j] + __ldg(bias + tx * 8 + j);
        }
    }
}

// ---------------- pooling + MLP --------------------------------------------
__global__ void pool_init_kernel(unsigned* __restrict__ pe) {
    int i = blockIdx.x * blockDim.x + threadIdx.x;
    if (i < GG * HH) pe[i] = 0x007FFFFFu;
}

__global__ void pool_decode_kernel(const unsigned* __restrict__ pe,
                                   float* __restrict__ p) {
    int i = blockIdx.x * blockDim.x + threadIdx.x;
    if (i < GG * HH) p[i] = dec_f(pe[i]);
}

__global__ void mlp1_kernel(const float* __restrict__ pooled,
                            const float* __restrict__ Wc1,
                            const float* __restrict__ bc1,
                            float* __restrict__ h1) {
    int t = blockIdx.x * blockDim.x + threadIdx.x;
    if (t >= GG * 64) return;
    int g = t >> 6, c = t & 63;
    float acc = bc1[c];
    for (int k = 0; k < HH; ++k)
        acc = fmaf(pooled[g * HH + k], Wc1[k * 64 + c], acc);
    h1[t] = fmaxf(acc, 0.f);
}

__global__ void mlp2_kernel(const float* __restrict__ h1,
                            const float* __restrict__ Wc2,
                            const float* __restrict__ bc2,
                            float* __restrict__ h2) {
    int t = blockIdx.x * blockDim.x + threadIdx.x;
    if (t >= GG * HH) return;
    int g = t >> 7, c = t & 127;
    float acc = bc2[c];
    for (int k = 0; k < 64; ++k)
        acc = fmaf(h1[g * 64 + k], Wc2[k * HH + c], acc);
    h2[t] = fmaxf(acc, 0.f);
}

__global__ void mlp3_kernel(const float* __restrict__ h2,
                            const float* __restrict__ Wc3,
                            const float* __restrict__ bc3,
                            float* __restrict__ out) {
    int t = blockIdx.x * blockDim.x + threadIdx.x;
    if (t >= GG * 10) return;
    int g = t / 10, c = t % 10;
    float acc = bc3[c];
    for (int k = 0; k < HH; ++k)
        acc = fmaf(h2[g * HH + k], Wc3[k * 10 + c], acc);
    out[t] = acc;
}

// ---------------- host orchestration ---------------------------------------
static void build_csr(cudaStream_t st, const int* src, const int* dst, int E, int n,
                      int* cnt, int* off, int* cur, int* csr, int* bsum) {
    int nb = (n + SCAN_BLK - 1) / SCAN_BLK;
    cudaMemsetAsync(cnt, 0, (size_t)n * sizeof(int), st);
    hist_kernel<<<(E + 255) / 256, 256, 0, st>>>(dst, cnt, E);
    scanA_kernel<<<nb, SCAN_BLK, 0, st>>>(cnt, off, bsum, n);
    scanB_kernel<<<1, 256, 0, st>>>(bsum, nb);
    scanC_kernel<<<nb, SCAN_BLK, 0, st>>>(off, cur, bsum, n, E);
    fill_kernel<<<(E + 255) / 256, 256, 0, st>>>(src, dst, cur, csr, E);
}

extern "C" void kernel_launch(void* const* d_in, const int* in_sizes, int n_in,
                              void* d_out, int out_size) {
    const int*   host_ids  = (const int*)  d_in[0];
    const float* flow_x    = (const float*)d_in[1];
    const int*   h2f_src   = (const int*)  d_in[2];
    const int*   h2f_dst   = (const int*)  d_in[3];
    const int*   f2h_src   = (const int*)  d_in[4];
    const int*   f2h_dst   = (const int*)  d_in[5];
    const int*   rel_src   = (const int*)  d_in[6];
    const int*   rel_dst   = (const int*)  d_in[7];
    const int*   flow_batch= (const int*)  d_in[8];
    const float* host_embed= (const float*)d_in[9];
    const float* Wr0_h2f   = (const float*)d_in[10];
    const float* br0_h2f   = (const float*)d_in[11];
    const float* Wo0_h2f   = (const float*)d_in[12];
    const float* Wr0_f2h   = (const float*)d_in[13];
    const float* br0_f2h   = (const float*)d_in[14];
    const float* Wo0_f2h   = (const float*)d_in[15];
    const float* Wr0_rel   = (const float*)d_in[16];
    const float* br0_rel   = (const float*)d_in[17];
    const float* Wo0_rel   = (const float*)d_in[18];
    const float* Wr        = (const float*)d_in[19];  // [2,3,128,128]
    const float* br        = (const float*)d_in[20];  // [2,3,128]
    const float* Wo        = (const float*)d_in[21];  // [2,3,128,128]
    const float* Wc1       = (const float*)d_in[22];
    const float* bc1       = (const float*)d_in[23];
    const float* Wc2       = (const float*)d_in[24];
    const float* bc2       = (const float*)d_in[25];
    const float* Wc3       = (const float*)d_in[26];
    const float* bc3       = (const float*)d_in[27];
    float* out = (float*)d_out;

    float *xfA, *xfB, *xhA, *xhB, *ah;
    __half *trel, *th;
    float *WF, *Wf2hPad, *biasF, *zeroBias;
    unsigned* poolEnc; float *pooled, *h1, *h2;
    int *csr_rel, *csr_h2f, *csr_f2h;
    int *off_rel, *off_h2f, *off_f2h;
    int *cur_rel, *cur_h2f, *cur_f2h;
    int *cnt_rel, *cnt_h2f, *cnt_f2h, *bsum;
    cudaGetSymbolAddress((void**)&xfA, g_xflowA);
    cudaGetSymbolAddress((void**)&xfB, g_xflowB);
    cudaGetSymbolAddress((void**)&trel, g_trel);
    cudaGetSymbolAddress((void**)&th,  g_th);
    cudaGetSymbolAddress((void**)&xhA, g_xhostA);
    cudaGetSymbolAddress((void**)&xhB, g_xhostB);
    cudaGetSymbolAddress((void**)&ah,  g_aggh);
    cudaGetSymbolAddress((void**)&WF,  g_WF);
    cudaGetSymbolAddress((void**)&Wf2hPad, g_Wf2hPad);
    cudaGetSymbolAddress((void**)&biasF,   g_biasF);
    cudaGetSymbolAddress((void**)&zeroBias, g_zeroBias);
    cudaGetSymbolAddress((void**)&poolEnc, g_poolEnc);
    cudaGetSymbolAddress((void**)&pooled,  g_pooled);
    cudaGetSymbolAddress((void**)&h1, g_h1);
    cudaGetSymbolAddress((void**)&h2, g_h2);
    cudaGetSymbolAddress((void**)&csr_rel, g_csr_rel);
    cudaGetSymbolAddress((void**)&csr_h2f, g_csr_h2f);
    cudaGetSymbolAddress((void**)&csr_f2h, g_csr_f2h);
    cudaGetSymbolAddress((void**)&off_rel, g_off_rel);
    cudaGetSymbolAddress((void**)&off_h2f, g_off_h2f);
    cudaGetSymbolAddress((void**)&off_f2h, g_off_f2h);
    cudaGetSymbolAddress((void**)&cur_rel, g_cur_rel);
    cudaGetSymbolAddress((void**)&cur_h2f, g_cur_h2f);
    cudaGetSymbolAddress((void**)&cur_f2h, g_cur_f2h);
    cudaGetSymbolAddress((void**)&cnt_rel, g_cnt_rel);
    cudaGetSymbolAddress((void**)&cnt_h2f, g_cnt_h2f);
    cudaGetSymbolAddress((void**)&cnt_f2h, g_cnt_f2h);
    cudaGetSymbolAddress((void**)&bsum, g_bsum);

    static cudaStream_t sB = nullptr;
    static cudaEvent_t evFork = nullptr, evPrep = nullptr, evCsrB = nullptr,
                       evTh = nullptr, evFlow = nullptr, evHG = nullptr;
    if (!sB) {
        cudaStreamCreateWithFlags(&sB, cudaStreamNonBlocking);
        cudaEventCreateWithFlags(&evFork, cudaEventDisableTiming);
        cudaEventCreateWithFlags(&evPrep, cudaEventDisableTiming);
        cudaEventCreateWithFlags(&evCsrB, cudaEventDisableTiming);
        cudaEventCreateWithFlags(&evTh,   cudaEventDisableTiming);
        cudaEventCreateWithFlags(&evFlow, cudaEventDisableTiming);
        cudaEventCreateWithFlags(&evHG,   cudaEventDisableTiming);
    }
    cudaStream_t s0 = 0;

    int flowBlocks = (N_FLOW + 127) / 128;
    int hostBlocks = (N_HOST + 127) / 128;

    cudaEventRecord(evFork, s0);
    cudaStreamWaitEvent(sB, evFork, 0);

    // s0 prologue: weights + padded flow features, then straight into GEMM L0
    prep_weights_kernel<<<HH, 256, 0, s0>>>(Wo0_h2f, Wo0_rel, Wr0_rel, Wr0_f2h,
                                            Wo, Wr, br0_h2f, br0_rel, br);
    pad_flow_kernel<<<(N_FLOW * HH + 255) / 256, 256, 0, s0>>>(flow_x, xfA);
    cudaEventRecord(evPrep, s0);

    // sB prologue: embed + pool init + th(L0) + all CSR builds + host chain L0
    embed_kernel<<<(N_HOST * HH + 255) / 256, 256, 0, sB>>>(host_ids, host_embed, xhA);
    pool_init_kernel<<<(GG * HH + 255) / 256, 256, 0, sB>>>(poolEnc);
    gemm2_kernel<<<hostBlocks, 256, 0, sB>>>(xhA, Wr0_h2f, nullptr, nullptr,
                                             zeroBias, nullptr, th, N_HOST, 1, 0);
    cudaEventRecord(evTh, sB);
    build_csr(sB, rel_src, rel_dst, E_REL, N_FLOW, cnt_rel, off_rel, cur_rel, csr_rel, bsum + 0 * 256);
    build_csr(sB, h2f_src, h2f_dst, E_HF,  N_FLOW, cnt_h2f, off_h2f, cur_h2f, csr_h2f, bsum + 1 * 256);
    cudaEventRecord(evCsrB, sB);
    build_csr(sB, f2h_src, f2h_dst, E_HF,  N_HOST, cnt_f2h, off_f2h, cur_f2h, csr_f2h, bsum + 2 * 256);
    cudaStreamWaitEvent(sB, evPrep, 0);
    gather_host_kernel<<<(N_HOST * 32 + 255) / 256, 256, 0, sB>>>(
        xfA, off_f2h, csr_f2h, ah, 0);
    cudaEventRecord(evHG, sB);
    gemm2_kernel<<<hostBlocks, 256, 0, sB>>>(ah, Wf2hPad, xhA, Wo0_f2h, br0_f2h,
                                             xhB, nullptr, N_HOST, 2, 0);

    // ---- layer 0 flow (s0) ----
    gemm_dual_tc_kernel<<<flowBlocks, 512, 0, s0>>>(xfA, WF, biasF, xfB, trel, N_FLOW, 0);
    cudaStreamWaitEvent(s0, evTh, 0);
    cudaStreamWaitEvent(s0, evCsrB, 0);
    gather_flow_kernel<<<(N_FLOW * 32 + 255) / 256, 256, 0, s0>>>(
        trel, th, off_rel, csr_rel, off_h2f, csr_h2f, xfB);
    cudaEventRecord(evFlow, s0);

    // ---- layer 1 ----
    {
        const float* WF1 = WF + (size_t)1 * HH * 2 * HH;
        const float* bF1 = biasF + (size_t)1 * HH;
        const float* WrH2F = Wr + (size_t)(0 * 3 + 0) * HH * HH;
        const float* WrF2H = Wr + (size_t)(0 * 3 + 1) * HH * HH;
        const float* WoF2H = Wo + (size_t)(0 * 3 + 1) * HH * HH;
        const float* bH    = br + (0 * 3 + 1) * HH;

        // s0: wait for gather_host L0 (last reader of xfA) before overwriting it
        cudaStreamWaitEvent(s0, evHG, 0);
        gemm_dual_tc_kernel<<<flowBlocks, 512, 0, s0>>>(xfB, WF1, bF1, xfA, trel, N_FLOW, 1);

        // sB: host chain L1
        cudaStreamWaitEvent(sB, evFlow, 0);
        gemm2_kernel<<<hostBlocks, 256, 0, sB>>>(xhB, WrH2F, nullptr, nullptr,
                                                 zeroBias, nullptr, th, N_HOST, 1, 1);
        cudaEventRecord(evTh, sB);
        gather_host_kernel<<<(N_HOST * 32 + 255) / 256, 256, 0, sB>>>(
            xfB, off_f2h, csr_f2h, ah, 1);
        cudaEventRecord(evHG, sB);
        gemm2_kernel<<<hostBlocks, 256, 0, sB>>>(ah, WrF2H, xhB, WoF2H, bH,
                                                 xhA, nullptr, N_HOST, 2, 2);

        // s0: gather
        cudaStreamWaitEvent(s0, evTh, 0);
        gather_flow_kernel<<<(N_FLOW * 32 + 255) / 256, 256, 0, s0>>>(
            trel, th, off_rel, csr_rel, off_h2f, csr_h2f, xfA);
        cudaEventRecord(evFlow, s0);
    }

    // ---- layer 2 (flow only; fused gather+pool) ----
    {
        const float* WF2 = WF + (size_t)2 * HH * 2 * HH;
        const float* bF2 = biasF + (size_t)2 * HH;
        const float* WrH2F = Wr + (size_t)(1 * 3 + 0) * HH * HH;

        cudaStreamWaitEvent(s0, evHG, 0);   // gather_host L1 read xfB
        gemm_dual_tc_kernel<<<flowBlocks, 512, 0, s0>>>(xfA, WF2, bF2, xfB, trel, N_FLOW, 1);

        cudaStreamWaitEvent(sB, evFlow, 0);
        gemm2_kernel<<<hostBlocks, 256, 0, sB>>>(xhA, WrH2F, nullptr, nullptr,
                                                 zeroBias, nullptr, th, N_HOST, 1, 1);
        cudaEventRecord(evTh, sB);

        cudaStreamWaitEvent(s0, evTh, 0);
        gather_flow_pool_kernel<<<(N_FLOW + 7) / 8, 256, 0, s0>>>(
            trel, th, xfB, off_rel, csr_rel, off_h2f, csr_h2f, flow_batch, poolEnc);
    }

    // epilogue on s0
    pool_decode_kernel<<<(GG * HH + 255) / 256, 256, 0, s0>>>(poolEnc, pooled);
    mlp1_kernel<<<(GG * 64 + 255) / 256, 256, 0, s0>>>(pooled, Wc1, bc1, h1);
    mlp2_kernel<<<(GG * HH + 255) / 256, 256, 0, s0>>>(h1, Wc2, bc2, h2);
    mlp3_kernel<<<(GG * 10 + 255) / 256, 256, 0, s0>>>(h2, Wc3, bc3, out);
}

// round 9
// speedup vs baseline: 3.2375x; 1.0063x over previous
#include <cuda_runtime.h>
#include <cuda_fp16.h>
#include <math.h>
#include <stdint.h>

#define N_HOST 20000
#define N_FLOW 200000
#define E_HF   400000
#define E_REL  800000
#define GG     64
#define HH     128
#define FI     97
#define SCAN_BLK 1024

// ---------------- scratch (device globals; no allocation allowed) ----------
__device__ __half g_xflowA[(size_t)N_FLOW * HH];   // ping (fp16 activations)
__device__ __half g_xflowB[(size_t)N_FLOW * HH];   // pong
__device__ __half g_trel  [(size_t)N_FLOW * HH];   // transformed flow (rel), fp16
__device__ __half g_th    [(size_t)N_HOST * HH];   // transformed host (h2f), fp16
__device__ float  g_xhostA[(size_t)N_HOST * HH];
__device__ float  g_xhostB[(size_t)N_HOST * HH];
__device__ float  g_aggh  [(size_t)N_HOST * HH];   // f2h aggregation into hosts

__device__ float g_WF[3][HH * 2 * HH];  // per layer: [128][256] = [WoComb | Wr_rel]
__device__ float g_Wf2hPad[HH * HH];    // pad(Wr0_f2h) 97->128 rows
__device__ float g_biasF[3][HH];        // br_h2f + br_rel per layer
__device__ float g_zeroBias[HH];        // zero-initialized device global

// CSR scratch (built once per launch, reused across layers)
__device__ int g_csr_rel[E_REL];
__device__ int g_csr_h2f[E_HF];
__device__ int g_csr_f2h[E_HF];
__device__ int g_off_rel[N_FLOW + 1];
__device__ int g_off_h2f[N_FLOW + 1];
__device__ int g_off_f2h[N_HOST + 1];
__device__ int g_cur_rel[N_FLOW];
__device__ int g_cur_h2f[N_FLOW];
__device__ int g_cur_f2h[N_HOST];
__device__ int g_cnt_rel[N_FLOW];
__device__ int g_cnt_h2f[N_FLOW];
__device__ int g_cnt_f2h[N_HOST];
__device__ int g_bsum[3][256];

__device__ unsigned g_poolEnc[GG * HH];
__device__ float    g_pooled [GG * HH];
__device__ float    g_h1[GG * 64];
__device__ float    g_h2[GG * HH];

// ---------------- small helpers -------------------------------------------
__device__ __forceinline__ unsigned enc_f(float f) {
    unsigned u = __float_as_uint(f);
    return (u & 0x80000000u) ? ~u : (u | 0x80000000u);
}
__device__ __forceinline__ float dec_f(unsigned e) {
    return (e & 0x80000000u) ? __uint_as_float(e ^ 0x80000000u)
                             : __uint_as_float(~e);
}
__device__ __forceinline__ uint32_t f2tf32(float f) {
    uint32_t r;
    asm("cvt.rna.tf32.f32 %0, %1;" : "=r"(r) : "f"(f));
    return r;
}
__device__ __forceinline__ void mma_tf32(float4& d, const uint32_t* a,
                                         const uint32_t* b) {
    asm volatile(
        "mma.sync.aligned.m16n8k8.row.col.f32.tf32.tf32.f32 "
        "{%0,%1,%2,%3}, {%4,%5,%6,%7}, {%8,%9}, {%0,%1,%2,%3};"
        : "+f"(d.x), "+f"(d.y), "+f"(d.z), "+f"(d.w)
        : "r"(a[0]), "r"(a[1]), "r"(a[2]), "r"(a[3]), "r"(b[0]), "r"(b[1]));
}

// ---------------- CSR construction -----------------------------------------
__global__ void hist_kernel(const int* __restrict__ dst, int* __restrict__ cnt,
                            int E) {
    int i = blockIdx.x * blockDim.x + threadIdx.x;
    if (i < E) atomicAdd(&cnt[__ldg(dst + i)], 1);
}

__global__ void scanA_kernel(const int* __restrict__ cnt, int* __restrict__ off,
                             int* __restrict__ bsum, int n) {
    __shared__ int sh[SCAN_BLK];
    int tx = threadIdx.x;
    int i = blockIdx.x * SCAN_BLK + tx;
    int v = (i < n) ? cnt[i] : 0;
    sh[tx] = v;
    __syncthreads();
    for (int d = 1; d < SCAN_BLK; d <<= 1) {
        int t = (tx >= d) ? sh[tx - d] : 0;
        __syncthreads();
        sh[tx] += t;
        __syncthreads();
    }
    if (i < n) off[i] = sh[tx] - v;
    if (tx == SCAN_BLK - 1) bsum[blockIdx.x] = sh[tx];
}

__global__ void scanB_kernel(int* __restrict__ bsum, int nb) {
    __shared__ int sh[256];
    int tx = threadIdx.x;
    int v = (tx < nb) ? bsum[tx] : 0;
    sh[tx] = v;
    __syncthreads();
    for (int d = 1; d < 256; d <<= 1) {
        int t = (tx >= d) ? sh[tx - d] : 0;
        __syncthreads();
        sh[tx] += t;
        __syncthreads();
    }
    if (tx < nb) bsum[tx] = sh[tx] - v;
}

__global__ void scanC_kernel(int* __restrict__ off, int* __restrict__ cur,
                             const int* __restrict__ bsum, int n, int E) {
    int i = blockIdx.x * SCAN_BLK + threadIdx.x;
    if (i < n) {
        int o = off[i] + bsum[blockIdx.x];
        off[i] = o;
        cur[i] = o;
    }
    if (i == 0) off[n] = E;
}

__global__ void fill_kernel(const int* __restrict__ src, const int* __restrict__ dst,
                            int* __restrict__ cur, int* __restrict__ csr, int E) {
    int i = blockIdx.x * blockDim.x + threadIdx.x;
    if (i < E) {
        int d = __ldg(dst + i);
        int p = atomicAdd(&cur[d], 1);
        csr[p] = __ldg(src + i);
    }
}

// ---------------- gathers ---------------------------------------------------
// warp per flow node; fb fp16 read-modify-write; fp32 accumulation
__global__ void gather_flow_kernel(const __half* __restrict__ trel,
                                   const __half* __restrict__ th,
                                   const int* __restrict__ off_rel,
                                   const int* __restrict__ csr_rel,
                                   const int* __restrict__ off_h2f,
                                   const int* __restrict__ csr_h2f,
                                   __half* __restrict__ fb) {
    int w = (blockIdx.x * blockDim.x + threadIdx.x) >> 5;
    int lane = threadIdx.x & 31;
    if (w >= N_FLOW) return;
    uint2* fp = (uint2*)(fb + (size_t)w * HH);
    uint2 fv = fp[lane];
    float2 a0 = __half22float2(*(__half2*)&fv.x);
    float2 a1 = __half22float2(*(__half2*)&fv.y);
    float4 acc = make_float4(a0.x, a0.y, a1.x, a1.y);
    int b = __ldg(off_rel + w), e = __ldg(off_rel + w + 1);
    for (int i = b; i < e; ++i) {
        int s = __ldg(csr_rel + i);
        uint2 v = ((const uint2*)(trel + (size_t)s * HH))[lane];
        float2 p0 = __half22float2(*(__half2*)&v.x);
        float2 p1 = __half22float2(*(__half2*)&v.y);
        acc.x += p0.x; acc.y += p0.y; acc.z += p1.x; acc.w += p1.y;
    }
    b = __ldg(off_h2f + w); e = __ldg(off_h2f + w + 1);
    for (int i = b; i < e; ++i) {
        int s = __ldg(csr_h2f + i);
        uint2 v = ((const uint2*)(th + (size_t)s * HH))[lane];
        float2 p0 = __half22float2(*(__half2*)&v.x);
        float2 p1 = __half22float2(*(__half2*)&v.y);
        acc.x += p0.x; acc.y += p0.y; acc.z += p1.x; acc.w += p1.y;
    }
    __half2 h0 = __floats2half2_rn(acc.x, acc.y);
    __half2 h1 = __floats2half2_rn(acc.z, acc.w);
    uint2 ov;
    ov.x = *(uint32_t*)&h0; ov.y = *(uint32_t*)&h1;
    fp[lane] = ov;
}

// last layer: gather + global max pool fused; never writes fb.
__global__ __launch_bounds__(256)
void gather_flow_pool_kernel(const __half* __restrict__ trel,
                             const __half* __restrict__ th,
                             const __half* __restrict__ fmain,
                             const int* __restrict__ off_rel,
                             const int* __restrict__ csr_rel,
                             const int* __restrict__ off_h2f,
                             const int* __restrict__ csr_h2f,
                             const int* __restrict__ batch,
                             unsigned* __restrict__ pe) {
    __shared__ float sm[8][HH];
    __shared__ int sg[8];
    int warp = threadIdx.x >> 5, lane = threadIdx.x & 31;
    int w = blockIdx.x * 8 + warp;
    float4 acc = make_float4(0.f, 0.f, 0.f, 0.f);
    int g = -1;
    if (w < N_FLOW) {
        g = __ldg(batch + w);
        uint2 fv = ((const uint2*)(fmain + (size_t)w * HH))[lane];
        float2 a0 = __half22float2(*(__half2*)&fv.x);
        float2 a1 = __half22float2(*(__half2*)&fv.y);
        acc = make_float4(a0.x, a0.y, a1.x, a1.y);
        int b = __ldg(off_rel + w), e = __ldg(off_rel + w + 1);
        for (int i = b; i < e; ++i) {
            int s = __ldg(csr_rel + i);
            uint2 v = ((const uint2*)(trel + (size_t)s * HH))[lane];
            float2 p0 = __half22float2(*(__half2*)&v.x);
            float2 p1 = __half22float2(*(__half2*)&v.y);
            acc.x += p0.x; acc.y += p0.y; acc.z += p1.x; acc.w += p1.y;
        }
        b = __ldg(off_h2f + w); e = __ldg(off_h2f + w + 1);
        for (int i = b; i < e; ++i) {
            int s = __ldg(csr_h2f + i);
            uint2 v = ((const uint2*)(th + (size_t)s * HH))[lane];
            float2 p0 = __half22float2(*(__half2*)&v.x);
            float2 p1 = __half22float2(*(__half2*)&v.y);
            acc.x += p0.x; acc.y += p0.y; acc.z += p1.x; acc.w += p1.y;
        }
    }
    if (lane == 0) sg[warp] = g;
    *(float4*)&sm[warp][lane * 4] = acc;
    __syncthreads();
    if (threadIdx.x < HH) {
        int c = threadIdx.x;
        int cur = sg[0];
        float m = -INFINITY;
#pragma unroll
        for (int r = 0; r < 8; ++r) {
            int gg = sg[r];
            if (gg != cur) {
                if (cur >= 0) atomicMax(&pe[cur * HH + c], enc_f(m));
                cur = gg; m = -INFINITY;
            }
            if (gg >= 0) m = fmaxf(m, sm[r][c]);
        }
        if (cur >= 0) atomicMax(&pe[cur * HH + c], enc_f(m));
    }
}

// warp per host node; fa is fp16 flow activations; ah fp32
__global__ void gather_host_kernel(const __half* __restrict__ fa,
                                   const int* __restrict__ off,
                                   const int* __restrict__ csr,
                                   float* __restrict__ ah, int relu_in) {
    int w = (blockIdx.x * blockDim.x + threadIdx.x) >> 5;
    int lane = threadIdx.x & 31;
    if (w >= N_HOST) return;
    float4 acc = make_float4(0.f, 0.f, 0.f, 0.f);
    int b = __ldg(off + w), e = __ldg(off + w + 1);
    for (int i = b; i < e; ++i) {
        int s = __ldg(csr + i);
        uint2 v = ((const uint2*)(fa + (size_t)s * HH))[lane];
        float2 p0 = __half22float2(*(__half2*)&v.x);
        float2 p1 = __half22float2(*(__half2*)&v.y);
        if (relu_in) {
            p0.x = fmaxf(p0.x, 0.f); p0.y = fmaxf(p0.y, 0.f);
            p1.x = fmaxf(p1.x, 0.f); p1.y = fmaxf(p1.y, 0.f);
        }
        acc.x += p0.x; acc.y += p0.y; acc.z += p1.x; acc.w += p1.y;
    }
    ((float4*)(ah + (size_t)w * HH))[lane] = acc;
}

// ---------------- prep ------------------------------------------------------
__global__ void embed_kernel(const int* __restrict__ ids,
                             const float* __restrict__ table,
                             float* __restrict__ xh) {
    int i = blockIdx.x * blockDim.x + threadIdx.x;
    if (i >= N_HOST * HH) return;
    int row = i >> 7, c = i & 127;
    xh[i] = table[(size_t)__ldg(ids + row) * HH + c];
}

__global__ void pad_flow_kernel(const float* __restrict__ fx,
                                __half* __restrict__ xf) {
    int i = blockIdx.x * blockDim.x + threadIdx.x;
    if (i >= N_FLOW * HH) return;
    int row = i >> 7, c = i & 127;
    xf[i] = __float2half((c < FI) ? fx[(size_t)row * FI + c] : 0.f);
}

__global__ void prep_weights_kernel(const float* __restrict__ Wo0_h2f,
                                    const float* __restrict__ Wo0_rel,
                                    const float* __restrict__ Wr0_rel,
                                    const float* __restrict__ Wr0_f2h,
                                    const float* __restrict__ Wo,
                                    const float* __restrict__ Wr,
                                    const float* __restrict__ br0_h2f,
                                    const float* __restrict__ br0_rel,
                                    const float* __restrict__ br) {
    int k = blockIdx.x;
    int c = threadIdx.x;
    int idx = k * 256 + c;
    if (c < HH) {
        g_WF[0][idx] = (k < FI) ? (Wo0_h2f[k * HH + c] + Wo0_rel[k * HH + c]) : 0.f;
        g_Wf2hPad[k * HH + c] = (k < FI) ? Wr0_f2h[k * HH + c] : 0.f;
    } else {
        int cc = c - HH;
        g_WF[0][idx] = (k < FI) ? Wr0_rel[k * HH + cc] : 0.f;
    }
    for (int l = 0; l < 2; ++l) {
        float v;
        if (c < HH)
            v = Wo[((size_t)l * 3 + 0) * HH * HH + k * HH + c]
              + Wo[((size_t)l * 3 + 2) * HH * HH + k * HH + c];
        else
            v = Wr[((size_t)l * 3 + 2) * HH * HH + k * HH + (c - HH)];
        g_WF[l + 1][idx] = v;
    }
    if (k == 0 && c < HH) {
        g_biasF[0][c] = br0_h2f[c] + br0_rel[c];
        for (int l = 0; l < 2; ++l)
            g_biasF[l + 1][c] = br[(l * 3 + 0) * HH + c] + br[(l * 3 + 2) * HH + c];
        g_zeroBias[c] = 0.f;
    }
}

// ---------------- tf32 tensor-core GEMM (flow path, fp16 A + fp16 outputs) --
__global__ __launch_bounds__(512, 1)
void gemm_dual_tc_kernel(const __half* __restrict__ A, const float* __restrict__ W,
                         const float* __restrict__ bias,
                         __half* __restrict__ out_main, __half* __restrict__ out_aux,
                         int M, int relu_in) {
    const int BK = 16;
    __shared__ uint32_t As[2][BK][136];
    __shared__ uint32_t Ws[2][BK][264];

    int tid  = threadIdx.x;
    int warp = tid >> 5, lane = tid & 31;
    int wm = warp >> 2, wn = warp & 3;
    int tg = lane & 3, gp = lane >> 2;
    int row0 = blockIdx.x * 128;

    float4 acc[2][8];
#pragma unroll
    for (int i = 0; i < 2; ++i)
#pragma unroll
        for (int j = 0; j < 8; ++j) acc[i][j] = make_float4(0.f, 0.f, 0.f, 0.f);

    int a_r = tid >> 2, a_kq = tid & 3;
    int a_grow = row0 + a_r;
    float4 aREG;
    float4 wREG[2];

    auto loadA = [&](int k0) {
        aREG = make_float4(0.f, 0.f, 0.f, 0.f);
        if (a_grow < M) {
            uint2 hv = *(const uint2*)(A + (size_t)a_grow * HH + k0 + a_kq * 4);
            float2 p0 = __half22float2(*(__half2*)&hv.x);
            float2 p1 = __half22float2(*(__half2*)&hv.y);
            aREG = make_float4(p0.x, p0.y, p1.x, p1.y);
        }
    };

    {
        loadA(0);
#pragma unroll
        for (int i = 0; i < 2; ++i) {
            int idx = tid + i * 512;
            int kk = idx >> 6, cq = idx & 63;
            wREG[i] = *(const float4*)(W + (size_t)kk * 256 + cq * 4);
        }
        if (relu_in) {
            aREG.x = fmaxf(aREG.x, 0.f); aREG.y = fmaxf(aREG.y, 0.f);
            aREG.z = fmaxf(aREG.z, 0.f); aREG.w = fmaxf(aREG.w, 0.f);
        }
        As[0][a_kq * 4 + 0][a_r] = f2tf32(aREG.x);
        As[0][a_kq * 4 + 1][a_r] = f2tf32(aREG.y);
        As[0][a_kq * 4 + 2][a_r] = f2tf32(aREG.z);
        As[0][a_kq * 4 + 3][a_r] = f2tf32(aREG.w);
#pragma unroll
        for (int i = 0; i < 2; ++i) {
            int idx = tid + i * 512;
            int kk = idx >> 6, cq = idx & 63;
            uint32_t* p = &Ws[0][kk][cq * 4];
            p[0] = f2tf32(wREG[i].x); p[1] = f2tf32(wREG[i].y);
            p[2] = f2tf32(wREG[i].z); p[3] = f2tf32(wREG[i].w);
        }
        __syncthreads();
    }

    const int NITER = HH / BK;
    for (int iter = 0; iter < NITER; ++iter) {
        int cur = iter & 1;
        if (iter + 1 < NITER) {
            int k0 = (iter + 1) * BK;
            loadA(k0);
#pragma unroll
            for (int i = 0; i < 2; ++i) {
                int idx = tid + i * 512;
                int kk = idx >> 6, cq = idx & 63;
                wREG[i] = *(const float4*)(W + (size_t)(k0 + kk) * 256 + cq * 4);
            }
        }
#pragma unroll
        for (int ks = 0; ks < BK; ks += 8) {
            uint32_t af[2][4];
            uint32_t bf[8][2];
#pragma unroll
            for (int mi = 0; mi < 2; ++mi) {
                int ar = wm * 32 + mi * 16 + gp;
                af[mi][0] = As[cur][ks + tg][ar];
                af[mi][1] = As[cur][ks + tg][ar + 8];
                af[mi][2] = As[cur][ks + tg + 4][ar];
                af[mi][3] = As[cur][ks + tg + 4][ar + 8];
            }
#pragma unroll
            for (int ni = 0; ni < 8; ++ni) {
                int nc = wn * 64 + ni * 8 + gp;
                bf[ni][0] = Ws[cur][ks + tg][nc];
                bf[ni][1] = Ws[cur][ks + tg + 4][nc];
            }
#pragma unroll
            for (int mi = 0; mi < 2; ++mi)
#pragma unroll
                for (int ni = 0; ni < 8; ++ni)
                    mma_tf32(acc[mi][ni], af[mi], bf[ni]);
        }
        if (iter + 1 < NITER) {
            int nxt = 1 - cur;
            if (relu_in) {
                aREG.x = fmaxf(aREG.x, 0.f); aREG.y = fmaxf(aREG.y, 0.f);
                aREG.z = fmaxf(aREG.z, 0.f); aREG.w = fmaxf(aREG.w, 0.f);
            }
            As[nxt][a_kq * 4 + 0][a_r] = f2tf32(aREG.x);
            As[nxt][a_kq * 4 + 1][a_r] = f2tf32(aREG.y);
            As[nxt][a_kq * 4 + 2][a_r] = f2tf32(aREG.z);
            As[nxt][a_kq * 4 + 3][a_r] = f2tf32(aREG.w);
#pragma unroll
            for (int i = 0; i < 2; ++i) {
                int idx = tid + i * 512;
                int kk = idx >> 6, cq = idx & 63;
                uint32_t* p = &Ws[nxt][kk][cq * 4];
                p[0] = f2tf32(wREG[i].x); p[1] = f2tf32(wREG[i].y);
                p[2] = f2tf32(wREG[i].z); p[3] = f2tf32(wREG[i].w);
            }
        }
        __syncthreads();
    }

#pragma unroll
    for (int ni = 0; ni < 8; ++ni) {
        int col = wn * 64 + ni * 8 + tg * 2;
        bool main_half = (col < HH);
        float b0 = 0.f, b1 = 0.f;
        if (main_half) { b0 = __ldg(bias + col); b1 = __ldg(bias + col + 1); }
        int oc = main_half ? col : (col - HH);
        __half* outp = main_half ? out_main : out_aux;
#pragma unroll
        for (int mi = 0; mi < 2; ++mi) {
            int r0 = row0 + wm * 32 + mi * 16 + gp;
            int r1 = r0 + 8;
            float4 d = acc[mi][ni];
            if (r0 < M)
                *(__half2*)(outp + (size_t)r0 * HH + oc) =
                    __floats2half2_rn(d.x + b0, d.y + b1);
            if (r1 < M)
                *(__half2*)(outp + (size_t)r1 * HH + oc) =
                    __floats2half2_rn(d.z + b0, d.w + b1);
        }
    }
}

// ---------------- fp32 GEMM (host path, small) ------------------------------
__global__ __launch_bounds__(256)
void gemm2_kernel(const float* __restrict__ A0, const float* __restrict__ W0,
                  const float* __restrict__ A1, const float* __restrict__ W1,
                  const float* __restrict__ bias, float* __restrict__ out,
                  __half* __restrict__ outh,
                  int M, int nsrc, int relu_mask) {
    const int BM = 128, BK = 16;
    __shared__ float As[BK][BM + 4];
    __shared__ float Ws[BK][128];
    int tid = threadIdx.x;
    int tx = tid & 15, ty = tid >> 4;
    int row0 = blockIdx.x * BM;
    float acc[8][8];
#pragma unroll
    for (int i = 0; i < 8; ++i)
#pragma unroll
        for (int j = 0; j < 8; ++j) acc[i][j] = 0.f;

    const float* Aarr[2] = {A0, A1};
    const float* Warr[2] = {W0, W1};

    for (int s = 0; s < nsrc; ++s) {
        const float* A = Aarr[s];
        const float* W = Warr[s];
        int rl = (relu_mask >> s) & 1;
        for (int k0 = 0; k0 < 128; k0 += BK) {
#pragma unroll
            for (int i = 0; i < 2; ++i) {
                int idx = tid + i * 256;
                int r = idx >> 2, kq = idx & 3;
                int grow = row0 + r;
                float4 v = make_float4(0.f, 0.f, 0.f, 0.f);
                if (grow < M)
                    v = *(const float4*)(A + (size_t)grow * 128 + k0 + kq * 4);
                if (rl) {
                    v.x = fmaxf(v.x, 0.f); v.y = fmaxf(v.y, 0.f);
                    v.z = fmaxf(v.z, 0.f); v.w = fmaxf(v.w, 0.f);
                }
                As[kq * 4 + 0][r] = v.x;
                As[kq * 4 + 1][r] = v.y;
                As[kq * 4 + 2][r] = v.z;
                As[kq * 4 + 3][r] = v.w;
            }
#pragma unroll
            for (int i = 0; i < 2; ++i) {
                int idx = tid + i * 256;
                int kk = idx >> 5, cq = idx & 31;
                *(float4*)&Ws[kk][cq * 4] =
                    *(const float4*)(W + (size_t)(k0 + kk) * 128 + cq * 4);
            }
            __syncthreads();
#pragma unroll
            for (int k = 0; k < BK; ++k) {
                float a[8], b[8];
#pragma unroll
                for (int i = 0; i < 8; i += 4)
                    *(float4*)&a[i] = *(const float4*)&As[k][ty * 8 + i];
#pragma unroll
                for (int j = 0; j < 8; j += 4)
                    *(float4*)&b[j] = *(const float4*)&Ws[k][tx * 8 + j];
#pragma unroll
                for (int i = 0; i < 8; ++i)
#pragma unroll
                    for (int j = 0; j < 8; ++j)
                        acc[i][j] = fmaf(a[i], b[j], acc[i][j]);
            }
            __syncthreads();
        }
    }
#pragma unroll
    for (int i = 0; i < 8; ++i) {
        int r = row0 + ty * 8 + i;
        if (r >= M) break;
        if (outh) {
#pragma unroll
            for (int j = 0; j < 8; j += 2) {
                float v0 = acc[i][j]   + __ldg(bias + tx * 8 + j);
                float v1 = acc[i][j+1] + __ldg(bias + tx * 8 + j + 1);
                *(__half2*)(outh + (size_t)r * 128 + tx * 8 + j) =
                    __floats2half2_rn(v0, v1);
            }
        } else {
#pragma unroll
            for (int j = 0; j < 8; ++j)
                out[(size_t)r * 128 + tx * 8 + j] = acc[i][j] + __ldg(bias + tx * 8 + j);
        }
    }
}

// ---------------- pooling + MLP --------------------------------------------
__global__ void pool_init_kernel(unsigned* __restrict__ pe) {
    int i = blockIdx.x * blockDim.x + threadIdx.x;
    if (i < GG * HH) pe[i] = 0x007FFFFFu;
}

__global__ void pool_decode_kernel(const unsigned* __restrict__ pe,
                                   float* __restrict__ p) {
    int i = blockIdx.x * blockDim.x + threadIdx.x;
    if (i < GG * HH) p[i] = dec_f(pe[i]);
}

__global__ void mlp1_kernel(const float* __restrict__ pooled,
                            const float* __restrict__ Wc1,
                            const float* __restrict__ bc1,
                            float* __restrict__ h1) {
    int t = blockIdx.x * blockDim.x + threadIdx.x;
    if (t >= GG * 64) return;
    int g = t >> 6, c = t & 63;
    float acc = bc1[c];
    for (int k = 0; k < HH; ++k)
        acc = fmaf(pooled[g * HH + k], Wc1[k * 64 + c], acc);
    h1[t] = fmaxf(acc, 0.f);
}

__global__ void mlp2_kernel(const float* __restrict__ h1,
                            const float* __restrict__ Wc2,
                            const float* __restrict__ bc2,
                            float* __restrict__ h2) {
    int t = blockIdx.x * blockDim.x + threadIdx.x;
    if (t >= GG * HH) return;
    int g = t >> 7, c = t & 127;
    float acc = bc2[c];
    for (int k = 0; k < 64; ++k)
        acc = fmaf(h1[g * 64 + k], Wc2[k * HH + c], acc);
    h2[t] = fmaxf(acc, 0.f);
}

__global__ void mlp3_kernel(const float* __restrict__ h2,
                            const float* __restrict__ Wc3,
                            const float* __restrict__ bc3,
                            float* __restrict__ out) {
    int t = blockIdx.x * blockDim.x + threadIdx.x;
    if (t >= GG * 10) return;
    int g = t / 10, c = t % 10;
    float acc = bc3[c];
    for (int k = 0; k < HH; ++k)
        acc = fmaf(h2[g * HH + k], Wc3[k * 10 + c], acc);
    out[t] = acc;
}

// ---------------- host orchestration ---------------------------------------
static void build_csr(cudaStream_t st, const int* src, const int* dst, int E, int n,
                      int* cnt, int* off, int* cur, int* csr, int* bsum) {
    int nb = (n + SCAN_BLK - 1) / SCAN_BLK;
    cudaMemsetAsync(cnt, 0, (size_t)n * sizeof(int), st);
    hist_kernel<<<(E + 255) / 256, 256, 0, st>>>(dst, cnt, E);
    scanA_kernel<<<nb, SCAN_BLK, 0, st>>>(cnt, off, bsum, n);
    scanB_kernel<<<1, 256, 0, st>>>(bsum, nb);
    scanC_kernel<<<nb, SCAN_BLK, 0, st>>>(off, cur, bsum, n, E);
    fill_kernel<<<(E + 255) / 256, 256, 0, st>>>(src, dst, cur, csr, E);
}

extern "C" void kernel_launch(void* const* d_in, const int* in_sizes, int n_in,
                              void* d_out, int out_size) {
    const int*   host_ids  = (const int*)  d_in[0];
    const float* flow_x    = (const float*)d_in[1];
    const int*   h2f_src   = (const int*)  d_in[2];
    const int*   h2f_dst   = (const int*)  d_in[3];
    const int*   f2h_src   = (const int*)  d_in[4];
    const int*   f2h_dst   = (const int*)  d_in[5];
    const int*   rel_src   = (const int*)  d_in[6];
    const int*   rel_dst   = (const int*)  d_in[7];
    const int*   flow_batch= (const int*)  d_in[8];
    const float* host_embed= (const float*)d_in[9];
    const float* Wr0_h2f   = (const float*)d_in[10];
    const float* br0_h2f   = (const float*)d_in[11];
    const float* Wo0_h2f   = (const float*)d_in[12];
    const float* Wr0_f2h   = (const float*)d_in[13];
    const float* br0_f2h   = (const float*)d_in[14];
    const float* Wo0_f2h   = (const float*)d_in[15];
    const float* Wr0_rel   = (const float*)d_in[16];
    const float* br0_rel   = (const float*)d_in[17];
    const float* Wo0_rel   = (const float*)d_in[18];
    const float* Wr        = (const float*)d_in[19];  // [2,3,128,128]
    const float* br        = (const float*)d_in[20];  // [2,3,128]
    const float* Wo        = (const float*)d_in[21];  // [2,3,128,128]
    const float* Wc1       = (const float*)d_in[22];
    const float* bc1       = (const float*)d_in[23];
    const float* Wc2       = (const float*)d_in[24];
    const float* bc2       = (const float*)d_in[25];
    const float* Wc3       = (const float*)d_in[26];
    const float* bc3       = (const float*)d_in[27];
    float* out = (float*)d_out;

    __half *xfA, *xfB, *trel, *th;
    float *xhA, *xhB, *ah;
    float *WF, *Wf2hPad, *biasF, *zeroBias;
    unsigned* poolEnc; float *pooled, *h1, *h2;
    int *csr_rel, *csr_h2f, *csr_f2h;
    int *off_rel, *off_h2f, *off_f2h;
    int *cur_rel, *cur_h2f, *cur_f2h;
    int *cnt_rel, *cnt_h2f, *cnt_f2h, *bsum;
    cudaGetSymbolAddress((void**)&xfA, g_xflowA);
    cudaGetSymbolAddress((void**)&xfB, g_xflowB);
    cudaGetSymbolAddress((void**)&trel, g_trel);
    cudaGetSymbolAddress((void**)&th,  g_th);
    cudaGetSymbolAddress((void**)&xhA, g_xhostA);
    cudaGetSymbolAddress((void**)&xhB, g_xhostB);
    cudaGetSymbolAddress((void**)&ah,  g_aggh);
    cudaGetSymbolAddress((void**)&WF,  g_WF);
    cudaGetSymbolAddress((void**)&Wf2hPad, g_Wf2hPad);
    cudaGetSymbolAddress((void**)&biasF,   g_biasF);
    cudaGetSymbolAddress((void**)&zeroBias, g_zeroBias);
    cudaGetSymbolAddress((void**)&poolEnc, g_poolEnc);
    cudaGetSymbolAddress((void**)&pooled,  g_pooled);
    cudaGetSymbolAddress((void**)&h1, g_h1);
    cudaGetSymbolAddress((void**)&h2, g_h2);
    cudaGetSymbolAddress((void**)&csr_rel, g_csr_rel);
    cudaGetSymbolAddress((void**)&csr_h2f, g_csr_h2f);
    cudaGetSymbolAddress((void**)&csr_f2h, g_csr_f2h);
    cudaGetSymbolAddress((void**)&off_rel, g_off_rel);
    cudaGetSymbolAddress((void**)&off_h2f, g_off_h2f);
    cudaGetSymbolAddress((void**)&off_f2h, g_off_f2h);
    cudaGetSymbolAddress((void**)&cur_rel, g_cur_rel);
    cudaGetSymbolAddress((void**)&cur_h2f, g_cur_h2f);
    cudaGetSymbolAddress((void**)&cur_f2h, g_cur_f2h);
    cudaGetSymbolAddress((void**)&cnt_rel, g_cnt_rel);
    cudaGetSymbolAddress((void**)&cnt_h2f, g_cnt_h2f);
    cudaGetSymbolAddress((void**)&cnt_f2h, g_cnt_f2h);
    cudaGetSymbolAddress((void**)&bsum, g_bsum);

    static cudaStream_t sB = nullptr;
    static cudaEvent_t evFork = nullptr, evPrep = nullptr, evCsrB = nullptr,
                       evTh = nullptr, evFlow = nullptr, evHG = nullptr;
    if (!sB) {
        cudaStreamCreateWithFlags(&sB, cudaStreamNonBlocking);
        cudaEventCreateWithFlags(&evFork, cudaEventDisableTiming);
        cudaEventCreateWithFlags(&evPrep, cudaEventDisableTiming);
        cudaEventCreateWithFlags(&evCsrB, cudaEventDisableTiming);
        cudaEventCreateWithFlags(&evTh,   cudaEventDisableTiming);
        cudaEventCreateWithFlags(&evFlow, cudaEventDisableTiming);
        cudaEventCreateWithFlags(&evHG,   cudaEventDisableTiming);
    }
    cudaStream_t s0 = 0;

    int flowBlocks = (N_FLOW + 127) / 128;
    int hostBlocks = (N_HOST + 127) / 128;

    cudaEventRecord(evFork, s0);
    cudaStreamWaitEvent(sB, evFork, 0);

    // s0 prologue: weights + padded fp16 flow features, then GEMM L0
    prep_weights_kernel<<<HH, 256, 0, s0>>>(Wo0_h2f, Wo0_rel, Wr0_rel, Wr0_f2h,
                                            Wo, Wr, br0_h2f, br0_rel, br);
    pad_flow_kernel<<<(N_FLOW * HH + 255) / 256, 256, 0, s0>>>(flow_x, xfA);
    cudaEventRecord(evPrep, s0);

    // sB prologue: embed + pool init + th(L0) + all CSR builds + host chain L0
    embed_kernel<<<(N_HOST * HH + 255) / 256, 256, 0, sB>>>(host_ids, host_embed, xhA);
    pool_init_kernel<<<(GG * HH + 255) / 256, 256, 0, sB>>>(poolEnc);
    gemm2_kernel<<<hostBlocks, 256, 0, sB>>>(xhA, Wr0_h2f, nullptr, nullptr,
                                             zeroBias, nullptr, th, N_HOST, 1, 0);
    cudaEventRecord(evTh, sB);
    build_csr(sB, rel_src, rel_dst, E_REL, N_FLOW, cnt_rel, off_rel, cur_rel, csr_rel, bsum + 0 * 256);
    build_csr(sB, h2f_src, h2f_dst, E_HF,  N_FLOW, cnt_h2f, off_h2f, cur_h2f, csr_h2f, bsum + 1 * 256);
    cudaEventRecord(evCsrB, sB);
    build_csr(sB, f2h_src, f2h_dst, E_HF,  N_HOST, cnt_f2h, off_f2h, cur_f2h, csr_f2h, bsum + 2 * 256);
    cudaStreamWaitEvent(sB, evPrep, 0);
    gather_host_kernel<<<(N_HOST * 32 + 255) / 256, 256, 0, sB>>>(
        xfA, off_f2h, csr_f2h, ah, 0);
    cudaEventRecord(evHG, sB);
    gemm2_kernel<<<hostBlocks, 256, 0, sB>>>(ah, Wf2hPad, xhA, Wo0_f2h, br0_f2h,
                                             xhB, nullptr, N_HOST, 2, 0);

    // ---- layer 0 flow (s0) ----
    gemm_dual_tc_kernel<<<flowBlocks, 512, 0, s0>>>(xfA, WF, biasF, xfB, trel, N_FLOW, 0);
    cudaStreamWaitEvent(s0, evTh, 0);
    cudaStreamWaitEvent(s0, evCsrB, 0);
    gather_flow_kernel<<<(N_FLOW * 32 + 255) / 256, 256, 0, s0>>>(
        trel, th, off_rel, csr_rel, off_h2f, csr_h2f, xfB);
    cudaEventRecord(evFlow, s0);

    // ---- layer 1 ----
    {
        const float* WF1 = WF + (size_t)1 * HH * 2 * HH;
        const float* bF1 = biasF + (size_t)1 * HH;
        const float* WrH2F = Wr + (size_t)(0 * 3 + 0) * HH * HH;
        const float* WrF2H = Wr + (size_t)(0 * 3 + 1) * HH * HH;
        const float* WoF2H = Wo + (size_t)(0 * 3 + 1) * HH * HH;
        const float* bH    = br + (0 * 3 + 1) * HH;

        cudaStreamWaitEvent(s0, evHG, 0);  // gather_host L0 read xfA
        gemm_dual_tc_kernel<<<flowBlocks, 512, 0, s0>>>(xfB, WF1, bF1, xfA, trel, N_FLOW, 1);

        cudaStreamWaitEvent(sB, evFlow, 0);
        gemm2_kernel<<<hostBlocks, 256, 0, sB>>>(xhB, WrH2F, nullptr, nullptr,
                                                 zeroBias, nullptr, th, N_HOST, 1, 1);
        cudaEventRecord(evTh, sB);
        gather_host_kernel<<<(N_HOST * 32 + 255) / 256, 256, 0, sB>>>(
            xfB, off_f2h, csr_f2h, ah, 1);
        cudaEventRecord(evHG, sB);
        gemm2_kernel<<<hostBlocks, 256, 0, sB>>>(ah, WrF2H, xhB, WoF2H, bH,
                                                 xhA, nullptr, N_HOST, 2, 2);

        cudaStreamWaitEvent(s0, evTh, 0);
        gather_flow_kernel<<<(N_FLOW * 32 + 255) / 256, 256, 0, s0>>>(
            trel, th, off_rel, csr_rel, off_h2f, csr_h2f, xfA);
        cudaEventRecord(evFlow, s0);
    }

    // ---- layer 2 (flow only; fused gather+pool) ----
    {
        const float* WF2 = WF + (size_t)2 * HH * 2 * HH;
        const float* bF2 = biasF + (size_t)2 * HH;
        const float* WrH2F = Wr + (size_t)(1 * 3 + 0) * HH * HH;

        cudaStreamWaitEvent(s0, evHG, 0);  // gather_host L1 read xfB
        gemm_dual_tc_kernel<<<flowBlocks, 512, 0, s0>>>(xfA, WF2, bF2, xfB, trel, N_FLOW, 1);

        cudaStreamWaitEvent(sB, evFlow, 0);
        gemm2_kernel<<<hostBlocks, 256, 0, sB>>>(xhA, WrH2F, nullptr, nullptr,
                                                 zeroBias, nullptr, th, N_HOST, 1, 1);
        cudaEventRecord(evTh, sB);

        cudaStreamWaitEvent(s0, evTh, 0);
        gather_flow_pool_kernel<<<(N_FLOW + 7) / 8, 256, 0, s0>>>(
            trel, th, xfB, off_rel, csr_rel, off_h2f, csr_h2f, flow_batch, poolEnc);
    }

    // epilogue on s0
    pool_decode_kernel<<<(GG * HH + 255) / 256, 256, 0, s0>>>(poolEnc, pooled);
    mlp1_kernel<<<(GG * 64 + 255) / 256, 256, 0, s0>>>(pooled, Wc1, bc1, h1);
    mlp2_kernel<<<(GG * HH + 255) / 256, 256, 0, s0>>>(h1, Wc2, bc2, h2);
    mlp3_kernel<<<(GG * 10 + 255) / 256, 256, 0, s0>>>(h2, Wc3, bc3, out);
}

// round 11
// speedup vs baseline: 3.9270x; 1.2130x over previous
#include <cuda_runtime.h>
#include <cuda_fp16.h>
#include <math.h>
#include <stdint.h>

#define N_HOST 20000
#define N_FLOW 200000
#define E_HF   400000
#define E_REL  800000
#define GG     64
#define HH     128
#define FI     97
#define SCAN_BLK 1024

// ---------------- scratch (device globals; no allocation allowed) ----------
__device__ __half g_xflowA[(size_t)N_FLOW * HH];   // ping (fp16 activations)
__device__ __half g_xflowB[(size_t)N_FLOW * HH];   // pong
__device__ __half g_trel  [(size_t)N_FLOW * HH];   // transformed flow (rel), fp16
__device__ __half g_th    [(size_t)N_HOST * HH];   // transformed host (h2f), fp16
__device__ float  g_xhostA[(size_t)N_HOST * HH];
__device__ float  g_xhostB[(size_t)N_HOST * HH];
__device__ float  g_aggh  [(size_t)N_HOST * HH];   // f2h aggregation into hosts

__device__ __half g_WFh[3][HH * 2 * HH]; // per layer fp16: [128][256]=[WoComb|Wr_rel]
__device__ float  g_Wf2hPad[HH * HH];    // pad(Wr0_f2h) 97->128 rows
__device__ float  g_biasF[3][HH];        // br_h2f + br_rel per layer
__device__ float  g_zeroBias[HH];        // zero-initialized device global

// CSR scratch (built once per launch, reused across layers)
__device__ int g_csr_rel[E_REL];
__device__ int g_csr_h2f[E_HF];
__device__ int g_csr_f2h[E_HF];
__device__ int g_off_rel[N_FLOW + 1];
__device__ int g_off_h2f[N_FLOW + 1];
__device__ int g_off_f2h[N_HOST + 1];
__device__ int g_cur_rel[N_FLOW];
__device__ int g_cur_h2f[N_FLOW];
__device__ int g_cur_f2h[N_HOST];
__device__ int g_cnt_rel[N_FLOW];
__device__ int g_cnt_h2f[N_FLOW];
__device__ int g_cnt_f2h[N_HOST];
__device__ int g_bsum[3][256];

__device__ unsigned g_poolEnc[GG * HH];
__device__ float    g_pooled [GG * HH];
__device__ float    g_h1[GG * 64];
__device__ float    g_h2[GG * HH];

// ---------------- small helpers -------------------------------------------
__device__ __forceinline__ unsigned enc_f(float f) {
    unsigned u = __float_as_uint(f);
    return (u & 0x80000000u) ? ~u : (u | 0x80000000u);
}
__device__ __forceinline__ float dec_f(unsigned e) {
    return (e & 0x80000000u) ? __uint_as_float(e ^ 0x80000000u)
                             : __uint_as_float(~e);
}
__device__ __forceinline__ uint32_t smaddr(const void* p) {
    return (uint32_t)__cvta_generic_to_shared(p);
}
__device__ __forceinline__ void ldsm4(uint32_t& r0, uint32_t& r1,
                                      uint32_t& r2, uint32_t& r3, uint32_t a) {
    asm volatile("ldmatrix.sync.aligned.m8n8.x4.shared.b16 {%0,%1,%2,%3}, [%4];"
                 : "=r"(r0), "=r"(r1), "=r"(r2), "=r"(r3) : "r"(a));
}
__device__ __forceinline__ void ldsm4t(uint32_t& r0, uint32_t& r1,
                                       uint32_t& r2, uint32_t& r3, uint32_t a) {
    asm volatile("ldmatrix.sync.aligned.m8n8.x4.trans.shared.b16 {%0,%1,%2,%3}, [%4];"
                 : "=r"(r0), "=r"(r1), "=r"(r2), "=r"(r3) : "r"(a));
}
__device__ __forceinline__ void mma_f16(float4& d, const uint32_t* a,
                                        const uint32_t* b) {
    asm volatile(
        "mma.sync.aligned.m16n8k16.row.col.f32.f16.f16.f32 "
        "{%0,%1,%2,%3}, {%4,%5,%6,%7}, {%8,%9}, {%0,%1,%2,%3};"
        : "+f"(d.x), "+f"(d.y), "+f"(d.z), "+f"(d.w)
        : "r"(a[0]), "r"(a[1]), "r"(a[2]), "r"(a[3]), "r"(b[0]), "r"(b[1]));
}

// ---------------- CSR construction -----------------------------------------
__global__ void hist_kernel(const int* __restrict__ dst, int* __restrict__ cnt,
                            int E) {
    int i = blockIdx.x * blockDim.x + threadIdx.x;
    if (i < E) atomicAdd(&cnt[__ldg(dst + i)], 1);
}

__global__ void scanA_kernel(const int* __restrict__ cnt, int* __restrict__ off,
                             int* __restrict__ bsum, int n) {
    __shared__ int sh[SCAN_BLK];
    int tx = threadIdx.x;
    int i = blockIdx.x * SCAN_BLK + tx;
    int v = (i < n) ? cnt[i] : 0;
    sh[tx] = v;
    __syncthreads();
    for (int d = 1; d < SCAN_BLK; d <<= 1) {
        int t = (tx >= d) ? sh[tx - d] : 0;
        __syncthreads();
        sh[tx] += t;
        __syncthreads();
    }
    if (i < n) off[i] = sh[tx] - v;
    if (tx == SCAN_BLK - 1) bsum[blockIdx.x] = sh[tx];
}

__global__ void scanB_kernel(int* __restrict__ bsum, int nb) {
    __shared__ int sh[256];
    int tx = threadIdx.x;
    int v = (tx < nb) ? bsum[tx] : 0;
    sh[tx] = v;
    __syncthreads();
    for (int d = 1; d < 256; d <<= 1) {
        int t = (tx >= d) ? sh[tx - d] : 0;
        __syncthreads();
        sh[tx] += t;
        __syncthreads();
    }
    if (tx < nb) bsum[tx] = sh[tx] - v;
}

__global__ void scanC_kernel(int* __restrict__ off, int* __restrict__ cur,
                             const int* __restrict__ bsum, int n, int E) {
    int i = blockIdx.x * SCAN_BLK + threadIdx.x;
    if (i < n) {
        int o = off[i] + bsum[blockIdx.x];
        off[i] = o;
        cur[i] = o;
    }
    if (i == 0) off[n] = E;
}

__global__ void fill_kernel(const int* __restrict__ src, const int* __restrict__ dst,
                            int* __restrict__ cur, int* __restrict__ csr, int E) {
    int i = blockIdx.x * blockDim.x + threadIdx.x;
    if (i < E) {
        int d = __ldg(dst + i);
        int p = atomicAdd(&cur[d], 1);
        csr[p] = __ldg(src + i);
    }
}

// ---------------- gathers ---------------------------------------------------
__global__ void gather_flow_kernel(const __half* __restrict__ trel,
                                   const __half* __restrict__ th,
                                   const int* __restrict__ off_rel,
                                   const int* __restrict__ csr_rel,
                                   const int* __restrict__ off_h2f,
                                   const int* __restrict__ csr_h2f,
                                   __half* __restrict__ fb) {
    int w = (blockIdx.x * blockDim.x + threadIdx.x) >> 5;
    int lane = threadIdx.x & 31;
    if (w >= N_FLOW) return;
    uint2* fp = (uint2*)(fb + (size_t)w * HH);
    uint2 fv = fp[lane];
    float2 a0 = __half22float2(*(__half2*)&fv.x);
    float2 a1 = __half22float2(*(__half2*)&fv.y);
    float4 acc = make_float4(a0.x, a0.y, a1.x, a1.y);
    int b = __ldg(off_rel + w), e = __ldg(off_rel + w + 1);
    for (int i = b; i < e; ++i) {
        int s = __ldg(csr_rel + i);
        uint2 v = ((const uint2*)(trel + (size_t)s * HH))[lane];
        float2 p0 = __half22float2(*(__half2*)&v.x);
        float2 p1 = __half22float2(*(__half2*)&v.y);
        acc.x += p0.x; acc.y += p0.y; acc.z += p1.x; acc.w += p1.y;
    }
    b = __ldg(off_h2f + w); e = __ldg(off_h2f + w + 1);
    for (int i = b; i < e; ++i) {
        int s = __ldg(csr_h2f + i);
        uint2 v = ((const uint2*)(th + (size_t)s * HH))[lane];
        float2 p0 = __half22float2(*(__half2*)&v.x);
        float2 p1 = __half22float2(*(__half2*)&v.y);
        acc.x += p0.x; acc.y += p0.y; acc.z += p1.x; acc.w += p1.y;
    }
    __half2 h0 = __floats2half2_rn(acc.x, acc.y);
    __half2 h1 = __floats2half2_rn(acc.z, acc.w);
    uint2 ov;
    ov.x = *(uint32_t*)&h0; ov.y = *(uint32_t*)&h1;
    fp[lane] = ov;
}

// last layer: gather + global max pool fused; never writes fb.
__global__ __launch_bounds__(256)
void gather_flow_pool_kernel(const __half* __restrict__ trel,
                             const __half* __restrict__ th,
                             const __half* __restrict__ fmain,
                             const int* __restrict__ off_rel,
                             const int* __restrict__ csr_rel,
                             const int* __restrict__ off_h2f,
                             const int* __restrict__ csr_h2f,
                             const int* __restrict__ batch,
                             unsigned* __restrict__ pe) {
    __shared__ float sm[8][HH];
    __shared__ int sg[8];
    int warp = threadIdx.x >> 5, lane = threadIdx.x & 31;
    int w = blockIdx.x * 8 + warp;
    float4 acc = make_float4(0.f, 0.f, 0.f, 0.f);
    int g = -1;
    if (w < N_FLOW) {
        g = __ldg(batch + w);
        uint2 fv = ((const uint2*)(fmain + (size_t)w * HH))[lane];
        float2 a0 = __half22float2(*(__half2*)&fv.x);
        float2 a1 = __half22float2(*(__half2*)&fv.y);
        acc = make_float4(a0.x, a0.y, a1.x, a1.y);
        int b = __ldg(off_rel + w), e = __ldg(off_rel + w + 1);
        for (int i = b; i < e; ++i) {
            int s = __ldg(csr_rel + i);
            uint2 v = ((const uint2*)(trel + (size_t)s * HH))[lane];
            float2 p0 = __half22float2(*(__half2*)&v.x);
            float2 p1 = __half22float2(*(__half2*)&v.y);
            acc.x += p0.x; acc.y += p0.y; acc.z += p1.x; acc.w += p1.y;
        }
        b = __ldg(off_h2f + w); e = __ldg(off_h2f + w + 1);
        for (int i = b; i < e; ++i) {
            int s = __ldg(csr_h2f + i);
            uint2 v = ((const uint2*)(th + (size_t)s * HH))[lane];
            float2 p0 = __half22float2(*(__half2*)&v.x);
            float2 p1 = __half22float2(*(__half2*)&v.y);
            acc.x += p0.x; acc.y += p0.y; acc.z += p1.x; acc.w += p1.y;
        }
    }
    if (lane == 0) sg[warp] = g;
    *(float4*)&sm[warp][lane * 4] = acc;
    __syncthreads();
    if (threadIdx.x < HH) {
        int c = threadIdx.x;
        int cur = sg[0];
        float m = -INFINITY;
#pragma unroll
        for (int r = 0; r < 8; ++r) {
            int gg = sg[r];
            if (gg != cur) {
                if (cur >= 0) atomicMax(&pe[cur * HH + c], enc_f(m));
                cur = gg; m = -INFINITY;
            }
            if (gg >= 0) m = fmaxf(m, sm[r][c]);
        }
        if (cur >= 0) atomicMax(&pe[cur * HH + c], enc_f(m));
    }
}

__global__ void gather_host_kernel(const __half* __restrict__ fa,
                                   const int* __restrict__ off,
                                   const int* __restrict__ csr,
                                   float* __restrict__ ah, int relu_in) {
    int w = (blockIdx.x * blockDim.x + threadIdx.x) >> 5;
    int lane = threadIdx.x & 31;
    if (w >= N_HOST) return;
    float4 acc = make_float4(0.f, 0.f, 0.f, 0.f);
    int b = __ldg(off + w), e = __ldg(off + w + 1);
    for (int i = b; i < e; ++i) {
        int s = __ldg(csr + i);
        uint2 v = ((const uint2*)(fa + (size_t)s * HH))[lane];
        float2 p0 = __half22float2(*(__half2*)&v.x);
        float2 p1 = __half22float2(*(__half2*)&v.y);
        if (relu_in) {
            p0.x = fmaxf(p0.x, 0.f); p0.y = fmaxf(p0.y, 0.f);
            p1.x = fmaxf(p1.x, 0.f); p1.y = fmaxf(p1.y, 0.f);
        }
        acc.x += p0.x; acc.y += p0.y; acc.z += p1.x; acc.w += p1.y;
    }
    ((float4*)(ah + (size_t)w * HH))[lane] = acc;
}

// ---------------- prep ------------------------------------------------------
__global__ void embed_kernel(const int* __restrict__ ids,
                             const float* __restrict__ table,
                             float* __restrict__ xh) {
    int i = blockIdx.x * blockDim.x + threadIdx.x;
    if (i >= N_HOST * HH) return;
    int row = i >> 7, c = i & 127;
    xh[i] = table[(size_t)__ldg(ids + row) * HH + c];
}

__global__ void pad_flow_kernel(const float* __restrict__ fx,
                                __half* __restrict__ xf) {
    int i = blockIdx.x * blockDim.x + threadIdx.x;
    if (i >= N_FLOW * HH) return;
    int row = i >> 7, c = i & 127;
    xf[i] = __float2half((c < FI) ? fx[(size_t)row * FI + c] : 0.f);
}

__global__ void prep_weights_kernel(const float* __restrict__ Wo0_h2f,
                                    const float* __restrict__ Wo0_rel,
                                    const float* __restrict__ Wr0_rel,
                                    const float* __restrict__ Wr0_f2h,
                                    const float* __restrict__ Wo,
                                    const float* __restrict__ Wr,
                                    const float* __restrict__ br0_h2f,
                                    const float* __restrict__ br0_rel,
                                    const float* __restrict__ br) {
    int k = blockIdx.x;
    int c = threadIdx.x;
    int idx = k * 256 + c;
    if (c < HH) {
        float v = (k < FI) ? (Wo0_h2f[k * HH + c] + Wo0_rel[k * HH + c]) : 0.f;
        g_WFh[0][idx] = __float2half(v);
        g_Wf2hPad[k * HH + c] = (k < FI) ? Wr0_f2h[k * HH + c] : 0.f;
    } else {
        int cc = c - HH;
        g_WFh[0][idx] = __float2half((k < FI) ? Wr0_rel[k * HH + cc] : 0.f);
    }
    for (int l = 0; l < 2; ++l) {
        float v;
        if (c < HH)
            v = Wo[((size_t)l * 3 + 0) * HH * HH + k * HH + c]
              + Wo[((size_t)l * 3 + 2) * HH * HH + k * HH + c];
        else
            v = Wr[((size_t)l * 3 + 2) * HH * HH + k * HH + (c - HH)];
        g_WFh[l + 1][idx] = __float2half(v);
    }
    if (k == 0 && c < HH) {
        g_biasF[0][c] = br0_h2f[c] + br0_rel[c];
        for (int l = 0; l < 2; ++l)
            g_biasF[l + 1][c] = br[(l * 3 + 0) * HH + c] + br[(l * 3 + 2) * HH + c];
        g_zeroBias[c] = 0.f;
    }
}

// ---------------- fp16 HMMA GEMM (flow path) --------------------------------
// [out_main | out_aux] = (relu?)A[M,128](fp16) @ W[128,256](fp16); bias on main.
// 512 thr = 16 warps (4x4), warp tile 32x64, BK=16, m16n8k16 HMMA via ldmatrix.
__global__ __launch_bounds__(512, 1)
void gemm_dual_h_kernel(const __half* __restrict__ A, const __half* __restrict__ W,
                        const float* __restrict__ bias,
                        __half* __restrict__ out_main, __half* __restrict__ out_aux,
                        int M, int relu_in) {
    const int BK = 16;
    __shared__ __half As[2][128][16];    // 32B rows; ldmatrix-friendly
    __shared__ __half Ws[2][BK][264];    // padded rows (528B) -> conflict-free trans

    int tid  = threadIdx.x;
    int warp = tid >> 5, lane = tid & 31;
    int wm = warp >> 2, wn = warp & 3;
    int tg = lane & 3, gp = lane >> 2;
    int row0 = blockIdx.x * 128;

    float4 acc[2][8];
#pragma unroll
    for (int i = 0; i < 2; ++i)
#pragma unroll
        for (int j = 0; j < 8; ++j) acc[i][j] = make_float4(0.f, 0.f, 0.f, 0.f);

    int a_r = tid >> 2, a_kq = tid & 3;
    int a_grow = row0 + a_r;
    uint2 aREG, wREG[2];
    const __half2 hz = __float2half2_rn(0.f);

    auto loadA = [&](int k0) {
        aREG = make_uint2(0u, 0u);
        if (a_grow < M)
            aREG = *(const uint2*)(A + (size_t)a_grow * HH + k0 + a_kq * 4);
        if (relu_in) {
            *(__half2*)&aREG.x = __hmax2(*(__half2*)&aREG.x, hz);
            *(__half2*)&aREG.y = __hmax2(*(__half2*)&aREG.y, hz);
        }
    };
    auto loadW = [&](int k0) {
#pragma unroll
        for (int i = 0; i < 2; ++i) {
            int idx = tid + i * 512;
            int kk = idx >> 6, cq = idx & 63;
            wREG[i] = *(const uint2*)(W + (size_t)(k0 + kk) * 256 + cq * 4);
        }
    };
    auto storeTile = [&](int buf) {
        *(uint2*)&As[buf][a_r][a_kq * 4] = aREG;
#pragma unroll
        for (int i = 0; i < 2; ++i) {
            int idx = tid + i * 512;
            int kk = idx >> 6, cq = idx & 63;
            *(uint2*)&Ws[buf][kk][cq * 4] = wREG[i];
        }
    };

    loadA(0); loadW(0);
    storeTile(0);
    __syncthreads();

    const int NITER = HH / BK;  // 8
    for (int iter = 0; iter < NITER; ++iter) {
        int cur = iter & 1;
        if (iter + 1 < NITER) {
            int k0 = (iter + 1) * BK;
            loadA(k0); loadW(k0);
        }
        // fragments via ldmatrix
        uint32_t af[2][4];
#pragma unroll
        for (int mi = 0; mi < 2; ++mi) {
            int row = wm * 32 + mi * 16 + (lane & 15);
            int col = (lane >> 4) * 8;
            ldsm4(af[mi][0], af[mi][1], af[mi][2], af[mi][3],
                  smaddr(&As[cur][row][col]));
        }
        uint32_t bf[8][2];
#pragma unroll
        for (int pr = 0; pr < 4; ++pr) {
            int krow = lane & 15;
            int ncol = wn * 64 + pr * 16 + ((lane >> 4) * 8);
            uint32_t b0, b1, b2, b3;
            ldsm4t(b0, b1, b2, b3, smaddr(&Ws[cur][krow][ncol]));
            bf[pr * 2][0] = b0; bf[pr * 2][1] = b1;
            bf[pr * 2 + 1][0] = b2; bf[pr * 2 + 1][1] = b3;
        }
#pragma unroll
        for (int mi = 0; mi < 2; ++mi)
#pragma unroll
            for (int ni = 0; ni < 8; ++ni)
                mma_f16(acc[mi][ni], af[mi], bf[ni]);
        if (iter + 1 < NITER) storeTile(1 - cur);
        __syncthreads();
    }

#pragma unroll
    for (int ni = 0; ni < 8; ++ni) {
        int col = wn * 64 + ni * 8 + tg * 2;
        bool main_half = (col < HH);
        float b0 = 0.f, b1 = 0.f;
        if (main_half) { b0 = __ldg(bias + col); b1 = __ldg(bias + col + 1); }
        int oc = main_half ? col : (col - HH);
        __half* outp = main_half ? out_main : out_aux;
#pragma unroll
        for (int mi = 0; mi < 2; ++mi) {
            int r0 = row0 + wm * 32 + mi * 16 + gp;
            int r1 = r0 + 8;
            float4 d = acc[mi][ni];
            if (r0 < M)
                *(__half2*)(outp + (size_t)r0 * HH + oc) =
                    __floats2half2_rn(d.x + b0, d.y + b1);
            if (r1 < M)
                *(__half2*)(outp + (size_t)r1 * HH + oc) =
                    __floats2half2_rn(d.z + b0, d.w + b1);
        }
    }
}

// ---------------- fp32 GEMM (host path, small) ------------------------------
__global__ __launch_bounds__(256)
void gemm2_kernel(const float* __restrict__ A0, const float* __restrict__ W0,
                  const float* __restrict__ A1, const float* __restrict__ W1,
                  const float* __restrict__ bias, float* __restrict__ out,
                  __half* __restrict__ outh,
                  int M, int nsrc, int relu_mask) {
    const int BM = 128, BK = 16;
    __shared__ float As[BK][BM + 4];
    __shared__ float Ws[BK][128];
    int tid = threadIdx.x;
    int tx = tid & 15, ty = tid >> 4;
    int row0 = blockIdx.x * BM;
    float acc[8][8];
#pragma unroll
    for (int i = 0; i < 8; ++i)
#pragma unroll
        for (int j = 0; j < 8; ++j) acc[i][j] = 0.f;

    const float* Aarr[2] = {A0, A1};
    const float* Warr[2] = {W0, W1};

    for (int s = 0; s < nsrc; ++s) {
        const float* A = Aarr[s];
        const float* W = Warr[s];
        int rl = (relu_mask >> s) & 1;
        for (int k0 = 0; k0 < 128; k0 += BK) {
#pragma unroll
            for (int i = 0; i < 2; ++i) {
                int idx = tid + i * 256;
                int r = idx >> 2, kq = idx & 3;
                int grow = row0 + r;
                float4 v = make_float4(0.f, 0.f, 0.f, 0.f);
                if (grow < M)
                    v = *(const float4*)(A + (size_t)grow * 128 + k0 + kq * 4);
                if (rl) {
                    v.x = fmaxf(v.x, 0.f); v.y = fmaxf(v.y, 0.f);
                    v.z = fmaxf(v.z, 0.f); v.w = fmaxf(v.w, 0.f);
                }
                As[kq * 4 + 0][r] = v.x;
                As[kq * 4 + 1][r] = v.y;
                As[kq * 4 + 2][r] = v.z;
                As[kq * 4 + 3][r] = v.w;
            }
#pragma unroll
            for (int i = 0; i < 2; ++i) {
                int idx = tid + i * 256;
                int kk = idx >> 5, cq = idx & 31;
                *(float4*)&Ws[kk][cq * 4] =
                    *(const float4*)(W + (size_t)(k0 + kk) * 128 + cq * 4);
            }
            __syncthreads();
#pragma unroll
            for (int k = 0; k < BK; ++k) {
                float a[8], b[8];
#pragma unroll
                for (int i = 0; i < 8; i += 4)
                    *(float4*)&a[i] = *(const float4*)&As[k][ty * 8 + i];
#pragma unroll
                for (int j = 0; j < 8; j += 4)
                    *(float4*)&b[j] = *(const float4*)&Ws[k][tx * 8 + j];
#pragma unroll
                for (int i = 0; i < 8; ++i)
#pragma unroll
                    for (int j = 0; j < 8; ++j)
                        acc[i][j] = fmaf(a[i], b[j], acc[i][j]);
            }
            __syncthreads();
        }
    }
#pragma unroll
    for (int i = 0; i < 8; ++i) {
        int r = row0 + ty * 8 + i;
        if (r >= M) break;
        if (outh) {
#pragma unroll
            for (int j = 0; j < 8; j += 2) {
                float v0 = acc[i][j]   + __ldg(bias + tx * 8 + j);
                float v1 = acc[i][j+1] + __ldg(bias + tx * 8 + j + 1);
                *(__half2*)(outh + (size_t)r * 128 + tx * 8 + j) =
                    __floats2half2_rn(v0, v1);
            }
        } else {
#pragma unroll
            for (int j = 0; j < 8; ++j)
                out[(size_t)r * 128 + tx * 8 + j] = acc[i][j] + __ldg(bias + tx * 8 + j);
        }
    }
}

// ---------------- pooling + MLP --------------------------------------------
__global__ void pool_init_kernel(unsigned* __restrict__ pe) {
    int i = blockIdx.x * blockDim.x + threadIdx.x;
    if (i < GG * HH) pe[i] = 0x007FFFFFu;
}

__global__ void pool_decode_kernel(const unsigned* __restrict__ pe,
                                   float* __restrict__ p) {
    int i = blockIdx.x * blockDim.x + threadIdx.x;
    if (i < GG * HH) p[i] = dec_f(pe[i]);
}

__global__ void mlp1_kernel(const float* __restrict__ pooled,
                            const float* __restrict__ Wc1,
                            const float* __restrict__ bc1,
                            float* __restrict__ h1) {
    int t = blockIdx.x * blockDim.x + threadIdx.x;
    if (t >= GG * 64) return;
    int g = t >> 6, c = t & 63;
    float acc = bc1[c];
    for (int k = 0; k < HH; ++k)
        acc = fmaf(pooled[g * HH + k], Wc1[k * 64 + c], acc);
    h1[t] = fmaxf(acc, 0.f);
}

__global__ void mlp2_kernel(const float* __restrict__ h1,
                            const float* __restrict__ Wc2,
                            const float* __restrict__ bc2,
                            float* __restrict__ h2) {
    int t = blockIdx.x * blockDim.x + threadIdx.x;
    if (t >= GG * HH) return;
    int g = t >> 7, c = t & 127;
    float acc = bc2[c];
    for (int k = 0; k < 64; ++k)
        acc = fmaf(h1[g * 64 + k], Wc2[k * HH + c], acc);
    h2[t] = fmaxf(acc, 0.f);
}

__global__ void mlp3_kernel(const float* __restrict__ h2,
                            const float* __restrict__ Wc3,
                            const float* __restrict__ bc3,
                            float* __restrict__ out) {
    int t = blockIdx.x * blockDim.x + threadIdx.x;
    if (t >= GG * 10) return;
    int g = t / 10, c = t % 10;
    float acc = bc3[c];
    for (int k = 0; k < HH; ++k)
        acc = fmaf(h2[g * HH + k], Wc3[k * 10 + c], acc);
    out[t] = acc;
}

// ---------------- host orchestration ---------------------------------------
static void build_csr(cudaStream_t st, const int* src, const int* dst, int E, int n,
                      int* cnt, int* off, int* cur, int* csr, int* bsum) {
    int nb = (n + SCAN_BLK - 1) / SCAN_BLK;
    cudaMemsetAsync(cnt, 0, (size_t)n * sizeof(int), st);
    hist_kernel<<<(E + 255) / 256, 256, 0, st>>>(dst, cnt, E);
    scanA_kernel<<<nb, SCAN_BLK, 0, st>>>(cnt, off, bsum, n);
    scanB_kernel<<<1, 256, 0, st>>>(bsum, nb);
    scanC_kernel<<<nb, SCAN_BLK, 0, st>>>(off, cur, bsum, n, E);
    fill_kernel<<<(E + 255) / 256, 256, 0, st>>>(src, dst, cur, csr, E);
}

extern "C" void kernel_launch(void* const* d_in, const int* in_sizes, int n_in,
                              void* d_out, int out_size) {
    const int*   host_ids  = (const int*)  d_in[0];
    const float* flow_x    = (const float*)d_in[1];
    const int*   h2f_src   = (const int*)  d_in[2];
    const int*   h2f_dst   = (const int*)  d_in[3];
    const int*   f2h_src   = (const int*)  d_in[4];
    const int*   f2h_dst   = (const int*)  d_in[5];
    const int*   rel_src   = (const int*)  d_in[6];
    const int*   rel_dst   = (const int*)  d_in[7];
    const int*   flow_batch= (const int*)  d_in[8];
    const float* host_embed= (const float*)d_in[9];
    const float* Wr0_h2f   = (const float*)d_in[10];
    const float* br0_h2f   = (const float*)d_in[11];
    const float* Wo0_h2f   = (const float*)d_in[12];
    const float* Wr0_f2h   = (const float*)d_in[13];
    const float* br0_f2h   = (const float*)d_in[14];
    const float* Wo0_f2h   = (const float*)d_in[15];
    const float* Wr0_rel   = (const float*)d_in[16];
    const float* br0_rel   = (const float*)d_in[17];
    const float* Wo0_rel   = (const float*)d_in[18];
    const float* Wr        = (const float*)d_in[19];  // [2,3,128,128]
    const float* br        = (const float*)d_in[20];  // [2,3,128]
    const float* Wo        = (const float*)d_in[21];  // [2,3,128,128]
    const float* Wc1       = (const float*)d_in[22];
    const float* bc1       = (const float*)d_in[23];
    const float* Wc2       = (const float*)d_in[24];
    const float* bc2       = (const float*)d_in[25];
    const float* Wc3       = (const float*)d_in[26];
    const float* bc3       = (const float*)d_in[27];
    float* out = (float*)d_out;

    __half *xfA, *xfB, *trel, *th, *WFh;
    float *xhA, *xhB, *ah;
    float *Wf2hPad, *biasF, *zeroBias;
    unsigned* poolEnc; float *pooled, *h1, *h2;
    int *csr_rel, *csr_h2f, *csr_f2h;
    int *off_rel, *off_h2f, *off_f2h;
    int *cur_rel, *cur_h2f, *cur_f2h;
    int *cnt_rel, *cnt_h2f, *cnt_f2h, *bsum;
    cudaGetSymbolAddress((void**)&xfA, g_xflowA);
    cudaGetSymbolAddress((void**)&xfB, g_xflowB);
    cudaGetSymbolAddress((void**)&trel, g_trel);
    cudaGetSymbolAddress((void**)&th,  g_th);
    cudaGetSymbolAddress((void**)&xhA, g_xhostA);
    cudaGetSymbolAddress((void**)&xhB, g_xhostB);
    cudaGetSymbolAddress((void**)&ah,  g_aggh);
    cudaGetSymbolAddress((void**)&WFh, g_WFh);
    cudaGetSymbolAddress((void**)&Wf2hPad, g_Wf2hPad);
    cudaGetSymbolAddress((void**)&biasF,   g_biasF);
    cudaGetSymbolAddress((void**)&zeroBias, g_zeroBias);
    cudaGetSymbolAddress((void**)&poolEnc, g_poolEnc);
    cudaGetSymbolAddress((void**)&pooled,  g_pooled);
    cudaGetSymbolAddress((void**)&h1, g_h1);
    cudaGetSymbolAddress((void**)&h2, g_h2);
    cudaGetSymbolAddress((void**)&csr_rel, g_csr_rel);
    cudaGetSymbolAddress((void**)&csr_h2f, g_csr_h2f);
    cudaGetSymbolAddress((void**)&csr_f2h, g_csr_f2h);
    cudaGetSymbolAddress((void**)&off_rel, g_off_rel);
    cudaGetSymbolAddress((void**)&off_h2f, g_off_h2f);
    cudaGetSymbolAddress((void**)&off_f2h, g_off_f2h);
    cudaGetSymbolAddress((void**)&cur_rel, g_cur_rel);
    cudaGetSymbolAddress((void**)&cur_h2f, g_cur_h2f);
    cudaGetSymbolAddress((void**)&cur_f2h, g_cur_f2h);
    cudaGetSymbolAddress((void**)&cnt_rel, g_cnt_rel);
    cudaGetSymbolAddress((void**)&cnt_h2f, g_cnt_h2f);
    cudaGetSymbolAddress((void**)&cnt_f2h, g_cnt_f2h);
    cudaGetSymbolAddress((void**)&bsum, g_bsum);

    static cudaStream_t sB = nullptr;
    static cudaEvent_t evFork = nullptr, evPrep = nullptr, evCsrB = nullptr,
                       evTh = nullptr, evFlow = nullptr, evHG = nullptr;
    if (!sB) {
        cudaStreamCreateWithFlags(&sB, cudaStreamNonBlocking);
        cudaEventCreateWithFlags(&evFork, cudaEventDisableTiming);
        cudaEventCreateWithFlags(&evPrep, cudaEventDisableTiming);
        cudaEventCreateWithFlags(&evCsrB, cudaEventDisableTiming);
        cudaEventCreateWithFlags(&evTh,   cudaEventDisableTiming);
        cudaEventCreateWithFlags(&evFlow, cudaEventDisableTiming);
        cudaEventCreateWithFlags(&evHG,   cudaEventDisableTiming);
    }
    cudaStream_t s0 = 0;

    int flowBlocks = (N_FLOW + 127) / 128;
    int hostBlocks = (N_HOST + 127) / 128;

    cudaEventRecord(evFork, s0);
    cudaStreamWaitEvent(sB, evFork, 0);

    // s0 prologue: weights + padded fp16 flow features, then GEMM L0
    prep_weights_kernel<<<HH, 256, 0, s0>>>(Wo0_h2f, Wo0_rel, Wr0_rel, Wr0_f2h,
                                            Wo, Wr, br0_h2f, br0_rel, br);
    pad_flow_kernel<<<(N_FLOW * HH + 255) / 256, 256, 0, s0>>>(flow_x, xfA);
    cudaEventRecord(evPrep, s0);

    // sB prologue: embed + pool init + th(L0) + CSR builds + host chain L0
    embed_kernel<<<(N_HOST * HH + 255) / 256, 256, 0, sB>>>(host_ids, host_embed, xhA);
    pool_init_kernel<<<(GG * HH + 255) / 256, 256, 0, sB>>>(poolEnc);
    gemm2_kernel<<<hostBlocks, 256, 0, sB>>>(xhA, Wr0_h2f, nullptr, nullptr,
                                             zeroBias, nullptr, th, N_HOST, 1, 0);
    cudaEventRecord(evTh, sB);
    build_csr(sB, rel_src, rel_dst, E_REL, N_FLOW, cnt_rel, off_rel, cur_rel, csr_rel, bsum + 0 * 256);
    build_csr(sB, h2f_src, h2f_dst, E_HF,  N_FLOW, cnt_h2f, off_h2f, cur_h2f, csr_h2f, bsum + 1 * 256);
    cudaEventRecord(evCsrB, sB);
    build_csr(sB, f2h_src, f2h_dst, E_HF,  N_HOST, cnt_f2h, off_f2h, cur_f2h, csr_f2h, bsum + 2 * 256);
    cudaStreamWaitEvent(sB, evPrep, 0);
    gather_host_kernel<<<(N_HOST * 32 + 255) / 256, 256, 0, sB>>>(
        xfA, off_f2h, csr_f2h, ah, 0);
    cudaEventRecord(evHG, sB);
    gemm2_kernel<<<hostBlocks, 256, 0, sB>>>(ah, Wf2hPad, xhA, Wo0_f2h, br0_f2h,
                                             xhB, nullptr, N_HOST, 2, 0);

    // ---- layer 0 flow (s0) ----
    gemm_dual_h_kernel<<<flowBlocks, 512, 0, s0>>>(xfA, WFh, biasF, xfB, trel, N_FLOW, 0);
    cudaStreamWaitEvent(s0, evTh, 0);
    cudaStreamWaitEvent(s0, evCsrB, 0);
    gather_flow_kernel<<<(N_FLOW * 32 + 255) / 256, 256, 0, s0>>>(
        trel, th, off_rel, csr_rel, off_h2f, csr_h2f, xfB);
    cudaEventRecord(evFlow, s0);

    // ---- layer 1 ----
    {
        const __half* WF1 = WFh + (size_t)1 * HH * 2 * HH;
        const float* bF1 = biasF + (size_t)1 * HH;
        const float* WrH2F = Wr + (size_t)(0 * 3 + 0) * HH * HH;
        const float* WrF2H = Wr + (size_t)(0 * 3 + 1) * HH * HH;
        const float* WoF2H = Wo + (size_t)(0 * 3 + 1) * HH * HH;
        const float* bH    = br + (0 * 3 + 1) * HH;

        cudaStreamWaitEvent(s0, evHG, 0);  // gather_host L0 read xfA
        gemm_dual_h_kernel<<<flowBlocks, 512, 0, s0>>>(xfB, WF1, bF1, xfA, trel, N_FLOW, 1);

        cudaStreamWaitEvent(sB, evFlow, 0);
        gemm2_kernel<<<hostBlocks, 256, 0, sB>>>(xhB, WrH2F, nullptr, nullptr,
                                                 zeroBias, nullptr, th, N_HOST, 1, 1);
        cudaEventRecord(evTh, sB);
        gather_host_kernel<<<(N_HOST * 32 + 255) / 256, 256, 0, sB>>>(
            xfB, off_f2h, csr_f2h, ah, 1);
        cudaEventRecord(evHG, sB);
        gemm2_kernel<<<hostBlocks, 256, 0, sB>>>(ah, WrF2H, xhB, WoF2H, bH,
                                                 xhA, nullptr, N_HOST, 2, 2);

        cudaStreamWaitEvent(s0, evTh, 0);
        gather_flow_kernel<<<(N_FLOW * 32 + 255) / 256, 256, 0, s0>>>(
            trel, th, off_rel, csr_rel, off_h2f, csr_h2f, xfA);
        cudaEventRecord(evFlow, s0);
    }

    // ---- layer 2 (flow only; fused gather+pool) ----
    {
        const __half* WF2 = WFh + (size_t)2 * HH * 2 * HH;
        const float* bF2 = biasF + (size_t)2 * HH;
        const float* WrH2F = Wr + (size_t)(1 * 3 + 0) * HH * HH;

        cudaStreamWaitEvent(s0, evHG, 0);  // gather_host L1 read xfB
        gemm_dual_h_kernel<<<flowBlocks, 512, 0, s0>>>(xfA, WF2, bF2, xfB, trel, N_FLOW, 1);

        cudaStreamWaitEvent(sB, evFlow, 0);
        gemm2_kernel<<<hostBlocks, 256, 0, sB>>>(xhA, WrH2F, nullptr, nullptr,
                                                 zeroBias, nullptr, th, N_HOST, 1, 1);
        cudaEventRecord(evTh, sB);

        cudaStreamWaitEvent(s0, evTh, 0);
        gather_flow_pool_kernel<<<(N_FLOW + 7) / 8, 256, 0, s0>>>(
            trel, th, xfB, off_rel, csr_rel, off_h2f, csr_h2f, flow_batch, poolEnc);
    }

    // epilogue on s0
    pool_decode_kernel<<<(GG * HH + 255) / 256, 256, 0, s0>>>(poolEnc, pooled);
    mlp1_kernel<<<(GG * 64 + 255) / 256, 256, 0, s0>>>(pooled, Wc1, bc1, h1);
    mlp2_kernel<<<(GG * HH + 255) / 256, 256, 0, s0>>>(h1, Wc2, bc2, h2);
    mlp3_kernel<<<(GG * 10 + 255) / 256, 256, 0, s0>>>(h2, Wc3, bc3, out);
}